// round 8
// baseline (speedup 1.0000x reference)
#include <cuda_runtime.h>
#include <cstdint>
#include <cstddef>

#define Bb 256
#define Tt 512
#define Ii 64
#define Hh 512
#define Gg 2048   // 4*H

// ---------------- tf32 mma.sync helpers (baseline PTX, sm_80+) -------------
__device__ __forceinline__ void mma_tf32(float* d, const uint32_t* a, const uint32_t* b) {
    asm volatile(
        "mma.sync.aligned.m16n8k8.row.col.f32.tf32.tf32.f32 "
        "{%0,%1,%2,%3}, {%4,%5,%6,%7}, {%8,%9}, {%0,%1,%2,%3};"
        : "+f"(d[0]), "+f"(d[1]), "+f"(d[2]), "+f"(d[3])
        : "r"(a[0]), "r"(a[1]), "r"(a[2]), "r"(a[3]), "r"(b[0]), "r"(b[1]));
}
__device__ __forceinline__ uint32_t f2tf32(float x) {
    uint32_t r; asm("cvt.rna.tf32.f32 %0, %1;" : "=r"(r) : "f"(x)); return r;
}
__device__ __forceinline__ float tf32f(float x) { return __uint_as_float(f2tf32(x)); }
__device__ __forceinline__ uint32_t fu(float x) { return __float_as_uint(x); }

__device__ __forceinline__ uint32_t smem_u32_of(const void* p) {
    uint32_t a;
    asm("{ .reg .u64 t; cvta.to.shared.u64 t, %1; cvt.u32.u64 %0, t; }" : "=r"(a) : "l"(p));
    return a;
}
__device__ __forceinline__ void cpa16(uint32_t dst, const void* src) {
    asm volatile("cp.async.cg.shared.global [%0], [%1], 16;"
                 :: "r"(dst), "l"(src) : "memory");
}
#define CP_COMMIT() asm volatile("cp.async.commit_group;" ::: "memory")
#define CP_WAIT0()  asm volatile("cp.async.wait_group 0;" ::: "memory")

// ---------------- static device scratch ------------------------------------
__device__ float g_xg[(size_t)Bb * Tt * Gg];     // 1.0 GiB gate pre-activations
__device__ float g_hseq[(size_t)Bb * Tt * Hh];   // 256 MiB layer-0 hidden seq
__device__ float g_hbuf[2 * (size_t)Bb * Hh];    // double-buffered h
__device__ unsigned int g_bar_count;             // grid barrier counter

__global__ void init_kernel() {
    unsigned idx = blockIdx.x * blockDim.x + threadIdx.x;
    if (idx < 2u * Bb * Hh) g_hbuf[idx] = 0.f;
    if (idx == 0) g_bar_count = 0u;
}

// ================= tf32 mma GEMM (validated, unchanged) =====================
#define GP 36
#define SA_BUF (128 * GP)
#define GEMM_SMEM_BYTES (4 * SA_BUF * 4)

__global__ void __launch_bounds__(256)
mma_gemm(const float* __restrict__ A, const float* __restrict__ W,
         const float* __restrict__ b1, const float* __restrict__ b2,
         float* __restrict__ C, int K)
{
    extern __shared__ float sm[];
    float* sA = sm;
    float* sB = sm + 2 * SA_BUF;

    const int tid = threadIdx.x;
    const int lane = tid & 31;
    const int wid = tid >> 5;
    const int gid = lane >> 2;
    const int tq = lane & 3;
    const int warpM = wid >> 2;
    const int warpN = wid & 3;
    const size_t n0 = (size_t)blockIdx.x * 128;
    const size_t m0 = (size_t)blockIdx.y * 128;
    const int NC = K >> 5;

    const int lrow = tid >> 3;
    const int lq = tid & 7;

    float acc[4][4][4];
#pragma unroll
    for (int mt = 0; mt < 4; ++mt)
#pragma unroll
        for (int nt = 0; nt < 4; ++nt)
#pragma unroll
            for (int k = 0; k < 4; ++k) acc[mt][nt][k] = 0.f;

    float4 pa[4], pb[4];
#pragma unroll
    for (int i = 0; i < 4; ++i) {
        int row = lrow + i * 32;
        pa[i] = *reinterpret_cast<const float4*>(&A[(m0 + row) * (size_t)K + lq * 4]);
        pb[i] = *reinterpret_cast<const float4*>(&W[(n0 + row) * (size_t)K + lq * 4]);
    }
#pragma unroll
    for (int i = 0; i < 4; ++i) {
        int row = lrow + i * 32;
        float* ap = &sA[row * GP + lq * 4];
        ap[0] = tf32f(pa[i].x); ap[1] = tf32f(pa[i].y); ap[2] = tf32f(pa[i].z); ap[3] = tf32f(pa[i].w);
        float* bp = &sB[row * GP + lq * 4];
        bp[0] = tf32f(pb[i].x); bp[1] = tf32f(pb[i].y); bp[2] = tf32f(pb[i].z); bp[3] = tf32f(pb[i].w);
    }
    __syncthreads();

#pragma unroll 1
    for (int c = 0; c < NC; ++c) {
        const int buf = c & 1;
        if (c + 1 < NC) {
            int k0 = (c + 1) * 32;
#pragma unroll
            for (int i = 0; i < 4; ++i) {
                int row = lrow + i * 32;
                pa[i] = *reinterpret_cast<const float4*>(&A[(m0 + row) * (size_t)K + k0 + lq * 4]);
                pb[i] = *reinterpret_cast<const float4*>(&W[(n0 + row) * (size_t)K + k0 + lq * 4]);
            }
        }
        const float* sAb = sA + buf * SA_BUF;
        const float* sBb = sB + buf * SA_BUF;
#pragma unroll
        for (int kk = 0; kk < 4; ++kk) {
            uint32_t a[4][4];
#pragma unroll
            for (int mt = 0; mt < 4; ++mt) {
                const float* ap = sAb + (warpM * 64 + mt * 16 + gid) * GP + kk * 8 + tq;
                a[mt][0] = fu(ap[0]);
                a[mt][1] = fu(ap[8 * GP]);
                a[mt][2] = fu(ap[4]);
                a[mt][3] = fu(ap[8 * GP + 4]);
            }
            uint32_t bf[4][2];
#pragma unroll
            for (int nt = 0; nt < 4; ++nt) {
                const float* bp = sBb + (warpN * 32 + nt * 8 + gid) * GP + kk * 8 + tq;
                bf[nt][0] = fu(bp[0]);
                bf[nt][1] = fu(bp[4]);
            }
#pragma unroll
            for (int mt = 0; mt < 4; ++mt)
#pragma unroll
                for (int nt = 0; nt < 4; ++nt)
                    mma_tf32(acc[mt][nt], a[mt], bf[nt]);
        }
        __syncthreads();
        if (c + 1 < NC) {
            float* dA = sA + (buf ^ 1) * SA_BUF;
            float* dB = sB + (buf ^ 1) * SA_BUF;
#pragma unroll
            for (int i = 0; i < 4; ++i) {
                int row = lrow + i * 32;
                float* ap = &dA[row * GP + lq * 4];
                ap[0] = tf32f(pa[i].x); ap[1] = tf32f(pa[i].y); ap[2] = tf32f(pa[i].z); ap[3] = tf32f(pa[i].w);
                float* bp = &dB[row * GP + lq * 4];
                bp[0] = tf32f(pb[i].x); bp[1] = tf32f(pb[i].y); bp[2] = tf32f(pb[i].z); bp[3] = tf32f(pb[i].w);
            }
            __syncthreads();
        }
    }

    float bias[4][2];
#pragma unroll
    for (int nt = 0; nt < 4; ++nt) {
        size_t ncol = n0 + warpN * 32 + nt * 8 + tq * 2;
        bias[nt][0] = b1[ncol] + b2[ncol];
        bias[nt][1] = b1[ncol + 1] + b2[ncol + 1];
    }
#pragma unroll
    for (int mt = 0; mt < 4; ++mt) {
        size_t r0 = m0 + warpM * 64 + mt * 16 + gid;
#pragma unroll
        for (int nt = 0; nt < 4; ++nt) {
            size_t ncol = n0 + warpN * 32 + nt * 8 + tq * 2;
            float2 v0, v1;
            v0.x = acc[mt][nt][0] + bias[nt][0];
            v0.y = acc[mt][nt][1] + bias[nt][1];
            v1.x = acc[mt][nt][2] + bias[nt][0];
            v1.y = acc[mt][nt][3] + bias[nt][1];
            *reinterpret_cast<float2*>(&C[r0 * Gg + ncol]) = v0;
            *reinterpret_cast<float2*>(&C[(r0 + 8) * Gg + ncol]) = v1;
        }
    }
}

// ================= persistent LSTM recurrence (512 threads) =================
// 128 CTAs = 4 M-tiles x 32 col-tiles. 16 warps = 2M x 2N x 4K-split.
// Warp tile 32m x 32gc x 32k/chunk. Same fragment bytes & L2 traffic as the
// 256-thread version; 4 warps/SMSP for latency hiding. 2-level K reduction.
#define NCTA_R 128
#define RWP 516
#define RHP 132
#define SH_BUF (64 * RHP)
#define XGP 68
#define REC_SMEM_FLOATS (64 * RWP + 2 * SH_BUF + 64 * XGP)
#define REC_SMEM_BYTES (REC_SMEM_FLOATS * 4)

__device__ __forceinline__ float sigmoidf_(float x) {
    return 1.0f / (1.0f + __expf(-x));
}

__global__ void __launch_bounds__(512, 1)
lstm_rec(const float* __restrict__ W_hh, const float* __restrict__ xg,
         float* __restrict__ hseq)
{
    extern __shared__ float sm[];
    float* sW  = sm;                      // [64][516] tf32(rna)
    float* sH  = sm + 64 * RWP;           // 2 x [64][132] raw f32
    float* sXG = sH + 2 * SH_BUF;         // [64][68] raw f32
    float* sRed = sH;                     // alias h buf0 (region0+1: 32KB)

    const uint32_t sH_u  = smem_u32_of(sH);
    const uint32_t sXG_u = smem_u32_of(sXG);

    const int tid = threadIdx.x;
    const int lane = tid & 31;
    const int wid = tid >> 5;             // 0..15
    const int wK = wid >> 2;              // 0..3 k-split
    const int wM = (wid >> 1) & 1;        // 0..1
    const int wN = wid & 1;               // 0..1
    const int gid = lane >> 2;
    const int tq = lane & 3;
    const int p = lane & 1;

    const int ctaM = blockIdx.x & 3;
    const int ctaC = blockIdx.x >> 2;
    const int m0 = ctaM * 64;
    const int hc0 = ctaC * 16;

    // staging decomposition (512 threads)
    const int hr = tid >> 3;              // 0..63 h row
    const int hq0 = tid & 7;              // 16B slot base (its of 8)
    const int xr = tid >> 3;              // 0..63 xg row
    const int xq0 = tid & 7;

    // W_hh slice -> smem (tf32 rna), row j = cl*4 + g
    for (int idx = tid; idx < 64 * 512; idx += 512) {
        int j = idx >> 9, k = idx & 511;
        sW[j * RWP + k] = tf32f(W_hh[((size_t)(j & 3) * Hh + hc0 + (j >> 2)) * Hh + k]);
    }
    __syncthreads();

    float cst[8];
#pragma unroll
    for (int s = 0; s < 8; ++s) cst[s] = 0.f;
    unsigned phase = 0;
    const int pair = wM * 2 + wN;

    // ---- xg(0) cp.async ----
#pragma unroll
    for (int it = 0; it < 2; ++it) {
        int qc = xq0 + it * 8;
        cpa16(sXG_u + (xr * XGP + qc * 4) * 4,
              &xg[((size_t)(m0 + xr) * Tt + 0) * Gg + (size_t)(qc >> 2) * Hh + hc0 + (qc & 3) * 4]);
    }
    CP_COMMIT();

    for (int t = 0; t < Tt; ++t) {
        const float* hin = g_hbuf + (size_t)(t & 1) * Bb * Hh;
        float* hout = g_hbuf + (size_t)((t + 1) & 1) * Bb * Hh;

        // ---- h chunk 0 -> buf 0 via cp.async ----
#pragma unroll
        for (int it = 0; it < 4; ++it) {
            int q = hq0 + it * 8;
            cpa16(sH_u + (hr * RHP + q * 4) * 4,
                  &hin[(size_t)(m0 + hr) * Hh + q * 4]);
        }
        CP_COMMIT();
        CP_WAIT0();
        __syncthreads();

        float acc[2][4][4];
#pragma unroll
        for (int mt = 0; mt < 2; ++mt)
#pragma unroll
            for (int nt = 0; nt < 4; ++nt)
#pragma unroll
                for (int k = 0; k < 4; ++k) acc[mt][nt][k] = 0.f;

        // ---- 4-chunk mainloop, one sync per chunk ----
#pragma unroll
        for (int cc = 0; cc < 4; ++cc) {
            if (cc < 3) {
                int kb = (cc + 1) * 128;
                uint32_t dstb = sH_u + ((cc + 1) & 1) * (SH_BUF * 4);
#pragma unroll
                for (int it = 0; it < 4; ++it) {
                    int q = hq0 + it * 8;
                    cpa16(dstb + (hr * RHP + q * 4) * 4,
                          &hin[(size_t)(m0 + hr) * Hh + kb + q * 4]);
                }
                CP_COMMIT();
            }
            const float* sHb = sH + (cc & 1) * SH_BUF;
            const int kq0 = wK * 32;
            const int wcol0 = cc * 128 + kq0;
#pragma unroll
            for (int kk = 0; kk < 4; ++kk) {
                uint32_t a[2][4];
#pragma unroll
                for (int mt = 0; mt < 2; ++mt) {
                    const float* ap = sHb + (wM * 32 + mt * 16 + gid) * RHP + kq0 + kk * 8 + tq;
                    a[mt][0] = fu(ap[0]);
                    a[mt][1] = fu(ap[8 * RHP]);
                    a[mt][2] = fu(ap[4]);
                    a[mt][3] = fu(ap[8 * RHP + 4]);
                }
#pragma unroll
                for (int nt = 0; nt < 4; ++nt) {
                    const float* bp = sW + (wN * 32 + nt * 8 + gid) * RWP + wcol0 + kk * 8 + tq;
                    uint32_t bfr[2];
                    bfr[0] = fu(bp[0]);
                    bfr[1] = fu(bp[4]);
#pragma unroll
                    for (int mt = 0; mt < 2; ++mt)
                        mma_tf32(acc[mt][nt], a[mt], bfr);
                }
            }
            if (cc == 3 && wK >= 2) {
                // level-1 partials: wK2 -> region0, wK3 -> region1 (32KB <= buf0)
                int base = (((wK - 2) * 4 + pair) * 8) * 128;
#pragma unroll
                for (int mt = 0; mt < 2; ++mt)
#pragma unroll
                    for (int nt = 0; nt < 4; ++nt) {
                        float4 v;
                        v.x = acc[mt][nt][0]; v.y = acc[mt][nt][1];
                        v.z = acc[mt][nt][2]; v.w = acc[mt][nt][3];
                        *reinterpret_cast<float4*>(
                            &sRed[base + (mt * 4 + nt) * 128 + lane * 4]) = v;
                    }
            }
            if (cc < 3) CP_WAIT0();
            __syncthreads();
        }

        // ---- level-1 combine: wK0 += region0, wK1 += region1 ----
        if (wK < 2) {
            int base = ((wK * 4 + pair) * 8) * 128;
#pragma unroll
            for (int mt = 0; mt < 2; ++mt)
#pragma unroll
                for (int nt = 0; nt < 4; ++nt) {
                    float4 v = *reinterpret_cast<const float4*>(
                        &sRed[base + (mt * 4 + nt) * 128 + lane * 4]);
                    acc[mt][nt][0] += v.x; acc[mt][nt][1] += v.y;
                    acc[mt][nt][2] += v.z; acc[mt][nt][3] += v.w;
                }
        }
        if (wK == 1) {
            // write combined (wK1+wK3) into region1
            int base = ((1 * 4 + pair) * 8) * 128;
#pragma unroll
            for (int mt = 0; mt < 2; ++mt)
#pragma unroll
                for (int nt = 0; nt < 4; ++nt) {
                    float4 v;
                    v.x = acc[mt][nt][0]; v.y = acc[mt][nt][1];
                    v.z = acc[mt][nt][2]; v.w = acc[mt][nt][3];
                    *reinterpret_cast<float4*>(
                        &sRed[base + (mt * 4 + nt) * 128 + lane * 4]) = v;
                }
        }
        __syncthreads();

        if (wK == 0) {
            int base = ((1 * 4 + pair) * 8) * 128;
#pragma unroll
            for (int mt = 0; mt < 2; ++mt)
#pragma unroll
                for (int nt = 0; nt < 4; ++nt) {
                    float4 v = *reinterpret_cast<const float4*>(
                        &sRed[base + (mt * 4 + nt) * 128 + lane * 4]);
                    acc[mt][nt][0] += v.x; acc[mt][nt][1] += v.y;
                    acc[mt][nt][2] += v.z; acc[mt][nt][3] += v.w;
                }

            // ---- epilogue: gate exchange + cell update + h write ----
#pragma unroll
            for (int mt = 0; mt < 2; ++mt) {
                int rl = wM * 32 + mt * 16 + gid + p * 8;
                size_t grow = m0 + rl;
#pragma unroll
                for (int nt = 0; nt < 4; ++nt) {
                    float s0 = p ? acc[mt][nt][0] : acc[mt][nt][2];
                    float s1 = p ? acc[mt][nt][1] : acc[mt][nt][3];
                    float r0 = __shfl_xor_sync(0xffffffffu, s0, 1);
                    float r1 = __shfl_xor_sync(0xffffffffu, s1, 1);
                    float gi = p ? r0 : acc[mt][nt][0];
                    float gf = p ? r1 : acc[mt][nt][1];
                    float gg = p ? acc[mt][nt][2] : r0;
                    float go = p ? acc[mt][nt][3] : r1;
                    int cl = wN * 8 + nt * 2 + (tq >> 1);
                    const float* xp = &sXG[rl * XGP + cl];
                    float iv = sigmoidf_(gi + xp[0]);
                    float fv = sigmoidf_(gf + xp[16]);
                    float gv = tanhf(gg + xp[32]);
                    float ov = sigmoidf_(go + xp[48]);
                    int slot = mt * 4 + nt;
                    cst[slot] = fv * cst[slot] + iv * gv;
                    float hv = ov * tanhf(cst[slot]);
                    hout[grow * Hh + hc0 + cl] = hv;
                    if (hseq) hseq[(grow * Tt + t) * Hh + hc0 + cl] = hv;
                }
            }
        }

        // ---- pre-barrier sync (protects sXG), then xg(t+1) cp.async ----
        __syncthreads();
        if (t + 1 < Tt) {
#pragma unroll
            for (int it = 0; it < 2; ++it) {
                int qc = xq0 + it * 8;
                cpa16(sXG_u + (xr * XGP + qc * 4) * 4,
                      &xg[((size_t)(m0 + xr) * Tt + (t + 1)) * Gg
                          + (size_t)(qc >> 2) * Hh + hc0 + (qc & 3) * 4]);
            }
            CP_COMMIT();
        }

        // ---- grid barrier: release arrive + acquire spin ----
        phase += NCTA_R;
        if (tid == 0) {
            asm volatile("red.release.gpu.add.u32 [%0], %1;"
                         :: "l"(&g_bar_count), "r"(1u) : "memory");
            unsigned v;
            while (true) {
                asm volatile("ld.acquire.gpu.u32 %0, [%1];"
                             : "=r"(v) : "l"(&g_bar_count) : "memory");
                if (v >= phase) break;
                __nanosleep(16);
            }
        }
        __syncthreads();
    }
}

// ---------------- final FC --------------------------------------------------
__global__ void fc_kernel(const float* __restrict__ h, const float* __restrict__ Wfc,
                          const float* __restrict__ bfc, float* __restrict__ out)
{
    int b = blockIdx.x;
    int tid = threadIdx.x;
    float s = 0.f;
    for (int k = tid; k < Hh; k += 128)
        s += h[(size_t)b * Hh + k] * Wfc[k];
#pragma unroll
    for (int o = 16; o > 0; o >>= 1) s += __shfl_xor_sync(0xffffffffu, s, o);
    __shared__ float ws[4];
    if ((tid & 31) == 0) ws[tid >> 5] = s;
    __syncthreads();
    if (tid == 0) out[b] = ws[0] + ws[1] + ws[2] + ws[3] + bfc[0];
}

// ---------------- launch ----------------------------------------------------
extern "C" void kernel_launch(void* const* d_in, const int* in_sizes, int n_in,
                              void* d_out, int out_size)
{
    (void)in_sizes; (void)n_in; (void)out_size;
    const float* x     = (const float*)d_in[0];
    const float* W_ih0 = (const float*)d_in[1];
    const float* W_hh0 = (const float*)d_in[2];
    const float* b_ih0 = (const float*)d_in[3];
    const float* b_hh0 = (const float*)d_in[4];
    const float* W_ih1 = (const float*)d_in[5];
    const float* W_hh1 = (const float*)d_in[6];
    const float* b_ih1 = (const float*)d_in[7];
    const float* b_hh1 = (const float*)d_in[8];
    const float* W_fc  = (const float*)d_in[9];
    const float* b_fc  = (const float*)d_in[10];
    float* out = (float*)d_out;

    void *p_xg = nullptr, *p_hseq = nullptr, *p_hbuf = nullptr;
    cudaGetSymbolAddress(&p_xg, g_xg);
    cudaGetSymbolAddress(&p_hseq, g_hseq);
    cudaGetSymbolAddress(&p_hbuf, g_hbuf);

    cudaFuncSetAttribute(mma_gemm, cudaFuncAttributeMaxDynamicSharedMemorySize,
                         GEMM_SMEM_BYTES);
    cudaFuncSetAttribute(lstm_rec, cudaFuncAttributeMaxDynamicSharedMemorySize,
                         REC_SMEM_BYTES);

    dim3 ggrid(Gg / 128, (Bb * Tt) / 128);   // (16, 1024)

    // Layer 0
    mma_gemm<<<ggrid, 256, GEMM_SMEM_BYTES>>>(x, W_ih0, b_ih0, b_hh0, (float*)p_xg, Ii);
    init_kernel<<<1024, 256>>>();
    lstm_rec<<<NCTA_R, 512, REC_SMEM_BYTES>>>(W_hh0, (const float*)p_xg, (float*)p_hseq);

    // Layer 1
    mma_gemm<<<ggrid, 256, GEMM_SMEM_BYTES>>>((const float*)p_hseq, W_ih1, b_ih1, b_hh1,
                                              (float*)p_xg, Hh);
    init_kernel<<<1024, 256>>>();
    lstm_rec<<<NCTA_R, 512, REC_SMEM_BYTES>>>(W_hh1, (const float*)p_xg, nullptr);

    // Final FC (h_last ends in buffer 0 since T=512 is even)
    fc_kernel<<<Bb, 128>>>((const float*)p_hbuf, W_fc, b_fc, out);
}

// round 9
// speedup vs baseline: 1.3453x; 1.3453x over previous
#include <cuda_runtime.h>
#include <cstdint>
#include <cstddef>

#define Bb 256
#define Tt 512
#define Ii 64
#define Hh 512
#define Gg 2048   // 4*H

// ---------------- tf32 mma.sync helpers (baseline PTX, sm_80+) -------------
__device__ __forceinline__ void mma_tf32(float* d, const uint32_t* a, const uint32_t* b) {
    asm volatile(
        "mma.sync.aligned.m16n8k8.row.col.f32.tf32.tf32.f32 "
        "{%0,%1,%2,%3}, {%4,%5,%6,%7}, {%8,%9}, {%0,%1,%2,%3};"
        : "+f"(d[0]), "+f"(d[1]), "+f"(d[2]), "+f"(d[3])
        : "r"(a[0]), "r"(a[1]), "r"(a[2]), "r"(a[3]), "r"(b[0]), "r"(b[1]));
}
__device__ __forceinline__ uint32_t f2tf32(float x) {
    uint32_t r; asm("cvt.rna.tf32.f32 %0, %1;" : "=r"(r) : "f"(x)); return r;
}
__device__ __forceinline__ float tf32f(float x) { return __uint_as_float(f2tf32(x)); }
__device__ __forceinline__ uint32_t fu(float x) { return __float_as_uint(x); }

__device__ __forceinline__ uint32_t smem_u32_of(const void* p) {
    uint32_t a;
    asm("{ .reg .u64 t; cvta.to.shared.u64 t, %1; cvt.u32.u64 %0, t; }" : "=r"(a) : "l"(p));
    return a;
}
__device__ __forceinline__ void cpa16(uint32_t dst, const void* src) {
    asm volatile("cp.async.cg.shared.global [%0], [%1], 16;"
                 :: "r"(dst), "l"(src) : "memory");
}
#define CP_COMMIT() asm volatile("cp.async.commit_group;" ::: "memory")
#define CP_WAIT0()  asm volatile("cp.async.wait_group 0;" ::: "memory")

// k-interleave within 8-groups: k = 8g + tq + 4h  ->  pos = 8g + 2*tq + h
__device__ __forceinline__ int kint(int k) {
    return (k & ~7) | (((k & 3) << 1) | ((k >> 2) & 1));
}

// ---------------- static device scratch ------------------------------------
__device__ float g_xg[(size_t)Bb * Tt * Gg];     // 1.0 GiB gate pre-activations
__device__ float g_hseq[(size_t)Bb * Tt * Hh];   // 256 MiB layer-0 hidden (canonical)
__device__ float g_hbuf[2 * (size_t)Bb * Hh];    // double-buffered h (k-PERMUTED)
__device__ unsigned int g_bar[4];                // per-ctaM-group barriers

__global__ void init_kernel() {
    unsigned idx = blockIdx.x * blockDim.x + threadIdx.x;
    if (idx < 2u * Bb * Hh) g_hbuf[idx] = 0.f;
    if (idx < 4) g_bar[idx] = 0u;
}

// ================= tf32 mma GEMM (validated, unchanged) =====================
#define GP 36
#define SA_BUF (128 * GP)
#define GEMM_SMEM_BYTES (4 * SA_BUF * 4)

__global__ void __launch_bounds__(256)
mma_gemm(const float* __restrict__ A, const float* __restrict__ W,
         const float* __restrict__ b1, const float* __restrict__ b2,
         float* __restrict__ C, int K)
{
    extern __shared__ float sm[];
    float* sA = sm;
    float* sB = sm + 2 * SA_BUF;

    const int tid = threadIdx.x;
    const int lane = tid & 31;
    const int wid = tid >> 5;
    const int gid = lane >> 2;
    const int tq = lane & 3;
    const int warpM = wid >> 2;
    const int warpN = wid & 3;
    const size_t n0 = (size_t)blockIdx.x * 128;
    const size_t m0 = (size_t)blockIdx.y * 128;
    const int NC = K >> 5;

    const int lrow = tid >> 3;
    const int lq = tid & 7;

    float acc[4][4][4];
#pragma unroll
    for (int mt = 0; mt < 4; ++mt)
#pragma unroll
        for (int nt = 0; nt < 4; ++nt)
#pragma unroll
            for (int k = 0; k < 4; ++k) acc[mt][nt][k] = 0.f;

    float4 pa[4], pb[4];
#pragma unroll
    for (int i = 0; i < 4; ++i) {
        int row = lrow + i * 32;
        pa[i] = *reinterpret_cast<const float4*>(&A[(m0 + row) * (size_t)K + lq * 4]);
        pb[i] = *reinterpret_cast<const float4*>(&W[(n0 + row) * (size_t)K + lq * 4]);
    }
#pragma unroll
    for (int i = 0; i < 4; ++i) {
        int row = lrow + i * 32;
        float* ap = &sA[row * GP + lq * 4];
        ap[0] = tf32f(pa[i].x); ap[1] = tf32f(pa[i].y); ap[2] = tf32f(pa[i].z); ap[3] = tf32f(pa[i].w);
        float* bp = &sB[row * GP + lq * 4];
        bp[0] = tf32f(pb[i].x); bp[1] = tf32f(pb[i].y); bp[2] = tf32f(pb[i].z); bp[3] = tf32f(pb[i].w);
    }
    __syncthreads();

#pragma unroll 1
    for (int c = 0; c < NC; ++c) {
        const int buf = c & 1;
        if (c + 1 < NC) {
            int k0 = (c + 1) * 32;
#pragma unroll
            for (int i = 0; i < 4; ++i) {
                int row = lrow + i * 32;
                pa[i] = *reinterpret_cast<const float4*>(&A[(m0 + row) * (size_t)K + k0 + lq * 4]);
                pb[i] = *reinterpret_cast<const float4*>(&W[(n0 + row) * (size_t)K + k0 + lq * 4]);
            }
        }
        const float* sAb = sA + buf * SA_BUF;
        const float* sBb = sB + buf * SA_BUF;
#pragma unroll
        for (int kk = 0; kk < 4; ++kk) {
            uint32_t a[4][4];
#pragma unroll
            for (int mt = 0; mt < 4; ++mt) {
                const float* ap = sAb + (warpM * 64 + mt * 16 + gid) * GP + kk * 8 + tq;
                a[mt][0] = fu(ap[0]);
                a[mt][1] = fu(ap[8 * GP]);
                a[mt][2] = fu(ap[4]);
                a[mt][3] = fu(ap[8 * GP + 4]);
            }
            uint32_t bf[4][2];
#pragma unroll
            for (int nt = 0; nt < 4; ++nt) {
                const float* bp = sBb + (warpN * 32 + nt * 8 + gid) * GP + kk * 8 + tq;
                bf[nt][0] = fu(bp[0]);
                bf[nt][1] = fu(bp[4]);
            }
#pragma unroll
            for (int mt = 0; mt < 4; ++mt)
#pragma unroll
                for (int nt = 0; nt < 4; ++nt)
                    mma_tf32(acc[mt][nt], a[mt], bf[nt]);
        }
        __syncthreads();
        if (c + 1 < NC) {
            float* dA = sA + (buf ^ 1) * SA_BUF;
            float* dB = sB + (buf ^ 1) * SA_BUF;
#pragma unroll
            for (int i = 0; i < 4; ++i) {
                int row = lrow + i * 32;
                float* ap = &dA[row * GP + lq * 4];
                ap[0] = tf32f(pa[i].x); ap[1] = tf32f(pa[i].y); ap[2] = tf32f(pa[i].z); ap[3] = tf32f(pa[i].w);
                float* bp = &dB[row * GP + lq * 4];
                bp[0] = tf32f(pb[i].x); bp[1] = tf32f(pb[i].y); bp[2] = tf32f(pb[i].z); bp[3] = tf32f(pb[i].w);
            }
            __syncthreads();
        }
    }

    float bias[4][2];
#pragma unroll
    for (int nt = 0; nt < 4; ++nt) {
        size_t ncol = n0 + warpN * 32 + nt * 8 + tq * 2;
        bias[nt][0] = b1[ncol] + b2[ncol];
        bias[nt][1] = b1[ncol + 1] + b2[ncol + 1];
    }
#pragma unroll
    for (int mt = 0; mt < 4; ++mt) {
        size_t r0 = m0 + warpM * 64 + mt * 16 + gid;
#pragma unroll
        for (int nt = 0; nt < 4; ++nt) {
            size_t ncol = n0 + warpN * 32 + nt * 8 + tq * 2;
            float2 v0, v1;
            v0.x = acc[mt][nt][0] + bias[nt][0];
            v0.y = acc[mt][nt][1] + bias[nt][1];
            v1.x = acc[mt][nt][2] + bias[nt][0];
            v1.y = acc[mt][nt][3] + bias[nt][1];
            *reinterpret_cast<float2*>(&C[r0 * Gg + ncol]) = v0;
            *reinterpret_cast<float2*>(&C[(r0 + 8) * Gg + ncol]) = v1;
        }
    }
}

// ================= persistent LSTM recurrence (R6 base + LDS.64 frags) ======
// 128 CTAs = 4 M-tiles x 32 col-tiles. 256 threads = 8 warps = 2M x 2N x 2K.
// W k-interleaved in smem; global h k-PERMUTED so fragment pairs are LDS.64.
// Per-ctaM group barriers (32 CTAs each).
#define NCTA_R 128
#define GRP_CTAS 32
#define RWP 516
#define RHP 132
#define SH_BUF (64 * RHP)
#define XGP 68
#define REC_SMEM_FLOATS (64 * RWP + 2 * SH_BUF + 64 * XGP)
#define REC_SMEM_BYTES (REC_SMEM_FLOATS * 4)

__device__ __forceinline__ float sigmoidf_(float x) {
    return 1.0f / (1.0f + __expf(-x));
}

__global__ void __launch_bounds__(256, 1)
lstm_rec(const float* __restrict__ W_hh, const float* __restrict__ xg,
         float* __restrict__ hseq)
{
    extern __shared__ float sm[];
    float* sW  = sm;                      // [64][516] tf32(rna), k-interleaved
    float* sH  = sm + 64 * RWP;           // 2 x [64][132] raw f32 (k-permuted)
    float* sXG = sH + 2 * SH_BUF;         // [64][68] raw f32 (canonical)
    float* sRed = sH;                     // alias h buffer 0

    const uint32_t sH_u  = smem_u32_of(sH);
    const uint32_t sXG_u = smem_u32_of(sXG);

    const int tid = threadIdx.x;
    const int lane = tid & 31;
    const int wid = tid >> 5;
    const int wK = wid >> 2;
    const int wM = (wid >> 1) & 1;
    const int wN = wid & 1;
    const int gid = lane >> 2;
    const int tq = lane & 3;
    const int p = lane & 1;

    const int ctaM = blockIdx.x & 3;
    const int ctaC = blockIdx.x >> 2;
    const int m0 = ctaM * 64;
    const int hc0 = ctaC * 16;

    const int hr = tid >> 5;              // h staging rows (8 passes)
    const int hq = tid & 31;
    const int xr = tid >> 4;              // xg staging rows (4 passes)
    const int xq = tid & 15;

    // W_hh slice -> smem (tf32 rna), row j = cl*4 + g, k-interleaved columns
    for (int idx = tid; idx < 64 * 512; idx += 256) {
        int j = idx >> 9, k = idx & 511;
        sW[j * RWP + kint(k)] = tf32f(W_hh[((size_t)(j & 3) * Hh + hc0 + (j >> 2)) * Hh + k]);
    }
    __syncthreads();

    float cst[8];
#pragma unroll
    for (int s = 0; s < 8; ++s) cst[s] = 0.f;
    unsigned phase = 0;

    // ---- xg(0) cp.async ----
#pragma unroll
    for (int it = 0; it < 4; ++it) {
        int row = xr + it * 16;
        cpa16(sXG_u + (row * XGP + xq * 4) * 4,
              &xg[((size_t)(m0 + row) * Tt + 0) * Gg + (size_t)(xq >> 2) * Hh + hc0 + (xq & 3) * 4]);
    }
    CP_COMMIT();

    for (int t = 0; t < Tt; ++t) {
        const float* hin = g_hbuf + (size_t)(t & 1) * Bb * Hh;
        float* hout = g_hbuf + (size_t)((t + 1) & 1) * Bb * Hh;

        // ---- h chunk 0 -> buf 0 via cp.async (verbatim; already permuted) --
#pragma unroll
        for (int it = 0; it < 8; ++it) {
            int r = hr + it * 8;
            cpa16(sH_u + (r * RHP + hq * 4) * 4,
                  &hin[(size_t)(m0 + r) * Hh + hq * 4]);
        }
        CP_COMMIT();
        CP_WAIT0();
        __syncthreads();

        float acc[2][4][4];
#pragma unroll
        for (int mt = 0; mt < 2; ++mt)
#pragma unroll
            for (int nt = 0; nt < 4; ++nt)
#pragma unroll
                for (int k = 0; k < 4; ++k) acc[mt][nt][k] = 0.f;

        // ---- 4-chunk mainloop, one sync per chunk ----
#pragma unroll
        for (int cc = 0; cc < 4; ++cc) {
            if (cc < 3) {
                int kb = (cc + 1) * 128;
                uint32_t dstb = sH_u + ((cc + 1) & 1) * (SH_BUF * 4);
#pragma unroll
                for (int it = 0; it < 8; ++it) {
                    int r = hr + it * 8;
                    cpa16(dstb + (r * RHP + hq * 4) * 4,
                          &hin[(size_t)(m0 + r) * Hh + kb + hq * 4]);
                }
                CP_COMMIT();
            }
            const float* sHb = sH + (cc & 1) * SH_BUF;
            const int kq0 = wK * 64;
            const int wcol0 = cc * 128 + kq0;
#pragma unroll
            for (int kk = 0; kk < 8; ++kk) {
                uint32_t a[2][4];
#pragma unroll
                for (int mt = 0; mt < 2; ++mt) {
                    const float* ap = sHb + (wM * 32 + mt * 16 + gid) * RHP + kq0 + kk * 8 + 2 * tq;
                    float2 v0 = *reinterpret_cast<const float2*>(ap);
                    float2 v1 = *reinterpret_cast<const float2*>(ap + 8 * RHP);
                    a[mt][0] = fu(v0.x);
                    a[mt][2] = fu(v0.y);
                    a[mt][1] = fu(v1.x);
                    a[mt][3] = fu(v1.y);
                }
#pragma unroll
                for (int nt = 0; nt < 4; ++nt) {
                    const float* bp = sW + (wN * 32 + nt * 8 + gid) * RWP + wcol0 + kk * 8 + 2 * tq;
                    float2 vb = *reinterpret_cast<const float2*>(bp);
                    uint32_t bfr[2];
                    bfr[0] = fu(vb.x);
                    bfr[1] = fu(vb.y);
#pragma unroll
                    for (int mt = 0; mt < 2; ++mt)
                        mma_tf32(acc[mt][nt], a[mt], bfr);
                }
            }
            if (cc == 3 && wK == 1) {
                int pair = wM * 2 + wN;
#pragma unroll
                for (int mt = 0; mt < 2; ++mt)
#pragma unroll
                    for (int nt = 0; nt < 4; ++nt) {
                        float4 v;
                        v.x = acc[mt][nt][0]; v.y = acc[mt][nt][1];
                        v.z = acc[mt][nt][2]; v.w = acc[mt][nt][3];
                        *reinterpret_cast<float4*>(
                            &sRed[(pair * 8 + mt * 4 + nt) * 128 + lane * 4]) = v;
                    }
            }
            if (cc < 3) CP_WAIT0();
            __syncthreads();
        }

        if (wK == 0) {
            int pair = wM * 2 + wN;
#pragma unroll
            for (int mt = 0; mt < 2; ++mt)
#pragma unroll
                for (int nt = 0; nt < 4; ++nt) {
                    float4 v = *reinterpret_cast<const float4*>(
                        &sRed[(pair * 8 + mt * 4 + nt) * 128 + lane * 4]);
                    acc[mt][nt][0] += v.x; acc[mt][nt][1] += v.y;
                    acc[mt][nt][2] += v.z; acc[mt][nt][3] += v.w;
                }

            // ---- epilogue: gate exchange + cell update + h write ----
#pragma unroll
            for (int mt = 0; mt < 2; ++mt) {
                int rl = wM * 32 + mt * 16 + gid + p * 8;
                size_t grow = m0 + rl;
#pragma unroll
                for (int nt = 0; nt < 4; ++nt) {
                    float s0 = p ? acc[mt][nt][0] : acc[mt][nt][2];
                    float s1 = p ? acc[mt][nt][1] : acc[mt][nt][3];
                    float r0 = __shfl_xor_sync(0xffffffffu, s0, 1);
                    float r1 = __shfl_xor_sync(0xffffffffu, s1, 1);
                    float gi = p ? r0 : acc[mt][nt][0];
                    float gf = p ? r1 : acc[mt][nt][1];
                    float gg = p ? acc[mt][nt][2] : r0;
                    float go = p ? acc[mt][nt][3] : r1;
                    int cl = wN * 8 + nt * 2 + (tq >> 1);
                    const float* xp = &sXG[rl * XGP + cl];
                    float iv = sigmoidf_(gi + xp[0]);
                    float fv = sigmoidf_(gf + xp[16]);
                    float gv = tanhf(gg + xp[32]);
                    float ov = sigmoidf_(go + xp[48]);
                    int slot = mt * 4 + nt;
                    cst[slot] = fv * cst[slot] + iv * gv;
                    float hv = ov * tanhf(cst[slot]);
                    // h write: k-PERMUTED column position
                    hout[grow * Hh + hc0 + kint(cl)] = hv;
                    // hseq: canonical
                    if (hseq) hseq[(grow * Tt + t) * Hh + hc0 + cl] = hv;
                }
            }
        }

        // ---- pre-barrier sync, then xg(t+1) cp.async ----
        __syncthreads();
        if (t + 1 < Tt) {
#pragma unroll
            for (int it = 0; it < 4; ++it) {
                int row = xr + it * 16;
                cpa16(sXG_u + (row * XGP + xq * 4) * 4,
                      &xg[((size_t)(m0 + row) * Tt + (t + 1)) * Gg
                          + (size_t)(xq >> 2) * Hh + hc0 + (xq & 3) * 4]);
            }
            CP_COMMIT();
        }

        // ---- per-ctaM-group barrier: release arrive + acquire spin ----
        phase += GRP_CTAS;
        if (tid == 0) {
            asm volatile("red.release.gpu.add.u32 [%0], %1;"
                         :: "l"(&g_bar[ctaM]), "r"(1u) : "memory");
            unsigned v;
            while (true) {
                asm volatile("ld.acquire.gpu.u32 %0, [%1];"
                             : "=r"(v) : "l"(&g_bar[ctaM]) : "memory");
                if (v >= phase) break;
                __nanosleep(32);
            }
        }
        __syncthreads();
    }
}

// ---------------- final FC (h in permuted layout) ---------------------------
__global__ void fc_kernel(const float* __restrict__ h, const float* __restrict__ Wfc,
                          const float* __restrict__ bfc, float* __restrict__ out)
{
    int b = blockIdx.x;
    int tid = threadIdx.x;
    float s = 0.f;
    for (int pos = tid; pos < Hh; pos += 128) {
        int k = (pos & ~7) | ((pos >> 1) & 3) | ((pos & 1) << 2);
        s += h[(size_t)b * Hh + pos] * Wfc[k];
    }
#pragma unroll
    for (int o = 16; o > 0; o >>= 1) s += __shfl_xor_sync(0xffffffffu, s, o);
    __shared__ float ws[4];
    if ((tid & 31) == 0) ws[tid >> 5] = s;
    __syncthreads();
    if (tid == 0) out[b] = ws[0] + ws[1] + ws[2] + ws[3] + bfc[0];
}

// ---------------- launch ----------------------------------------------------
extern "C" void kernel_launch(void* const* d_in, const int* in_sizes, int n_in,
                              void* d_out, int out_size)
{
    (void)in_sizes; (void)n_in; (void)out_size;
    const float* x     = (const float*)d_in[0];
    const float* W_ih0 = (const float*)d_in[1];
    const float* W_hh0 = (const float*)d_in[2];
    const float* b_ih0 = (const float*)d_in[3];
    const float* b_hh0 = (const float*)d_in[4];
    const float* W_ih1 = (const float*)d_in[5];
    const float* W_hh1 = (const float*)d_in[6];
    const float* b_ih1 = (const float*)d_in[7];
    const float* b_hh1 = (const float*)d_in[8];
    const float* W_fc  = (const float*)d_in[9];
    const float* b_fc  = (const float*)d_in[10];
    float* out = (float*)d_out;

    void *p_xg = nullptr, *p_hseq = nullptr, *p_hbuf = nullptr;
    cudaGetSymbolAddress(&p_xg, g_xg);
    cudaGetSymbolAddress(&p_hseq, g_hseq);
    cudaGetSymbolAddress(&p_hbuf, g_hbuf);

    cudaFuncSetAttribute(mma_gemm, cudaFuncAttributeMaxDynamicSharedMemorySize,
                         GEMM_SMEM_BYTES);
    cudaFuncSetAttribute(lstm_rec, cudaFuncAttributeMaxDynamicSharedMemorySize,
                         REC_SMEM_BYTES);

    dim3 ggrid(Gg / 128, (Bb * Tt) / 128);   // (16, 1024)

    // Layer 0
    mma_gemm<<<ggrid, 256, GEMM_SMEM_BYTES>>>(x, W_ih0, b_ih0, b_hh0, (float*)p_xg, Ii);
    init_kernel<<<1024, 256>>>();
    lstm_rec<<<NCTA_R, 256, REC_SMEM_BYTES>>>(W_hh0, (const float*)p_xg, (float*)p_hseq);

    // Layer 1
    mma_gemm<<<ggrid, 256, GEMM_SMEM_BYTES>>>((const float*)p_hseq, W_ih1, b_ih1, b_hh1,
                                              (float*)p_xg, Hh);
    init_kernel<<<1024, 256>>>();
    lstm_rec<<<NCTA_R, 256, REC_SMEM_BYTES>>>(W_hh1, (const float*)p_xg, nullptr);

    // Final FC (h_last ends in buffer 0 since T=512 is even; permuted layout)
    fc_kernel<<<Bb, 128>>>((const float*)p_hbuf, W_fc, b_fc, out);
}

// round 10
// speedup vs baseline: 1.8278x; 1.3587x over previous
#include <cuda_runtime.h>
#include <cuda_fp16.h>
#include <cstdint>
#include <cstddef>

#define Bb 256
#define Tt 512
#define Ii 64
#define Hh 512
#define Gg 2048   // 4*H

// ---------------- mma.sync helpers (baseline PTX, sm_80+) ------------------
__device__ __forceinline__ void mma_tf32(float* d, const uint32_t* a, const uint32_t* b) {
    asm volatile(
        "mma.sync.aligned.m16n8k8.row.col.f32.tf32.tf32.f32 "
        "{%0,%1,%2,%3}, {%4,%5,%6,%7}, {%8,%9}, {%0,%1,%2,%3};"
        : "+f"(d[0]), "+f"(d[1]), "+f"(d[2]), "+f"(d[3])
        : "r"(a[0]), "r"(a[1]), "r"(a[2]), "r"(a[3]), "r"(b[0]), "r"(b[1]));
}
__device__ __forceinline__ void mma_f16(float* d, const uint32_t* a, const uint32_t* b) {
    asm volatile(
        "mma.sync.aligned.m16n8k16.row.col.f32.f16.f16.f32 "
        "{%0,%1,%2,%3}, {%4,%5,%6,%7}, {%8,%9}, {%0,%1,%2,%3};"
        : "+f"(d[0]), "+f"(d[1]), "+f"(d[2]), "+f"(d[3])
        : "r"(a[0]), "r"(a[1]), "r"(a[2]), "r"(a[3]), "r"(b[0]), "r"(b[1]));
}
__device__ __forceinline__ uint32_t f2tf32(float x) {
    uint32_t r; asm("cvt.rna.tf32.f32 %0, %1;" : "=r"(r) : "f"(x)); return r;
}
__device__ __forceinline__ float tf32f(float x) { return __uint_as_float(f2tf32(x)); }
__device__ __forceinline__ uint32_t fu(float x) { return __float_as_uint(x); }

__device__ __forceinline__ uint32_t smem_u32_of(const void* p) {
    uint32_t a;
    asm("{ .reg .u64 t; cvta.to.shared.u64 t, %1; cvt.u32.u64 %0, t; }" : "=r"(a) : "l"(p));
    return a;
}
__device__ __forceinline__ void cpa16(uint32_t dst, const void* src) {
    asm volatile("cp.async.cg.shared.global [%0], [%1], 16;"
                 :: "r"(dst), "l"(src) : "memory");
}
#define CP_COMMIT() asm volatile("cp.async.commit_group;" ::: "memory")
#define CP_WAIT0()  asm volatile("cp.async.wait_group 0;" ::: "memory")

// ---------------- static device scratch ------------------------------------
__device__ float  g_xg[(size_t)Bb * Tt * Gg];    // 1.0 GiB gate pre-activations
__device__ float  g_hseq[(size_t)Bb * Tt * Hh];  // 256 MiB layer-0 hidden (f32)
__device__ __half g_hbuf[2 * (size_t)Bb * Hh];   // double-buffered h (fp16)
__device__ unsigned int g_bar_count;             // grid barrier counter

__global__ void init_kernel() {
    unsigned idx = blockIdx.x * blockDim.x + threadIdx.x;
    // 2*Bb*Hh halves = 262144 uints; grid is 1024x256 = 262144 threads
    reinterpret_cast<unsigned int*>(g_hbuf)[idx] = 0u;
    if (idx == 0) g_bar_count = 0u;
}

// ================= tf32 mma GEMM (validated, unchanged) =====================
#define GP 36
#define SA_BUF (128 * GP)
#define GEMM_SMEM_BYTES (4 * SA_BUF * 4)

__global__ void __launch_bounds__(256)
mma_gemm(const float* __restrict__ A, const float* __restrict__ W,
         const float* __restrict__ b1, const float* __restrict__ b2,
         float* __restrict__ C, int K)
{
    extern __shared__ float sm[];
    float* sA = sm;
    float* sB = sm + 2 * SA_BUF;

    const int tid = threadIdx.x;
    const int lane = tid & 31;
    const int wid = tid >> 5;
    const int gid = lane >> 2;
    const int tq = lane & 3;
    const int warpM = wid >> 2;
    const int warpN = wid & 3;
    const size_t n0 = (size_t)blockIdx.x * 128;
    const size_t m0 = (size_t)blockIdx.y * 128;
    const int NC = K >> 5;

    const int lrow = tid >> 3;
    const int lq = tid & 7;

    float acc[4][4][4];
#pragma unroll
    for (int mt = 0; mt < 4; ++mt)
#pragma unroll
        for (int nt = 0; nt < 4; ++nt)
#pragma unroll
            for (int k = 0; k < 4; ++k) acc[mt][nt][k] = 0.f;

    float4 pa[4], pb[4];
#pragma unroll
    for (int i = 0; i < 4; ++i) {
        int row = lrow + i * 32;
        pa[i] = *reinterpret_cast<const float4*>(&A[(m0 + row) * (size_t)K + lq * 4]);
        pb[i] = *reinterpret_cast<const float4*>(&W[(n0 + row) * (size_t)K + lq * 4]);
    }
#pragma unroll
    for (int i = 0; i < 4; ++i) {
        int row = lrow + i * 32;
        float* ap = &sA[row * GP + lq * 4];
        ap[0] = tf32f(pa[i].x); ap[1] = tf32f(pa[i].y); ap[2] = tf32f(pa[i].z); ap[3] = tf32f(pa[i].w);
        float* bp = &sB[row * GP + lq * 4];
        bp[0] = tf32f(pb[i].x); bp[1] = tf32f(pb[i].y); bp[2] = tf32f(pb[i].z); bp[3] = tf32f(pb[i].w);
    }
    __syncthreads();

#pragma unroll 1
    for (int c = 0; c < NC; ++c) {
        const int buf = c & 1;
        if (c + 1 < NC) {
            int k0 = (c + 1) * 32;
#pragma unroll
            for (int i = 0; i < 4; ++i) {
                int row = lrow + i * 32;
                pa[i] = *reinterpret_cast<const float4*>(&A[(m0 + row) * (size_t)K + k0 + lq * 4]);
                pb[i] = *reinterpret_cast<const float4*>(&W[(n0 + row) * (size_t)K + k0 + lq * 4]);
            }
        }
        const float* sAb = sA + buf * SA_BUF;
        const float* sBb = sB + buf * SA_BUF;
#pragma unroll
        for (int kk = 0; kk < 4; ++kk) {
            uint32_t a[4][4];
#pragma unroll
            for (int mt = 0; mt < 4; ++mt) {
                const float* ap = sAb + (warpM * 64 + mt * 16 + gid) * GP + kk * 8 + tq;
                a[mt][0] = fu(ap[0]);
                a[mt][1] = fu(ap[8 * GP]);
                a[mt][2] = fu(ap[4]);
                a[mt][3] = fu(ap[8 * GP + 4]);
            }
            uint32_t bf[4][2];
#pragma unroll
            for (int nt = 0; nt < 4; ++nt) {
                const float* bp = sBb + (warpN * 32 + nt * 8 + gid) * GP + kk * 8 + tq;
                bf[nt][0] = fu(bp[0]);
                bf[nt][1] = fu(bp[4]);
            }
#pragma unroll
            for (int mt = 0; mt < 4; ++mt)
#pragma unroll
                for (int nt = 0; nt < 4; ++nt)
                    mma_tf32(acc[mt][nt], a[mt], bf[nt]);
        }
        __syncthreads();
        if (c + 1 < NC) {
            float* dA = sA + (buf ^ 1) * SA_BUF;
            float* dB = sB + (buf ^ 1) * SA_BUF;
#pragma unroll
            for (int i = 0; i < 4; ++i) {
                int row = lrow + i * 32;
                float* ap = &dA[row * GP + lq * 4];
                ap[0] = tf32f(pa[i].x); ap[1] = tf32f(pa[i].y); ap[2] = tf32f(pa[i].z); ap[3] = tf32f(pa[i].w);
                float* bp = &dB[row * GP + lq * 4];
                bp[0] = tf32f(pb[i].x); bp[1] = tf32f(pb[i].y); bp[2] = tf32f(pb[i].z); bp[3] = tf32f(pb[i].w);
            }
            __syncthreads();
        }
    }

    float bias[4][2];
#pragma unroll
    for (int nt = 0; nt < 4; ++nt) {
        size_t ncol = n0 + warpN * 32 + nt * 8 + tq * 2;
        bias[nt][0] = b1[ncol] + b2[ncol];
        bias[nt][1] = b1[ncol + 1] + b2[ncol + 1];
    }
#pragma unroll
    for (int mt = 0; mt < 4; ++mt) {
        size_t r0 = m0 + warpM * 64 + mt * 16 + gid;
#pragma unroll
        for (int nt = 0; nt < 4; ++nt) {
            size_t ncol = n0 + warpN * 32 + nt * 8 + tq * 2;
            float2 v0, v1;
            v0.x = acc[mt][nt][0] + bias[nt][0];
            v0.y = acc[mt][nt][1] + bias[nt][1];
            v1.x = acc[mt][nt][2] + bias[nt][0];
            v1.y = acc[mt][nt][3] + bias[nt][1];
            *reinterpret_cast<float2*>(&C[r0 * Gg + ncol]) = v0;
            *reinterpret_cast<float2*>(&C[(r0 + 8) * Gg + ncol]) = v1;
        }
    }
}

// ================= persistent LSTM recurrence (fp16 m16n8k16) ===============
// 128 CTAs = 4 M-tiles x 32 col-tiles. 256 threads = 8 warps = 2M x 2N x 2K.
// h (fp16) staged whole-512k in one cp.async wave (single buffer, no inner
// syncs). W fp16 in smem. mma m16n8k16 f16 -> f32. 4 syncs/step.
#define NCTA_R 128
#define RWPH 520                         // W pitch (halves)
#define RHPH 520                         // h pitch (halves)
#define XGP 68
#define SM_W_BYTES   (64 * RWPH * 2)     // 66560
#define SM_H_BYTES   (64 * RHPH * 2)     // 66560
#define SM_XG_BYTES  (64 * XGP * 4)      // 17408
#define SM_RED_BYTES (4096 * 4)          // 16384
#define REC_SMEM_BYTES (SM_W_BYTES + SM_H_BYTES + SM_XG_BYTES + SM_RED_BYTES)

__device__ __forceinline__ float sigmoidf_(float x) {
    return 1.0f / (1.0f + __expf(-x));
}

__global__ void __launch_bounds__(256, 1)
lstm_rec(const float* __restrict__ W_hh, const float* __restrict__ xg,
         float* __restrict__ hseq)
{
    extern __shared__ char smc[];
    __half* sWh = reinterpret_cast<__half*>(smc);
    __half* sHh = reinterpret_cast<__half*>(smc + SM_W_BYTES);
    float*  sXG = reinterpret_cast<float*>(smc + SM_W_BYTES + SM_H_BYTES);
    float*  sRed = reinterpret_cast<float*>(smc + SM_W_BYTES + SM_H_BYTES + SM_XG_BYTES);

    const uint32_t sH_u  = smem_u32_of(sHh);
    const uint32_t sXG_u = smem_u32_of(sXG);

    const int tid = threadIdx.x;
    const int lane = tid & 31;
    const int wid = tid >> 5;
    const int wK = wid >> 2;              // 0..1 (256 k each)
    const int wM = (wid >> 1) & 1;        // 0..1 (32 rows)
    const int wN = wid & 1;               // 0..1 (32 gatecols)
    const int gid = lane >> 2;
    const int tq = lane & 3;
    const int p = lane & 1;

    const int ctaM = blockIdx.x & 3;
    const int ctaC = blockIdx.x >> 2;
    const int m0 = ctaM * 64;
    const int hc0 = ctaC * 16;

    const int xr = tid >> 4;              // xg staging rows (4 passes)
    const int xq = tid & 15;

    // W_hh slice -> smem (fp16 rne), row j = cl*4 + g
    for (int idx = tid; idx < 64 * 512; idx += 256) {
        int j = idx >> 9, k = idx & 511;
        sWh[j * RWPH + k] =
            __float2half_rn(W_hh[((size_t)(j & 3) * Hh + hc0 + (j >> 2)) * Hh + k]);
    }
    __syncthreads();

    float cst[8];
#pragma unroll
    for (int s = 0; s < 8; ++s) cst[s] = 0.f;
    unsigned phase = 0;
    const int pair = wM * 2 + wN;

    // ---- xg(0) cp.async ----
#pragma unroll
    for (int it = 0; it < 4; ++it) {
        int row = xr + it * 16;
        cpa16(sXG_u + (row * XGP + xq * 4) * 4,
              &xg[((size_t)(m0 + row) * Tt + 0) * Gg + (size_t)(xq >> 2) * Hh + hc0 + (xq & 3) * 4]);
    }
    CP_COMMIT();

    for (int t = 0; t < Tt; ++t) {
        const __half* hin = g_hbuf + (size_t)(t & 1) * Bb * Hh;
        __half* hout = g_hbuf + (size_t)((t + 1) & 1) * Bb * Hh;

        // ---- whole h tile (64 x 512 fp16 = 64KB) in one cp.async wave ----
#pragma unroll
        for (int it = 0; it < 16; ++it) {
            int seg = tid + it * 256;
            int row = seg >> 6;            // 64 x 16B segments per row
            int c16 = seg & 63;
            cpa16(sH_u + row * (RHPH * 2) + c16 * 16,
                  hin + (size_t)(m0 + row) * Hh + c16 * 8);
        }
        CP_COMMIT();
        CP_WAIT0();                        // also drains xg group
        __syncthreads();                   // (1)

        float acc[2][4][4];
#pragma unroll
        for (int mt = 0; mt < 2; ++mt)
#pragma unroll
            for (int nt = 0; nt < 4; ++nt)
#pragma unroll
                for (int k = 0; k < 4; ++k) acc[mt][nt][k] = 0.f;

        // ---- mainloop: 16 x k16 mma, NO internal syncs ----
        const int kq0 = wK * 256;
#pragma unroll
        for (int kk = 0; kk < 16; ++kk) {
            const int k0 = kq0 + kk * 16;
            uint32_t a[2][4];
#pragma unroll
            for (int mt = 0; mt < 2; ++mt) {
                const __half* ap = sHh + (wM * 32 + mt * 16 + gid) * RHPH + k0 + 2 * tq;
                a[mt][0] = *reinterpret_cast<const uint32_t*>(ap);
                a[mt][1] = *reinterpret_cast<const uint32_t*>(ap + 8 * RHPH);
                a[mt][2] = *reinterpret_cast<const uint32_t*>(ap + 8);
                a[mt][3] = *reinterpret_cast<const uint32_t*>(ap + 8 * RHPH + 8);
            }
#pragma unroll
            for (int nt = 0; nt < 4; ++nt) {
                const __half* bp = sWh + (wN * 32 + nt * 8 + gid) * RWPH + k0 + 2 * tq;
                uint32_t bfr[2];
                bfr[0] = *reinterpret_cast<const uint32_t*>(bp);
                bfr[1] = *reinterpret_cast<const uint32_t*>(bp + 8);
#pragma unroll
                for (int mt = 0; mt < 2; ++mt)
                    mma_f16(acc[mt][nt], a[mt], bfr);
            }
        }

        // ---- K-split partials (dedicated sRed region, no hazard) ----
        if (wK == 1) {
#pragma unroll
            for (int mt = 0; mt < 2; ++mt)
#pragma unroll
                for (int nt = 0; nt < 4; ++nt) {
                    float4 v;
                    v.x = acc[mt][nt][0]; v.y = acc[mt][nt][1];
                    v.z = acc[mt][nt][2]; v.w = acc[mt][nt][3];
                    *reinterpret_cast<float4*>(
                        &sRed[(pair * 8 + mt * 4 + nt) * 128 + lane * 4]) = v;
                }
        }
        __syncthreads();                   // (2)

        if (wK == 0) {
#pragma unroll
            for (int mt = 0; mt < 2; ++mt)
#pragma unroll
                for (int nt = 0; nt < 4; ++nt) {
                    float4 v = *reinterpret_cast<const float4*>(
                        &sRed[(pair * 8 + mt * 4 + nt) * 128 + lane * 4]);
                    acc[mt][nt][0] += v.x; acc[mt][nt][1] += v.y;
                    acc[mt][nt][2] += v.z; acc[mt][nt][3] += v.w;
                }

            // ---- epilogue: gate exchange + cell update + h write (fp16) ----
#pragma unroll
            for (int mt = 0; mt < 2; ++mt) {
                int rl = wM * 32 + mt * 16 + gid + p * 8;
                size_t grow = m0 + rl;
#pragma unroll
                for (int nt = 0; nt < 4; ++nt) {
                    float s0 = p ? acc[mt][nt][0] : acc[mt][nt][2];
                    float s1 = p ? acc[mt][nt][1] : acc[mt][nt][3];
                    float r0 = __shfl_xor_sync(0xffffffffu, s0, 1);
                    float r1 = __shfl_xor_sync(0xffffffffu, s1, 1);
                    float gi = p ? r0 : acc[mt][nt][0];
                    float gf = p ? r1 : acc[mt][nt][1];
                    float gg = p ? acc[mt][nt][2] : r0;
                    float go = p ? acc[mt][nt][3] : r1;
                    int cl = wN * 8 + nt * 2 + (tq >> 1);
                    const float* xp = &sXG[rl * XGP + cl];
                    float iv = sigmoidf_(gi + xp[0]);
                    float fv = sigmoidf_(gf + xp[16]);
                    float gv = tanhf(gg + xp[32]);
                    float ov = sigmoidf_(go + xp[48]);
                    int slot = mt * 4 + nt;
                    cst[slot] = fv * cst[slot] + iv * gv;
                    float hv = ov * tanhf(cst[slot]);
                    hout[grow * Hh + hc0 + cl] = __float2half_rn(hv);
                    if (hseq) hseq[(grow * Tt + t) * Hh + hc0 + cl] = hv;
                }
            }
        }

        // ---- pre-barrier sync (protects sXG), then xg(t+1) cp.async ----
        __syncthreads();                   // (3)
        if (t + 1 < Tt) {
#pragma unroll
            for (int it = 0; it < 4; ++it) {
                int row = xr + it * 16;
                cpa16(sXG_u + (row * XGP + xq * 4) * 4,
                      &xg[((size_t)(m0 + row) * Tt + (t + 1)) * Gg
                          + (size_t)(xq >> 2) * Hh + hc0 + (xq & 3) * 4]);
            }
            CP_COMMIT();
        }

        // ---- grid barrier: release arrive + acquire spin ----
        phase += NCTA_R;
        if (tid == 0) {
            asm volatile("red.release.gpu.add.u32 [%0], %1;"
                         :: "l"(&g_bar_count), "r"(1u) : "memory");
            unsigned v;
            while (true) {
                asm volatile("ld.acquire.gpu.u32 %0, [%1];"
                             : "=r"(v) : "l"(&g_bar_count) : "memory");
                if (v >= phase) break;
                __nanosleep(32);
            }
        }
        __syncthreads();                   // (4)
    }
}

// ---------------- final FC (h is fp16) --------------------------------------
__global__ void fc_kernel(const __half* __restrict__ h, const float* __restrict__ Wfc,
                          const float* __restrict__ bfc, float* __restrict__ out)
{
    int b = blockIdx.x;
    int tid = threadIdx.x;
    float s = 0.f;
    for (int k = tid; k < Hh; k += 128)
        s += __half2float(h[(size_t)b * Hh + k]) * Wfc[k];
#pragma unroll
    for (int o = 16; o > 0; o >>= 1) s += __shfl_xor_sync(0xffffffffu, s, o);
    __shared__ float ws[4];
    if ((tid & 31) == 0) ws[tid >> 5] = s;
    __syncthreads();
    if (tid == 0) out[b] = ws[0] + ws[1] + ws[2] + ws[3] + bfc[0];
}

// ---------------- launch ----------------------------------------------------
extern "C" void kernel_launch(void* const* d_in, const int* in_sizes, int n_in,
                              void* d_out, int out_size)
{
    (void)in_sizes; (void)n_in; (void)out_size;
    const float* x     = (const float*)d_in[0];
    const float* W_ih0 = (const float*)d_in[1];
    const float* W_hh0 = (const float*)d_in[2];
    const float* b_ih0 = (const float*)d_in[3];
    const float* b_hh0 = (const float*)d_in[4];
    const float* W_ih1 = (const float*)d_in[5];
    const float* W_hh1 = (const float*)d_in[6];
    const float* b_ih1 = (const float*)d_in[7];
    const float* b_hh1 = (const float*)d_in[8];
    const float* W_fc  = (const float*)d_in[9];
    const float* b_fc  = (const float*)d_in[10];
    float* out = (float*)d_out;

    void *p_xg = nullptr, *p_hseq = nullptr, *p_hbuf = nullptr;
    cudaGetSymbolAddress(&p_xg, g_xg);
    cudaGetSymbolAddress(&p_hseq, g_hseq);
    cudaGetSymbolAddress(&p_hbuf, g_hbuf);

    cudaFuncSetAttribute(mma_gemm, cudaFuncAttributeMaxDynamicSharedMemorySize,
                         GEMM_SMEM_BYTES);
    cudaFuncSetAttribute(lstm_rec, cudaFuncAttributeMaxDynamicSharedMemorySize,
                         REC_SMEM_BYTES);

    dim3 ggrid(Gg / 128, (Bb * Tt) / 128);   // (16, 1024)

    // Layer 0
    mma_gemm<<<ggrid, 256, GEMM_SMEM_BYTES>>>(x, W_ih0, b_ih0, b_hh0, (float*)p_xg, Ii);
    init_kernel<<<1024, 256>>>();
    lstm_rec<<<NCTA_R, 256, REC_SMEM_BYTES>>>(W_hh0, (const float*)p_xg, (float*)p_hseq);

    // Layer 1
    mma_gemm<<<ggrid, 256, GEMM_SMEM_BYTES>>>((const float*)p_hseq, W_ih1, b_ih1, b_hh1,
                                              (float*)p_xg, Hh);
    init_kernel<<<1024, 256>>>();
    lstm_rec<<<NCTA_R, 256, REC_SMEM_BYTES>>>(W_hh1, (const float*)p_xg, nullptr);

    // Final FC (h_last ends in buffer 0 since T=512 is even; fp16 layout)
    fc_kernel<<<Bb, 128>>>((const __half*)p_hbuf, W_fc, b_fc, out);
}

// round 11
// speedup vs baseline: 1.9593x; 1.0719x over previous
#include <cuda_runtime.h>
#include <cuda_fp16.h>
#include <cstdint>
#include <cstddef>

#define Bb 256
#define Tt 512
#define Ii 64
#define Hh 512
#define Gg 2048   // 4*H

// ---------------- mma.sync helpers (baseline PTX, sm_80+) ------------------
__device__ __forceinline__ void mma_f16(float* d, const uint32_t* a, const uint32_t* b) {
    asm volatile(
        "mma.sync.aligned.m16n8k16.row.col.f32.f16.f16.f32 "
        "{%0,%1,%2,%3}, {%4,%5,%6,%7}, {%8,%9}, {%0,%1,%2,%3};"
        : "+f"(d[0]), "+f"(d[1]), "+f"(d[2]), "+f"(d[3])
        : "r"(a[0]), "r"(a[1]), "r"(a[2]), "r"(a[3]), "r"(b[0]), "r"(b[1]));
}
__device__ __forceinline__ uint32_t ldu32(const __half* p) {
    return *reinterpret_cast<const uint32_t*>(p);
}
__device__ __forceinline__ uint32_t h2u(__half2 v) {
    return *reinterpret_cast<uint32_t*>(&v);
}
__device__ __forceinline__ uint32_t smem_u32_of(const void* p) {
    uint32_t a;
    asm("{ .reg .u64 t; cvta.to.shared.u64 t, %1; cvt.u32.u64 %0, t; }" : "=r"(a) : "l"(p));
    return a;
}
__device__ __forceinline__ void cpa16(uint32_t dst, const void* src) {
    asm volatile("cp.async.cg.shared.global [%0], [%1], 16;"
                 :: "r"(dst), "l"(src) : "memory");
}
#define CP_COMMIT() asm volatile("cp.async.commit_group;" ::: "memory")
#define CP_WAIT0()  asm volatile("cp.async.wait_group 0;" ::: "memory")

// ---------------- static device scratch ------------------------------------
__device__ float  g_xg[(size_t)Bb * Tt * Gg];    // 1.0 GiB gate pre-activations
__device__ float  g_hseq[(size_t)Bb * Tt * Hh];  // 256 MiB layer-0 hidden (f32)
__device__ __half g_hbuf[2 * (size_t)Bb * Hh];   // double-buffered h (fp16)
__device__ unsigned int g_bar_count;             // grid barrier counter

__global__ void init_kernel() {
    unsigned idx = blockIdx.x * blockDim.x + threadIdx.x;
    reinterpret_cast<unsigned int*>(g_hbuf)[idx] = 0u;
    if (idx == 0) g_bar_count = 0u;
}

// ================= fp16 mma GEMM ============================================
// C[M,2048] = A[M,K] @ W[2048,K]^T + b1 + b2 (fp16 rne operands, f32 accum)
// CTA tile 128x128, 8 warps (2M x 4N), warp 64x32. 32-k chunks, double buf.
#define GPH 40
#define SABUF_H (128 * GPH)                    // halves per buffer
#define GEMM_SMEM_BYTES (4 * SABUF_H * 2)      // 40960 B

__global__ void __launch_bounds__(256)
mma_gemm(const float* __restrict__ A, const float* __restrict__ W,
         const float* __restrict__ b1, const float* __restrict__ b2,
         float* __restrict__ C, int K)
{
    extern __shared__ __half smh[];
    __half* sA = smh;                          // 2 x [128][GPH]
    __half* sB = smh + 2 * SABUF_H;            // 2 x [128][GPH]

    const int tid = threadIdx.x;
    const int lane = tid & 31;
    const int wid = tid >> 5;
    const int gid = lane >> 2;
    const int tq = lane & 3;
    const int warpM = wid >> 2;
    const int warpN = wid & 3;
    const size_t n0 = (size_t)blockIdx.x * 128;
    const size_t m0 = (size_t)blockIdx.y * 128;
    const int NC = K >> 5;

    const int lrow = tid >> 3;
    const int lq = tid & 7;

    float acc[4][4][4];
#pragma unroll
    for (int mt = 0; mt < 4; ++mt)
#pragma unroll
        for (int nt = 0; nt < 4; ++nt)
#pragma unroll
            for (int k = 0; k < 4; ++k) acc[mt][nt][k] = 0.f;

    float4 pa[4], pb[4];
#pragma unroll
    for (int i = 0; i < 4; ++i) {
        int row = lrow + i * 32;
        pa[i] = *reinterpret_cast<const float4*>(&A[(m0 + row) * (size_t)K + lq * 4]);
        pb[i] = *reinterpret_cast<const float4*>(&W[(n0 + row) * (size_t)K + lq * 4]);
    }
#pragma unroll
    for (int i = 0; i < 4; ++i) {
        int row = lrow + i * 32;
        uint2 ua, ub;
        ua.x = h2u(__floats2half2_rn(pa[i].x, pa[i].y));
        ua.y = h2u(__floats2half2_rn(pa[i].z, pa[i].w));
        ub.x = h2u(__floats2half2_rn(pb[i].x, pb[i].y));
        ub.y = h2u(__floats2half2_rn(pb[i].z, pb[i].w));
        *reinterpret_cast<uint2*>(&sA[row * GPH + lq * 4]) = ua;
        *reinterpret_cast<uint2*>(&sB[row * GPH + lq * 4]) = ub;
    }
    __syncthreads();

#pragma unroll 1
    for (int c = 0; c < NC; ++c) {
        const int buf = c & 1;
        if (c + 1 < NC) {
            int k0 = (c + 1) * 32;
#pragma unroll
            for (int i = 0; i < 4; ++i) {
                int row = lrow + i * 32;
                pa[i] = *reinterpret_cast<const float4*>(&A[(m0 + row) * (size_t)K + k0 + lq * 4]);
                pb[i] = *reinterpret_cast<const float4*>(&W[(n0 + row) * (size_t)K + k0 + lq * 4]);
            }
        }
        const __half* sAb = sA + buf * SABUF_H;
        const __half* sBb = sB + buf * SABUF_H;
#pragma unroll
        for (int kk = 0; kk < 2; ++kk) {
            const int k0 = kk * 16;
            uint32_t a[4][4];
#pragma unroll
            for (int mt = 0; mt < 4; ++mt) {
                const __half* ap = sAb + (warpM * 64 + mt * 16 + gid) * GPH + k0 + 2 * tq;
                a[mt][0] = ldu32(ap);
                a[mt][1] = ldu32(ap + 8 * GPH);
                a[mt][2] = ldu32(ap + 8);
                a[mt][3] = ldu32(ap + 8 * GPH + 8);
            }
            uint32_t bf[4][2];
#pragma unroll
            for (int nt = 0; nt < 4; ++nt) {
                const __half* bp = sBb + (warpN * 32 + nt * 8 + gid) * GPH + k0 + 2 * tq;
                bf[nt][0] = ldu32(bp);
                bf[nt][1] = ldu32(bp + 8);
            }
#pragma unroll
            for (int mt = 0; mt < 4; ++mt)
#pragma unroll
                for (int nt = 0; nt < 4; ++nt)
                    mma_f16(acc[mt][nt], a[mt], bf[nt]);
        }
        __syncthreads();
        if (c + 1 < NC) {
            __half* dA = sA + (buf ^ 1) * SABUF_H;
            __half* dB = sB + (buf ^ 1) * SABUF_H;
#pragma unroll
            for (int i = 0; i < 4; ++i) {
                int row = lrow + i * 32;
                uint2 ua, ub;
                ua.x = h2u(__floats2half2_rn(pa[i].x, pa[i].y));
                ua.y = h2u(__floats2half2_rn(pa[i].z, pa[i].w));
                ub.x = h2u(__floats2half2_rn(pb[i].x, pb[i].y));
                ub.y = h2u(__floats2half2_rn(pb[i].z, pb[i].w));
                *reinterpret_cast<uint2*>(&dA[row * GPH + lq * 4]) = ua;
                *reinterpret_cast<uint2*>(&dB[row * GPH + lq * 4]) = ub;
            }
            __syncthreads();
        }
    }

    float bias[4][2];
#pragma unroll
    for (int nt = 0; nt < 4; ++nt) {
        size_t ncol = n0 + warpN * 32 + nt * 8 + tq * 2;
        bias[nt][0] = b1[ncol] + b2[ncol];
        bias[nt][1] = b1[ncol + 1] + b2[ncol + 1];
    }
#pragma unroll
    for (int mt = 0; mt < 4; ++mt) {
        size_t r0 = m0 + warpM * 64 + mt * 16 + gid;
#pragma unroll
        for (int nt = 0; nt < 4; ++nt) {
            size_t ncol = n0 + warpN * 32 + nt * 8 + tq * 2;
            float2 v0, v1;
            v0.x = acc[mt][nt][0] + bias[nt][0];
            v0.y = acc[mt][nt][1] + bias[nt][1];
            v1.x = acc[mt][nt][2] + bias[nt][0];
            v1.y = acc[mt][nt][3] + bias[nt][1];
            *reinterpret_cast<float2*>(&C[r0 * Gg + ncol]) = v0;
            *reinterpret_cast<float2*>(&C[(r0 + 8) * Gg + ncol]) = v1;
        }
    }
}

// ================= persistent LSTM recurrence (fp16, split-half staging) ====
// 128 CTAs = 4 M-tiles x 32 col-tiles. 256 threads = 8 warps = 2M x 2N x 2K.
// Threads 0-127 stage & consume k[0,256); threads 128-255 stage & consume
// k[256,512). Named barriers (1/2) decouple the halves until the reduction.
#define NCTA_R 128
#define RWPH 520                         // W pitch (halves)
#define RHPH 520                         // h pitch (halves)
#define XGP 68
#define SM_W_BYTES   (64 * RWPH * 2)     // 66560
#define SM_H_BYTES   (64 * RHPH * 2)     // 66560
#define SM_XG_BYTES  (64 * XGP * 4)      // 17408
#define SM_RED_BYTES (4096 * 4)          // 16384
#define REC_SMEM_BYTES (SM_W_BYTES + SM_H_BYTES + SM_XG_BYTES + SM_RED_BYTES)

__device__ __forceinline__ float sigmoidf_(float x) {
    return 1.0f / (1.0f + __expf(-x));
}

__global__ void __launch_bounds__(256, 1)
lstm_rec(const float* __restrict__ W_hh, const float* __restrict__ xg,
         float* __restrict__ hseq)
{
    extern __shared__ char smc[];
    __half* sWh = reinterpret_cast<__half*>(smc);
    __half* sHh = reinterpret_cast<__half*>(smc + SM_W_BYTES);
    float*  sXG = reinterpret_cast<float*>(smc + SM_W_BYTES + SM_H_BYTES);
    float*  sRed = reinterpret_cast<float*>(smc + SM_W_BYTES + SM_H_BYTES + SM_XG_BYTES);

    const uint32_t sH_u  = smem_u32_of(sHh);
    const uint32_t sXG_u = smem_u32_of(sXG);

    const int tid = threadIdx.x;
    const int lane = tid & 31;
    const int wid = tid >> 5;
    const int wK = wid >> 2;              // 0..1 (256 k each); == (tid>=128)
    const int wM = (wid >> 1) & 1;        // 0..1 (32 rows)
    const int wN = wid & 1;               // 0..1 (32 gatecols)
    const int gid = lane >> 2;
    const int tq = lane & 3;
    const int p = lane & 1;

    const int ctaM = blockIdx.x & 3;
    const int ctaC = blockIdx.x >> 2;
    const int m0 = ctaM * 64;
    const int hc0 = ctaC * 16;

    const int xr = tid >> 4;              // xg staging rows (4 passes)
    const int xq = tid & 15;

    // split-half h staging indices: each half stages its own k-range
    const int half = tid >> 7;            // 0: k[0,256) by thr 0-127; 1: hi half
    const int st = tid & 127;
    const int hcolh = half * 256;         // half offset in halves
    const int hcolb = half * 512;         // half offset in bytes

    // W_hh slice -> smem (fp16 rne), row j = cl*4 + g
    for (int idx = tid; idx < 64 * 512; idx += 256) {
        int j = idx >> 9, k = idx & 511;
        sWh[j * RWPH + k] =
            __float2half_rn(W_hh[((size_t)(j & 3) * Hh + hc0 + (j >> 2)) * Hh + k]);
    }
    __syncthreads();

    float cst[8];
#pragma unroll
    for (int s = 0; s < 8; ++s) cst[s] = 0.f;
    unsigned phase = 0;
    const int pair = wM * 2 + wN;

    // ---- xg(0) cp.async ----
#pragma unroll
    for (int it = 0; it < 4; ++it) {
        int row = xr + it * 16;
        cpa16(sXG_u + (row * XGP + xq * 4) * 4,
              &xg[((size_t)(m0 + row) * Tt + 0) * Gg + (size_t)(xq >> 2) * Hh + hc0 + (xq & 3) * 4]);
    }
    CP_COMMIT();

    for (int t = 0; t < Tt; ++t) {
        const __half* hin = g_hbuf + (size_t)(t & 1) * Bb * Hh;
        __half* hout = g_hbuf + (size_t)((t + 1) & 1) * Bb * Hh;

        // ---- each half-CTA stages its own 64x256 fp16 h region (32KB) ----
#pragma unroll
        for (int it = 0; it < 16; ++it) {
            int seg = st + it * 128;
            int row = seg >> 5;            // 32 x 16B segments per row-half
            int c16 = seg & 31;
            cpa16(sH_u + row * (RHPH * 2) + hcolb + c16 * 16,
                  hin + (size_t)(m0 + row) * Hh + hcolh + c16 * 8);
        }
        CP_COMMIT();
        CP_WAIT0();                        // drains this thread's xg cps too
        if (half == 0) {
            asm volatile("bar.sync 1, 128;" ::: "memory");
        } else {
            asm volatile("bar.sync 2, 128;" ::: "memory");
        }

        float acc[2][4][4];
#pragma unroll
        for (int mt = 0; mt < 2; ++mt)
#pragma unroll
            for (int nt = 0; nt < 4; ++nt)
#pragma unroll
                for (int k = 0; k < 4; ++k) acc[mt][nt][k] = 0.f;

        // ---- mainloop: 16 x k16 mma over this half's k-range ----
        const int kq0 = wK * 256;
#pragma unroll
        for (int kk = 0; kk < 16; ++kk) {
            const int k0 = kq0 + kk * 16;
            uint32_t a[2][4];
#pragma unroll
            for (int mt = 0; mt < 2; ++mt) {
                const __half* ap = sHh + (wM * 32 + mt * 16 + gid) * RHPH + k0 + 2 * tq;
                a[mt][0] = ldu32(ap);
                a[mt][1] = ldu32(ap + 8 * RHPH);
                a[mt][2] = ldu32(ap + 8);
                a[mt][3] = ldu32(ap + 8 * RHPH + 8);
            }
#pragma unroll
            for (int nt = 0; nt < 4; ++nt) {
                const __half* bp = sWh + (wN * 32 + nt * 8 + gid) * RWPH + k0 + 2 * tq;
                uint32_t bfr[2];
                bfr[0] = ldu32(bp);
                bfr[1] = ldu32(bp + 8);
#pragma unroll
                for (int mt = 0; mt < 2; ++mt)
                    mma_f16(acc[mt][nt], a[mt], bfr);
            }
        }

        // ---- K-split partials -> dedicated sRed region ----
        if (wK == 1) {
#pragma unroll
            for (int mt = 0; mt < 2; ++mt)
#pragma unroll
                for (int nt = 0; nt < 4; ++nt) {
                    float4 v;
                    v.x = acc[mt][nt][0]; v.y = acc[mt][nt][1];
                    v.z = acc[mt][nt][2]; v.w = acc[mt][nt][3];
                    *reinterpret_cast<float4*>(
                        &sRed[(pair * 8 + mt * 4 + nt) * 128 + lane * 4]) = v;
                }
        }
        __syncthreads();                   // (2) reduction + xg visibility

        if (wK == 0) {
#pragma unroll
            for (int mt = 0; mt < 2; ++mt)
#pragma unroll
                for (int nt = 0; nt < 4; ++nt) {
                    float4 v = *reinterpret_cast<const float4*>(
                        &sRed[(pair * 8 + mt * 4 + nt) * 128 + lane * 4]);
                    acc[mt][nt][0] += v.x; acc[mt][nt][1] += v.y;
                    acc[mt][nt][2] += v.z; acc[mt][nt][3] += v.w;
                }

            // ---- epilogue: gate exchange + cell update + h write (fp16) ----
#pragma unroll
            for (int mt = 0; mt < 2; ++mt) {
                int rl = wM * 32 + mt * 16 + gid + p * 8;
                size_t grow = m0 + rl;
#pragma unroll
                for (int nt = 0; nt < 4; ++nt) {
                    float s0 = p ? acc[mt][nt][0] : acc[mt][nt][2];
                    float s1 = p ? acc[mt][nt][1] : acc[mt][nt][3];
                    float r0 = __shfl_xor_sync(0xffffffffu, s0, 1);
                    float r1 = __shfl_xor_sync(0xffffffffu, s1, 1);
                    float gi = p ? r0 : acc[mt][nt][0];
                    float gf = p ? r1 : acc[mt][nt][1];
                    float gg = p ? acc[mt][nt][2] : r0;
                    float go = p ? acc[mt][nt][3] : r1;
                    int cl = wN * 8 + nt * 2 + (tq >> 1);
                    const float* xp = &sXG[rl * XGP + cl];
                    float iv = sigmoidf_(gi + xp[0]);
                    float fv = sigmoidf_(gf + xp[16]);
                    float gv = tanhf(gg + xp[32]);
                    float ov = sigmoidf_(go + xp[48]);
                    int slot = mt * 4 + nt;
                    cst[slot] = fv * cst[slot] + iv * gv;
                    float hv = ov * tanhf(cst[slot]);
                    hout[grow * Hh + hc0 + cl] = __float2half_rn(hv);
                    if (hseq) hseq[(grow * Tt + t) * Hh + hc0 + cl] = hv;
                }
            }
        }

        // ---- pre-barrier sync (protects sXG), then xg(t+1) cp.async ----
        __syncthreads();                   // (3)
        if (t + 1 < Tt) {
#pragma unroll
            for (int it = 0; it < 4; ++it) {
                int row = xr + it * 16;
                cpa16(sXG_u + (row * XGP + xq * 4) * 4,
                      &xg[((size_t)(m0 + row) * Tt + (t + 1)) * Gg
                          + (size_t)(xq >> 2) * Hh + hc0 + (xq & 3) * 4]);
            }
            CP_COMMIT();
        }

        // ---- grid barrier: release arrive + acquire spin ----
        phase += NCTA_R;
        if (tid == 0) {
            asm volatile("red.release.gpu.add.u32 [%0], %1;"
                         :: "l"(&g_bar_count), "r"(1u) : "memory");
            unsigned v;
            while (true) {
                asm volatile("ld.acquire.gpu.u32 %0, [%1];"
                             : "=r"(v) : "l"(&g_bar_count) : "memory");
                if (v >= phase) break;
                __nanosleep(32);
            }
        }
        __syncthreads();                   // (4)
    }
}

// ---------------- final FC (h is fp16) --------------------------------------
__global__ void fc_kernel(const __half* __restrict__ h, const float* __restrict__ Wfc,
                          const float* __restrict__ bfc, float* __restrict__ out)
{
    int b = blockIdx.x;
    int tid = threadIdx.x;
    float s = 0.f;
    for (int k = tid; k < Hh; k += 128)
        s += __half2float(h[(size_t)b * Hh + k]) * Wfc[k];
#pragma unroll
    for (int o = 16; o > 0; o >>= 1) s += __shfl_xor_sync(0xffffffffu, s, o);
    __shared__ float ws[4];
    if ((tid & 31) == 0) ws[tid >> 5] = s;
    __syncthreads();
    if (tid == 0) out[b] = ws[0] + ws[1] + ws[2] + ws[3] + bfc[0];
}

// ---------------- launch ----------------------------------------------------
extern "C" void kernel_launch(void* const* d_in, const int* in_sizes, int n_in,
                              void* d_out, int out_size)
{
    (void)in_sizes; (void)n_in; (void)out_size;
    const float* x     = (const float*)d_in[0];
    const float* W_ih0 = (const float*)d_in[1];
    const float* W_hh0 = (const float*)d_in[2];
    const float* b_ih0 = (const float*)d_in[3];
    const float* b_hh0 = (const float*)d_in[4];
    const float* W_ih1 = (const float*)d_in[5];
    const float* W_hh1 = (const float*)d_in[6];
    const float* b_ih1 = (const float*)d_in[7];
    const float* b_hh1 = (const float*)d_in[8];
    const float* W_fc  = (const float*)d_in[9];
    const float* b_fc  = (const float*)d_in[10];
    float* out = (float*)d_out;

    void *p_xg = nullptr, *p_hseq = nullptr, *p_hbuf = nullptr;
    cudaGetSymbolAddress(&p_xg, g_xg);
    cudaGetSymbolAddress(&p_hseq, g_hseq);
    cudaGetSymbolAddress(&p_hbuf, g_hbuf);

    cudaFuncSetAttribute(mma_gemm, cudaFuncAttributeMaxDynamicSharedMemorySize,
                         GEMM_SMEM_BYTES);
    cudaFuncSetAttribute(lstm_rec, cudaFuncAttributeMaxDynamicSharedMemorySize,
                         REC_SMEM_BYTES);

    dim3 ggrid(Gg / 128, (Bb * Tt) / 128);   // (16, 1024)

    // Layer 0
    mma_gemm<<<ggrid, 256, GEMM_SMEM_BYTES>>>(x, W_ih0, b_ih0, b_hh0, (float*)p_xg, Ii);
    init_kernel<<<1024, 256>>>();
    lstm_rec<<<NCTA_R, 256, REC_SMEM_BYTES>>>(W_hh0, (const float*)p_xg, (float*)p_hseq);

    // Layer 1
    mma_gemm<<<ggrid, 256, GEMM_SMEM_BYTES>>>((const float*)p_hseq, W_ih1, b_ih1, b_hh1,
                                              (float*)p_xg, Hh);
    init_kernel<<<1024, 256>>>();
    lstm_rec<<<NCTA_R, 256, REC_SMEM_BYTES>>>(W_hh1, (const float*)p_xg, nullptr);

    // Final FC (h_last ends in buffer 0 since T=512 is even; fp16 layout)
    fc_kernel<<<Bb, 128>>>((const __half*)p_hbuf, W_fc, b_fc, out);
}

// round 12
// speedup vs baseline: 2.0428x; 1.0426x over previous
#include <cuda_runtime.h>
#include <cuda_fp16.h>
#include <cstdint>
#include <cstddef>

#define Bb 256
#define Tt 512
#define Ii 64
#define Hh 512
#define Gg 2048   // 4*H

// ---------------- mma.sync helpers (baseline PTX, sm_80+) ------------------
__device__ __forceinline__ void mma_f16(float* d, const uint32_t* a, const uint32_t* b) {
    asm volatile(
        "mma.sync.aligned.m16n8k16.row.col.f32.f16.f16.f32 "
        "{%0,%1,%2,%3}, {%4,%5,%6,%7}, {%8,%9}, {%0,%1,%2,%3};"
        : "+f"(d[0]), "+f"(d[1]), "+f"(d[2]), "+f"(d[3])
        : "r"(a[0]), "r"(a[1]), "r"(a[2]), "r"(a[3]), "r"(b[0]), "r"(b[1]));
}
__device__ __forceinline__ uint32_t ldu32(const __half* p) {
    return *reinterpret_cast<const uint32_t*>(p);
}
__device__ __forceinline__ uint32_t h2u(__half2 v) {
    return *reinterpret_cast<uint32_t*>(&v);
}
__device__ __forceinline__ uint32_t smem_u32_of(const void* p) {
    uint32_t a;
    asm("{ .reg .u64 t; cvta.to.shared.u64 t, %1; cvt.u32.u64 %0, t; }" : "=r"(a) : "l"(p));
    return a;
}
__device__ __forceinline__ void cpa16(uint32_t dst, const void* src) {
    asm volatile("cp.async.cg.shared.global [%0], [%1], 16;"
                 :: "r"(dst), "l"(src) : "memory");
}
#define CP_COMMIT() asm volatile("cp.async.commit_group;" ::: "memory")
#define CP_WAIT0()  asm volatile("cp.async.wait_group 0;" ::: "memory")
#define CP_WAIT1()  asm volatile("cp.async.wait_group 1;" ::: "memory")

// ---------------- static device scratch ------------------------------------
__device__ float  g_xg[(size_t)Bb * Tt * Gg / 2]; // 512 MiB gate pre-acts (fp16)
__device__ float  g_hseq[(size_t)Bb * Tt * Hh];   // 256 MiB layer-0 hidden (f32)
__device__ __half g_hbuf[2 * (size_t)Bb * Hh];    // double-buffered h (fp16)
__device__ unsigned int g_bar_count;              // grid barrier counter

__global__ void init_kernel() {
    unsigned idx = blockIdx.x * blockDim.x + threadIdx.x;
    reinterpret_cast<unsigned int*>(g_hbuf)[idx] = 0u;
    if (idx == 0) g_bar_count = 0u;
}

// ================= fp16 mma GEMM (validated R10; fp16 output) ===============
// C[M,2048](fp16) = A[M,K] @ W[2048,K]^T + b1 + b2
#define GPH 40
#define SABUF_H (128 * GPH)
#define GEMM_SMEM_BYTES (4 * SABUF_H * 2)

__global__ void __launch_bounds__(256)
mma_gemm(const float* __restrict__ A, const float* __restrict__ W,
         const float* __restrict__ b1, const float* __restrict__ b2,
         __half* __restrict__ C, int K)
{
    extern __shared__ __half smh[];
    __half* sA = smh;
    __half* sB = smh + 2 * SABUF_H;

    const int tid = threadIdx.x;
    const int lane = tid & 31;
    const int wid = tid >> 5;
    const int gid = lane >> 2;
    const int tq = lane & 3;
    const int warpM = wid >> 2;
    const int warpN = wid & 3;
    const size_t n0 = (size_t)blockIdx.x * 128;
    const size_t m0 = (size_t)blockIdx.y * 128;
    const int NC = K >> 5;

    const int lrow = tid >> 3;
    const int lq = tid & 7;

    float acc[4][4][4];
#pragma unroll
    for (int mt = 0; mt < 4; ++mt)
#pragma unroll
        for (int nt = 0; nt < 4; ++nt)
#pragma unroll
            for (int k = 0; k < 4; ++k) acc[mt][nt][k] = 0.f;

    float4 pa[4], pb[4];
#pragma unroll
    for (int i = 0; i < 4; ++i) {
        int row = lrow + i * 32;
        pa[i] = *reinterpret_cast<const float4*>(&A[(m0 + row) * (size_t)K + lq * 4]);
        pb[i] = *reinterpret_cast<const float4*>(&W[(n0 + row) * (size_t)K + lq * 4]);
    }
#pragma unroll
    for (int i = 0; i < 4; ++i) {
        int row = lrow + i * 32;
        uint2 ua, ub;
        ua.x = h2u(__floats2half2_rn(pa[i].x, pa[i].y));
        ua.y = h2u(__floats2half2_rn(pa[i].z, pa[i].w));
        ub.x = h2u(__floats2half2_rn(pb[i].x, pb[i].y));
        ub.y = h2u(__floats2half2_rn(pb[i].z, pb[i].w));
        *reinterpret_cast<uint2*>(&sA[row * GPH + lq * 4]) = ua;
        *reinterpret_cast<uint2*>(&sB[row * GPH + lq * 4]) = ub;
    }
    __syncthreads();

#pragma unroll 1
    for (int c = 0; c < NC; ++c) {
        const int buf = c & 1;
        if (c + 1 < NC) {
            int k0 = (c + 1) * 32;
#pragma unroll
            for (int i = 0; i < 4; ++i) {
                int row = lrow + i * 32;
                pa[i] = *reinterpret_cast<const float4*>(&A[(m0 + row) * (size_t)K + k0 + lq * 4]);
                pb[i] = *reinterpret_cast<const float4*>(&W[(n0 + row) * (size_t)K + k0 + lq * 4]);
            }
        }
        const __half* sAb = sA + buf * SABUF_H;
        const __half* sBb = sB + buf * SABUF_H;
#pragma unroll
        for (int kk = 0; kk < 2; ++kk) {
            const int k0 = kk * 16;
            uint32_t a[4][4];
#pragma unroll
            for (int mt = 0; mt < 4; ++mt) {
                const __half* ap = sAb + (warpM * 64 + mt * 16 + gid) * GPH + k0 + 2 * tq;
                a[mt][0] = ldu32(ap);
                a[mt][1] = ldu32(ap + 8 * GPH);
                a[mt][2] = ldu32(ap + 8);
                a[mt][3] = ldu32(ap + 8 * GPH + 8);
            }
            uint32_t bf[4][2];
#pragma unroll
            for (int nt = 0; nt < 4; ++nt) {
                const __half* bp = sBb + (warpN * 32 + nt * 8 + gid) * GPH + k0 + 2 * tq;
                bf[nt][0] = ldu32(bp);
                bf[nt][1] = ldu32(bp + 8);
            }
#pragma unroll
            for (int mt = 0; mt < 4; ++mt)
#pragma unroll
                for (int nt = 0; nt < 4; ++nt)
                    mma_f16(acc[mt][nt], a[mt], bf[nt]);
        }
        __syncthreads();
        if (c + 1 < NC) {
            __half* dA = sA + (buf ^ 1) * SABUF_H;
            __half* dB = sB + (buf ^ 1) * SABUF_H;
#pragma unroll
            for (int i = 0; i < 4; ++i) {
                int row = lrow + i * 32;
                uint2 ua, ub;
                ua.x = h2u(__floats2half2_rn(pa[i].x, pa[i].y));
                ua.y = h2u(__floats2half2_rn(pa[i].z, pa[i].w));
                ub.x = h2u(__floats2half2_rn(pb[i].x, pb[i].y));
                ub.y = h2u(__floats2half2_rn(pb[i].z, pb[i].w));
                *reinterpret_cast<uint2*>(&dA[row * GPH + lq * 4]) = ua;
                *reinterpret_cast<uint2*>(&dB[row * GPH + lq * 4]) = ub;
            }
            __syncthreads();
        }
    }

    float bias[4][2];
#pragma unroll
    for (int nt = 0; nt < 4; ++nt) {
        size_t ncol = n0 + warpN * 32 + nt * 8 + tq * 2;
        bias[nt][0] = b1[ncol] + b2[ncol];
        bias[nt][1] = b1[ncol + 1] + b2[ncol + 1];
    }
#pragma unroll
    for (int mt = 0; mt < 4; ++mt) {
        size_t r0 = m0 + warpM * 64 + mt * 16 + gid;
#pragma unroll
        for (int nt = 0; nt < 4; ++nt) {
            size_t ncol = n0 + warpN * 32 + nt * 8 + tq * 2;
            uint32_t u0 = h2u(__floats2half2_rn(acc[mt][nt][0] + bias[nt][0],
                                                acc[mt][nt][1] + bias[nt][1]));
            uint32_t u1 = h2u(__floats2half2_rn(acc[mt][nt][2] + bias[nt][0],
                                                acc[mt][nt][3] + bias[nt][1]));
            *reinterpret_cast<uint32_t*>(&C[r0 * Gg + ncol]) = u0;
            *reinterpret_cast<uint32_t*>(&C[(r0 + 8) * Gg + ncol]) = u1;
        }
    }
}

// ================= persistent LSTM recurrence ================================
// fp16 mma, split-half staging in 2 pipelined commit groups, fp16 xg,
// coalesced h/hseq writes via smem transpose.
#define NCTA_R 128
#define RWPH 520
#define RHPH 520
#define XGPH 72
#define SM_W_BYTES   (64 * RWPH * 2)     // 66560
#define SM_H_BYTES   (64 * RHPH * 2)     // 66560
#define SM_XG_BYTES  (64 * XGPH * 2)     // 9216
#define SM_RED_BYTES (4096 * 4)          // 16384
#define SM_TRF_BYTES (64 * 16 * 4)       // 4096
#define SM_TRH_BYTES (64 * 16 * 2)       // 2048
#define REC_SMEM_BYTES (SM_W_BYTES + SM_H_BYTES + SM_XG_BYTES + SM_RED_BYTES + \
                        SM_TRF_BYTES + SM_TRH_BYTES)   // 164864

__device__ __forceinline__ float sigmoidf_(float x) {
    return 1.0f / (1.0f + __expf(-x));
}

__global__ void __launch_bounds__(256, 1)
lstm_rec(const float* __restrict__ W_hh, const __half* __restrict__ xgh,
         float* __restrict__ hseq)
{
    extern __shared__ char smc[];
    __half* sWh  = reinterpret_cast<__half*>(smc);
    __half* sHh  = reinterpret_cast<__half*>(smc + SM_W_BYTES);
    __half* sXG  = reinterpret_cast<__half*>(smc + SM_W_BYTES + SM_H_BYTES);
    float*  sRed = reinterpret_cast<float*>(smc + SM_W_BYTES + SM_H_BYTES + SM_XG_BYTES);
    float*  sTrF = reinterpret_cast<float*>(smc + SM_W_BYTES + SM_H_BYTES + SM_XG_BYTES + SM_RED_BYTES);
    __half* sTrH = reinterpret_cast<__half*>(smc + SM_W_BYTES + SM_H_BYTES + SM_XG_BYTES + SM_RED_BYTES + SM_TRF_BYTES);

    const uint32_t sH_u  = smem_u32_of(sHh);
    const uint32_t sXG_u = smem_u32_of(sXG);

    const int tid = threadIdx.x;
    const int lane = tid & 31;
    const int wid = tid >> 5;
    const int wK = wid >> 2;              // == half == (tid>=128)
    const int wM = (wid >> 1) & 1;
    const int wN = wid & 1;
    const int gid = lane >> 2;
    const int tq = lane & 3;
    const int p = lane & 1;

    const int ctaM = blockIdx.x & 3;
    const int ctaC = blockIdx.x >> 2;
    const int m0 = ctaM * 64;
    const int hc0 = ctaC * 16;

    // split-half h staging: each half stages its own k-range in 2 groups
    const int half = tid >> 7;
    const int st = tid & 127;
    const int hcolh = half * 256;         // halves
    const int hcolb = half * 512;         // bytes
    const int barid = 1 + half;

    // W_hh slice -> smem (fp16 rne), row j = cl*4 + g
    for (int idx = tid; idx < 64 * 512; idx += 256) {
        int j = idx >> 9, k = idx & 511;
        sWh[j * RWPH + k] =
            __float2half_rn(W_hh[((size_t)(j & 3) * Hh + hc0 + (j >> 2)) * Hh + k]);
    }
    __syncthreads();

    float cst[8];
#pragma unroll
    for (int s = 0; s < 8; ++s) cst[s] = 0.f;
    unsigned phase = 0;
    const int pair = wM * 2 + wN;

    // ---- xg(0) cp.async (fp16: 64 rows x 64 halves, 512 x 16B segs) ----
#pragma unroll
    for (int it = 0; it < 2; ++it) {
        int seg = tid + it * 256;
        int row = seg >> 3, c8 = seg & 7;
        int gate = c8 >> 1, colpart = (c8 & 1) * 8;
        cpa16(sXG_u + (row * XGPH + c8 * 8) * 2,
              &xgh[((size_t)(m0 + row) * Tt + 0) * Gg + (size_t)gate * Hh + hc0 + colpart]);
    }
    CP_COMMIT();

    for (int t = 0; t < Tt; ++t) {
        const __half* hin = g_hbuf + (size_t)(t & 1) * Bb * Hh;
        __half* hout = g_hbuf + (size_t)((t + 1) & 1) * Bb * Hh;

        // ---- stage this half's 64x256 h region in TWO commit groups ----
#pragma unroll
        for (int it = 0; it < 8; ++it) {       // group A: k-lo of half
            int seg = st + it * 128;
            int row = seg >> 4, c16 = seg & 15;
            cpa16(sH_u + row * (RHPH * 2) + hcolb + c16 * 16,
                  hin + (size_t)(m0 + row) * Hh + hcolh + c16 * 8);
        }
        CP_COMMIT();
#pragma unroll
        for (int it = 0; it < 8; ++it) {       // group B: k-hi of half
            int seg = st + it * 128;
            int row = seg >> 4, c16 = (seg & 15) + 16;
            cpa16(sH_u + row * (RHPH * 2) + hcolb + c16 * 16,
                  hin + (size_t)(m0 + row) * Hh + hcolh + c16 * 8);
        }
        CP_COMMIT();

        float acc[2][4][4];
#pragma unroll
        for (int mt = 0; mt < 2; ++mt)
#pragma unroll
            for (int nt = 0; nt < 4; ++nt)
#pragma unroll
                for (int k = 0; k < 4; ++k) acc[mt][nt][k] = 0.f;

        const int kq0 = wK * 256;

        // group A ready (xg + A complete; B may be pending)
        CP_WAIT1();
        asm volatile("bar.sync %0, 128;" :: "r"(barid) : "memory");
#pragma unroll
        for (int kk = 0; kk < 8; ++kk) {
            const int k0 = kq0 + kk * 16;
            uint32_t a[2][4];
#pragma unroll
            for (int mt = 0; mt < 2; ++mt) {
                const __half* ap = sHh + (wM * 32 + mt * 16 + gid) * RHPH + k0 + 2 * tq;
                a[mt][0] = ldu32(ap);
                a[mt][1] = ldu32(ap + 8 * RHPH);
                a[mt][2] = ldu32(ap + 8);
                a[mt][3] = ldu32(ap + 8 * RHPH + 8);
            }
#pragma unroll
            for (int nt = 0; nt < 4; ++nt) {
                const __half* bp = sWh + (wN * 32 + nt * 8 + gid) * RWPH + k0 + 2 * tq;
                uint32_t bfr[2];
                bfr[0] = ldu32(bp);
                bfr[1] = ldu32(bp + 8);
#pragma unroll
                for (int mt = 0; mt < 2; ++mt)
                    mma_f16(acc[mt][nt], a[mt], bfr);
            }
        }
        // group B ready
        CP_WAIT0();
        asm volatile("bar.sync %0, 128;" :: "r"(barid) : "memory");
#pragma unroll
        for (int kk = 8; kk < 16; ++kk) {
            const int k0 = kq0 + kk * 16;
            uint32_t a[2][4];
#pragma unroll
            for (int mt = 0; mt < 2; ++mt) {
                const __half* ap = sHh + (wM * 32 + mt * 16 + gid) * RHPH + k0 + 2 * tq;
                a[mt][0] = ldu32(ap);
                a[mt][1] = ldu32(ap + 8 * RHPH);
                a[mt][2] = ldu32(ap + 8);
                a[mt][3] = ldu32(ap + 8 * RHPH + 8);
            }
#pragma unroll
            for (int nt = 0; nt < 4; ++nt) {
                const __half* bp = sWh + (wN * 32 + nt * 8 + gid) * RWPH + k0 + 2 * tq;
                uint32_t bfr[2];
                bfr[0] = ldu32(bp);
                bfr[1] = ldu32(bp + 8);
#pragma unroll
                for (int mt = 0; mt < 2; ++mt)
                    mma_f16(acc[mt][nt], a[mt], bfr);
            }
        }

        // ---- K-split partials ----
        if (wK == 1) {
#pragma unroll
            for (int mt = 0; mt < 2; ++mt)
#pragma unroll
                for (int nt = 0; nt < 4; ++nt) {
                    float4 v;
                    v.x = acc[mt][nt][0]; v.y = acc[mt][nt][1];
                    v.z = acc[mt][nt][2]; v.w = acc[mt][nt][3];
                    *reinterpret_cast<float4*>(
                        &sRed[(pair * 8 + mt * 4 + nt) * 128 + lane * 4]) = v;
                }
        }
        __syncthreads();                   // (2)

        if (wK == 0) {
#pragma unroll
            for (int mt = 0; mt < 2; ++mt)
#pragma unroll
                for (int nt = 0; nt < 4; ++nt) {
                    float4 v = *reinterpret_cast<const float4*>(
                        &sRed[(pair * 8 + mt * 4 + nt) * 128 + lane * 4]);
                    acc[mt][nt][0] += v.x; acc[mt][nt][1] += v.y;
                    acc[mt][nt][2] += v.z; acc[mt][nt][3] += v.w;
                }

            // ---- epilogue: gates -> cell update -> transpose tile ----
#pragma unroll
            for (int mt = 0; mt < 2; ++mt) {
                int rl = wM * 32 + mt * 16 + gid + p * 8;
#pragma unroll
                for (int nt = 0; nt < 4; ++nt) {
                    float s0 = p ? acc[mt][nt][0] : acc[mt][nt][2];
                    float s1 = p ? acc[mt][nt][1] : acc[mt][nt][3];
                    float r0 = __shfl_xor_sync(0xffffffffu, s0, 1);
                    float r1 = __shfl_xor_sync(0xffffffffu, s1, 1);
                    float gi = p ? r0 : acc[mt][nt][0];
                    float gf = p ? r1 : acc[mt][nt][1];
                    float gg = p ? acc[mt][nt][2] : r0;
                    float go = p ? acc[mt][nt][3] : r1;
                    int cl = wN * 8 + nt * 2 + (tq >> 1);
                    const __half* xp = &sXG[rl * XGPH + cl];
                    float iv = sigmoidf_(gi + __half2float(xp[0]));
                    float fv = sigmoidf_(gf + __half2float(xp[16]));
                    float gv = tanhf(gg + __half2float(xp[32]));
                    float ov = sigmoidf_(go + __half2float(xp[48]));
                    int slot = mt * 4 + nt;
                    cst[slot] = fv * cst[slot] + iv * gv;
                    float hv = ov * tanhf(cst[slot]);
                    sTrH[rl * 16 + cl] = __float2half_rn(hv);
                    sTrF[rl * 16 + cl] = hv;
                }
            }
        }
        __syncthreads();                   // (2b) transpose tile ready

        // ---- coalesced copy-out: hout (fp16, 32B/row), hseq (f32, 64B/row)
        {
            int row = tid >> 2, part = tid & 3;
            *reinterpret_cast<uint2*>(&hout[(size_t)(m0 + row) * Hh + hc0 + part * 4]) =
                *reinterpret_cast<const uint2*>(&sTrH[row * 16 + part * 4]);
            if (hseq) {
                *reinterpret_cast<uint4*>(
                    &hseq[((size_t)(m0 + row) * Tt + t) * Hh + hc0 + part * 4]) =
                    *reinterpret_cast<const uint4*>(&sTrF[row * 16 + part * 4]);
            }
        }

        // ---- xg(t+1) cp.async (sXG free: consumed before (2b)) ----
        if (t + 1 < Tt) {
#pragma unroll
            for (int it = 0; it < 2; ++it) {
                int seg = tid + it * 256;
                int row = seg >> 3, c8 = seg & 7;
                int gate = c8 >> 1, colpart = (c8 & 1) * 8;
                cpa16(sXG_u + (row * XGPH + c8 * 8) * 2,
                      &xgh[((size_t)(m0 + row) * Tt + (t + 1)) * Gg
                           + (size_t)gate * Hh + hc0 + colpart]);
            }
            CP_COMMIT();
        }

        // ---- grid barrier: release arrive + acquire spin ----
        phase += NCTA_R;
        if (tid == 0) {
            asm volatile("red.release.gpu.add.u32 [%0], %1;"
                         :: "l"(&g_bar_count), "r"(1u) : "memory");
            unsigned v;
            while (true) {
                asm volatile("ld.acquire.gpu.u32 %0, [%1];"
                             : "=r"(v) : "l"(&g_bar_count) : "memory");
                if (v >= phase) break;
                __nanosleep(32);
            }
        }
        __syncthreads();                   // (4)
    }
}

// ---------------- final FC (h is fp16) --------------------------------------
__global__ void fc_kernel(const __half* __restrict__ h, const float* __restrict__ Wfc,
                          const float* __restrict__ bfc, float* __restrict__ out)
{
    int b = blockIdx.x;
    int tid = threadIdx.x;
    float s = 0.f;
    for (int k = tid; k < Hh; k += 128)
        s += __half2float(h[(size_t)b * Hh + k]) * Wfc[k];
#pragma unroll
    for (int o = 16; o > 0; o >>= 1) s += __shfl_xor_sync(0xffffffffu, s, o);
    __shared__ float ws[4];
    if ((tid & 31) == 0) ws[tid >> 5] = s;
    __syncthreads();
    if (tid == 0) out[b] = ws[0] + ws[1] + ws[2] + ws[3] + bfc[0];
}

// ---------------- launch ----------------------------------------------------
extern "C" void kernel_launch(void* const* d_in, const int* in_sizes, int n_in,
                              void* d_out, int out_size)
{
    (void)in_sizes; (void)n_in; (void)out_size;
    const float* x     = (const float*)d_in[0];
    const float* W_ih0 = (const float*)d_in[1];
    const float* W_hh0 = (const float*)d_in[2];
    const float* b_ih0 = (const float*)d_in[3];
    const float* b_hh0 = (const float*)d_in[4];
    const float* W_ih1 = (const float*)d_in[5];
    const float* W_hh1 = (const float*)d_in[6];
    const float* b_ih1 = (const float*)d_in[7];
    const float* b_hh1 = (const float*)d_in[8];
    const float* W_fc  = (const float*)d_in[9];
    const float* b_fc  = (const float*)d_in[10];
    float* out = (float*)d_out;

    void *p_xg = nullptr, *p_hseq = nullptr, *p_hbuf = nullptr;
    cudaGetSymbolAddress(&p_xg, g_xg);
    cudaGetSymbolAddress(&p_hseq, g_hseq);
    cudaGetSymbolAddress(&p_hbuf, g_hbuf);

    cudaFuncSetAttribute(mma_gemm, cudaFuncAttributeMaxDynamicSharedMemorySize,
                         GEMM_SMEM_BYTES);
    cudaFuncSetAttribute(lstm_rec, cudaFuncAttributeMaxDynamicSharedMemorySize,
                         REC_SMEM_BYTES);

    dim3 ggrid(Gg / 128, (Bb * Tt) / 128);   // (16, 1024)

    // Layer 0
    mma_gemm<<<ggrid, 256, GEMM_SMEM_BYTES>>>(x, W_ih0, b_ih0, b_hh0,
                                              (__half*)p_xg, Ii);
    init_kernel<<<1024, 256>>>();
    lstm_rec<<<NCTA_R, 256, REC_SMEM_BYTES>>>(W_hh0, (const __half*)p_xg,
                                              (float*)p_hseq);

    // Layer 1
    mma_gemm<<<ggrid, 256, GEMM_SMEM_BYTES>>>((const float*)p_hseq, W_ih1, b_ih1, b_hh1,
                                              (__half*)p_xg, Hh);
    init_kernel<<<1024, 256>>>();
    lstm_rec<<<NCTA_R, 256, REC_SMEM_BYTES>>>(W_hh1, (const __half*)p_xg, nullptr);

    // Final FC (h_last ends in buffer 0 since T=512 is even; fp16 layout)
    fc_kernel<<<Bb, 128>>>((const __half*)p_hbuf, W_fc, b_fc, out);
}

// round 13
// speedup vs baseline: 2.5844x; 1.2651x over previous
#include <cuda_runtime.h>
#include <cuda_fp16.h>
#include <cstdint>
#include <cstddef>

#define Bb 256
#define Tt 512
#define Ii 64
#define Hh 512
#define Gg 2048   // 4*H

// ---------------- mma.sync helpers (baseline PTX, sm_80+) ------------------
__device__ __forceinline__ void mma_f16(float* d, const uint32_t* a, const uint32_t* b) {
    asm volatile(
        "mma.sync.aligned.m16n8k16.row.col.f32.f16.f16.f32 "
        "{%0,%1,%2,%3}, {%4,%5,%6,%7}, {%8,%9}, {%0,%1,%2,%3};"
        : "+f"(d[0]), "+f"(d[1]), "+f"(d[2]), "+f"(d[3])
        : "r"(a[0]), "r"(a[1]), "r"(a[2]), "r"(a[3]), "r"(b[0]), "r"(b[1]));
}
__device__ __forceinline__ uint32_t ldu32(const __half* p) {
    return *reinterpret_cast<const uint32_t*>(p);
}
__device__ __forceinline__ uint32_t h2u(__half2 v) {
    return *reinterpret_cast<uint32_t*>(&v);
}
__device__ __forceinline__ uint32_t smem_u32_of(const void* p) {
    uint32_t a;
    asm("{ .reg .u64 t; cvta.to.shared.u64 t, %1; cvt.u32.u64 %0, t; }" : "=r"(a) : "l"(p));
    return a;
}
__device__ __forceinline__ void cpa16(uint32_t dst, const void* src) {
    asm volatile("cp.async.cg.shared.global [%0], [%1], 16;"
                 :: "r"(dst), "l"(src) : "memory");
}
#define CP_COMMIT() asm volatile("cp.async.commit_group;" ::: "memory")
#define CP_WAIT0()  asm volatile("cp.async.wait_group 0;" ::: "memory")
#define CP_WAIT1()  asm volatile("cp.async.wait_group 1;" ::: "memory")

// MUFU activations (tanh.approx, sm_75+ baseline PTX)
__device__ __forceinline__ float tanh_ap(float x) {
    float y; asm("tanh.approx.f32 %0, %1;" : "=f"(y) : "f"(x)); return y;
}
__device__ __forceinline__ float sigmoid_ap(float x) {
    return fmaf(tanh_ap(0.5f * x), 0.5f, 0.5f);
}

// ---------------- static device scratch ------------------------------------
__device__ float  g_xg[(size_t)Bb * Tt * Gg / 2]; // 512 MiB gate pre-acts (fp16)
__device__ __half g_hseq[(size_t)Bb * Tt * Hh];   // 128 MiB layer-0 hidden (fp16)
__device__ __half g_hbuf[2 * (size_t)Bb * Hh];    // double-buffered h (fp16)
__device__ unsigned int g_bar_count;              // grid barrier counter

__global__ void init_kernel() {
    unsigned idx = blockIdx.x * blockDim.x + threadIdx.x;
    reinterpret_cast<unsigned int*>(g_hbuf)[idx] = 0u;
    if (idx == 0) g_bar_count = 0u;
}

// ================= fp16 mma GEMM (f32 inputs; validated) ====================
#define GPH 40
#define SABUF_H (128 * GPH)
#define GEMM_SMEM_BYTES (4 * SABUF_H * 2)

__global__ void __launch_bounds__(256)
mma_gemm(const float* __restrict__ A, const float* __restrict__ W,
         const float* __restrict__ b1, const float* __restrict__ b2,
         __half* __restrict__ C, int K)
{
    extern __shared__ __half smh[];
    __half* sA = smh;
    __half* sB = smh + 2 * SABUF_H;

    const int tid = threadIdx.x;
    const int lane = tid & 31;
    const int wid = tid >> 5;
    const int gid = lane >> 2;
    const int tq = lane & 3;
    const int warpM = wid >> 2;
    const int warpN = wid & 3;
    const size_t n0 = (size_t)blockIdx.x * 128;
    const size_t m0 = (size_t)blockIdx.y * 128;
    const int NC = K >> 5;

    const int lrow = tid >> 3;
    const int lq = tid & 7;

    float acc[4][4][4];
#pragma unroll
    for (int mt = 0; mt < 4; ++mt)
#pragma unroll
        for (int nt = 0; nt < 4; ++nt)
#pragma unroll
            for (int k = 0; k < 4; ++k) acc[mt][nt][k] = 0.f;

    float4 pa[4], pb[4];
#pragma unroll
    for (int i = 0; i < 4; ++i) {
        int row = lrow + i * 32;
        pa[i] = *reinterpret_cast<const float4*>(&A[(m0 + row) * (size_t)K + lq * 4]);
        pb[i] = *reinterpret_cast<const float4*>(&W[(n0 + row) * (size_t)K + lq * 4]);
    }
#pragma unroll
    for (int i = 0; i < 4; ++i) {
        int row = lrow + i * 32;
        uint2 ua, ub;
        ua.x = h2u(__floats2half2_rn(pa[i].x, pa[i].y));
        ua.y = h2u(__floats2half2_rn(pa[i].z, pa[i].w));
        ub.x = h2u(__floats2half2_rn(pb[i].x, pb[i].y));
        ub.y = h2u(__floats2half2_rn(pb[i].z, pb[i].w));
        *reinterpret_cast<uint2*>(&sA[row * GPH + lq * 4]) = ua;
        *reinterpret_cast<uint2*>(&sB[row * GPH + lq * 4]) = ub;
    }
    __syncthreads();

#pragma unroll 1
    for (int c = 0; c < NC; ++c) {
        const int buf = c & 1;
        if (c + 1 < NC) {
            int k0 = (c + 1) * 32;
#pragma unroll
            for (int i = 0; i < 4; ++i) {
                int row = lrow + i * 32;
                pa[i] = *reinterpret_cast<const float4*>(&A[(m0 + row) * (size_t)K + k0 + lq * 4]);
                pb[i] = *reinterpret_cast<const float4*>(&W[(n0 + row) * (size_t)K + k0 + lq * 4]);
            }
        }
        const __half* sAb = sA + buf * SABUF_H;
        const __half* sBb = sB + buf * SABUF_H;
#pragma unroll
        for (int kk = 0; kk < 2; ++kk) {
            const int k0 = kk * 16;
            uint32_t a[4][4];
#pragma unroll
            for (int mt = 0; mt < 4; ++mt) {
                const __half* ap = sAb + (warpM * 64 + mt * 16 + gid) * GPH + k0 + 2 * tq;
                a[mt][0] = ldu32(ap);
                a[mt][1] = ldu32(ap + 8 * GPH);
                a[mt][2] = ldu32(ap + 8);
                a[mt][3] = ldu32(ap + 8 * GPH + 8);
            }
            uint32_t bf[4][2];
#pragma unroll
            for (int nt = 0; nt < 4; ++nt) {
                const __half* bp = sBb + (warpN * 32 + nt * 8 + gid) * GPH + k0 + 2 * tq;
                bf[nt][0] = ldu32(bp);
                bf[nt][1] = ldu32(bp + 8);
            }
#pragma unroll
            for (int mt = 0; mt < 4; ++mt)
#pragma unroll
                for (int nt = 0; nt < 4; ++nt)
                    mma_f16(acc[mt][nt], a[mt], bf[nt]);
        }
        __syncthreads();
        if (c + 1 < NC) {
            __half* dA = sA + (buf ^ 1) * SABUF_H;
            __half* dB = sB + (buf ^ 1) * SABUF_H;
#pragma unroll
            for (int i = 0; i < 4; ++i) {
                int row = lrow + i * 32;
                uint2 ua, ub;
                ua.x = h2u(__floats2half2_rn(pa[i].x, pa[i].y));
                ua.y = h2u(__floats2half2_rn(pa[i].z, pa[i].w));
                ub.x = h2u(__floats2half2_rn(pb[i].x, pb[i].y));
                ub.y = h2u(__floats2half2_rn(pb[i].z, pb[i].w));
                *reinterpret_cast<uint2*>(&dA[row * GPH + lq * 4]) = ua;
                *reinterpret_cast<uint2*>(&dB[row * GPH + lq * 4]) = ub;
            }
            __syncthreads();
        }
    }

    float bias[4][2];
#pragma unroll
    for (int nt = 0; nt < 4; ++nt) {
        size_t ncol = n0 + warpN * 32 + nt * 8 + tq * 2;
        bias[nt][0] = b1[ncol] + b2[ncol];
        bias[nt][1] = b1[ncol + 1] + b2[ncol + 1];
    }
#pragma unroll
    for (int mt = 0; mt < 4; ++mt) {
        size_t r0 = m0 + warpM * 64 + mt * 16 + gid;
#pragma unroll
        for (int nt = 0; nt < 4; ++nt) {
            size_t ncol = n0 + warpN * 32 + nt * 8 + tq * 2;
            uint32_t u0 = h2u(__floats2half2_rn(acc[mt][nt][0] + bias[nt][0],
                                                acc[mt][nt][1] + bias[nt][1]));
            uint32_t u1 = h2u(__floats2half2_rn(acc[mt][nt][2] + bias[nt][0],
                                                acc[mt][nt][3] + bias[nt][1]));
            *reinterpret_cast<uint32_t*>(&C[r0 * Gg + ncol]) = u0;
            *reinterpret_cast<uint32_t*>(&C[(r0 + 8) * Gg + ncol]) = u1;
        }
    }
}

// ================= fp16 mma GEMM, A already fp16 (layer 1) ==================
__global__ void __launch_bounds__(256)
mma_gemm_h(const __half* __restrict__ A, const float* __restrict__ W,
           const float* __restrict__ b1, const float* __restrict__ b2,
           __half* __restrict__ C, int K)
{
    extern __shared__ __half smh[];
    __half* sA = smh;
    __half* sB = smh + 2 * SABUF_H;

    const int tid = threadIdx.x;
    const int lane = tid & 31;
    const int wid = tid >> 5;
    const int gid = lane >> 2;
    const int tq = lane & 3;
    const int warpM = wid >> 2;
    const int warpN = wid & 3;
    const size_t n0 = (size_t)blockIdx.x * 128;
    const size_t m0 = (size_t)blockIdx.y * 128;
    const int NC = K >> 5;

    const int lrow = tid >> 3;
    const int lq = tid & 7;

    float acc[4][4][4];
#pragma unroll
    for (int mt = 0; mt < 4; ++mt)
#pragma unroll
        for (int nt = 0; nt < 4; ++nt)
#pragma unroll
            for (int k = 0; k < 4; ++k) acc[mt][nt][k] = 0.f;

    uint2 pa[4];
    float4 pb[4];
#pragma unroll
    for (int i = 0; i < 4; ++i) {
        int row = lrow + i * 32;
        pa[i] = *reinterpret_cast<const uint2*>(&A[(m0 + row) * (size_t)K + lq * 4]);
        pb[i] = *reinterpret_cast<const float4*>(&W[(n0 + row) * (size_t)K + lq * 4]);
    }
#pragma unroll
    for (int i = 0; i < 4; ++i) {
        int row = lrow + i * 32;
        uint2 ub;
        ub.x = h2u(__floats2half2_rn(pb[i].x, pb[i].y));
        ub.y = h2u(__floats2half2_rn(pb[i].z, pb[i].w));
        *reinterpret_cast<uint2*>(&sA[row * GPH + lq * 4]) = pa[i];
        *reinterpret_cast<uint2*>(&sB[row * GPH + lq * 4]) = ub;
    }
    __syncthreads();

#pragma unroll 1
    for (int c = 0; c < NC; ++c) {
        const int buf = c & 1;
        if (c + 1 < NC) {
            int k0 = (c + 1) * 32;
#pragma unroll
            for (int i = 0; i < 4; ++i) {
                int row = lrow + i * 32;
                pa[i] = *reinterpret_cast<const uint2*>(&A[(m0 + row) * (size_t)K + k0 + lq * 4]);
                pb[i] = *reinterpret_cast<const float4*>(&W[(n0 + row) * (size_t)K + k0 + lq * 4]);
            }
        }
        const __half* sAb = sA + buf * SABUF_H;
        const __half* sBb = sB + buf * SABUF_H;
#pragma unroll
        for (int kk = 0; kk < 2; ++kk) {
            const int k0 = kk * 16;
            uint32_t a[4][4];
#pragma unroll
            for (int mt = 0; mt < 4; ++mt) {
                const __half* ap = sAb + (warpM * 64 + mt * 16 + gid) * GPH + k0 + 2 * tq;
                a[mt][0] = ldu32(ap);
                a[mt][1] = ldu32(ap + 8 * GPH);
                a[mt][2] = ldu32(ap + 8);
                a[mt][3] = ldu32(ap + 8 * GPH + 8);
            }
            uint32_t bf[4][2];
#pragma unroll
            for (int nt = 0; nt < 4; ++nt) {
                const __half* bp = sBb + (warpN * 32 + nt * 8 + gid) * GPH + k0 + 2 * tq;
                bf[nt][0] = ldu32(bp);
                bf[nt][1] = ldu32(bp + 8);
            }
#pragma unroll
            for (int mt = 0; mt < 4; ++mt)
#pragma unroll
                for (int nt = 0; nt < 4; ++nt)
                    mma_f16(acc[mt][nt], a[mt], bf[nt]);
        }
        __syncthreads();
        if (c + 1 < NC) {
            __half* dA = sA + (buf ^ 1) * SABUF_H;
            __half* dB = sB + (buf ^ 1) * SABUF_H;
#pragma unroll
            for (int i = 0; i < 4; ++i) {
                int row = lrow + i * 32;
                uint2 ub;
                ub.x = h2u(__floats2half2_rn(pb[i].x, pb[i].y));
                ub.y = h2u(__floats2half2_rn(pb[i].z, pb[i].w));
                *reinterpret_cast<uint2*>(&dA[row * GPH + lq * 4]) = pa[i];
                *reinterpret_cast<uint2*>(&dB[row * GPH + lq * 4]) = ub;
            }
            __syncthreads();
        }
    }

    float bias[4][2];
#pragma unroll
    for (int nt = 0; nt < 4; ++nt) {
        size_t ncol = n0 + warpN * 32 + nt * 8 + tq * 2;
        bias[nt][0] = b1[ncol] + b2[ncol];
        bias[nt][1] = b1[ncol + 1] + b2[ncol + 1];
    }
#pragma unroll
    for (int mt = 0; mt < 4; ++mt) {
        size_t r0 = m0 + warpM * 64 + mt * 16 + gid;
#pragma unroll
        for (int nt = 0; nt < 4; ++nt) {
            size_t ncol = n0 + warpN * 32 + nt * 8 + tq * 2;
            uint32_t u0 = h2u(__floats2half2_rn(acc[mt][nt][0] + bias[nt][0],
                                                acc[mt][nt][1] + bias[nt][1]));
            uint32_t u1 = h2u(__floats2half2_rn(acc[mt][nt][2] + bias[nt][0],
                                                acc[mt][nt][3] + bias[nt][1]));
            *reinterpret_cast<uint32_t*>(&C[r0 * Gg + ncol]) = u0;
            *reinterpret_cast<uint32_t*>(&C[(r0 + 8) * Gg + ncol]) = u1;
        }
    }
}

// ================= persistent LSTM recurrence ================================
// fp16 mma; split-half pipelined staging; symmetric K-split epilogue
// (wK0 owns mt=0, wK1 owns mt=1); MUFU activations; fp16 hseq.
#define NCTA_R 128
#define RWPH 520
#define RHPH 520
#define XGPH 72
#define SM_W_BYTES   (64 * RWPH * 2)     // 66560
#define SM_H_BYTES   (64 * RHPH * 2)     // 66560
#define SM_XG_BYTES  (64 * XGPH * 2)     // 9216
#define SM_RED_BYTES (4096 * 4)          // 16384  (2 src x 4 pair x 4 nt x 128)
#define SM_TRH_BYTES (64 * 16 * 2)       // 2048
#define REC_SMEM_BYTES (SM_W_BYTES + SM_H_BYTES + SM_XG_BYTES + SM_RED_BYTES + \
                        SM_TRH_BYTES)    // 160768

__global__ void __launch_bounds__(256, 1)
lstm_rec(const float* __restrict__ W_hh, const __half* __restrict__ xgh,
         __half* __restrict__ hseq)
{
    extern __shared__ char smc[];
    __half* sWh  = reinterpret_cast<__half*>(smc);
    __half* sHh  = reinterpret_cast<__half*>(smc + SM_W_BYTES);
    __half* sXG  = reinterpret_cast<__half*>(smc + SM_W_BYTES + SM_H_BYTES);
    float*  sRed = reinterpret_cast<float*>(smc + SM_W_BYTES + SM_H_BYTES + SM_XG_BYTES);
    __half* sTrH = reinterpret_cast<__half*>(smc + SM_W_BYTES + SM_H_BYTES + SM_XG_BYTES + SM_RED_BYTES);

    const uint32_t sH_u  = smem_u32_of(sHh);
    const uint32_t sXG_u = smem_u32_of(sXG);

    const int tid = threadIdx.x;
    const int lane = tid & 31;
    const int wid = tid >> 5;
    const int wK = wid >> 2;              // == half == (tid>=128); owns mt=wK
    const int wM = (wid >> 1) & 1;
    const int wN = wid & 1;
    const int gid = lane >> 2;
    const int tq = lane & 3;
    const int p = lane & 1;

    const int ctaM = blockIdx.x & 3;
    const int ctaC = blockIdx.x >> 2;
    const int m0 = ctaM * 64;
    const int hc0 = ctaC * 16;

    const int half = tid >> 7;
    const int st = tid & 127;
    const int hcolh = half * 256;
    const int hcolb = half * 512;
    const int barid = 1 + half;

    // W_hh slice -> smem (fp16 rne), row j = cl*4 + g
    for (int idx = tid; idx < 64 * 512; idx += 256) {
        int j = idx >> 9, k = idx & 511;
        sWh[j * RWPH + k] =
            __float2half_rn(W_hh[((size_t)(j & 3) * Hh + hc0 + (j >> 2)) * Hh + k]);
    }
    __syncthreads();

    float cst[4];                          // this thread's owned slots (mt=wK)
#pragma unroll
    for (int s = 0; s < 4; ++s) cst[s] = 0.f;
    unsigned phase = 0;
    const int pair = wM * 2 + wN;

    // ---- xg(0) cp.async ----
#pragma unroll
    for (int it = 0; it < 2; ++it) {
        int seg = tid + it * 256;
        int row = seg >> 3, c8 = seg & 7;
        int gate = c8 >> 1, colpart = (c8 & 1) * 8;
        cpa16(sXG_u + (row * XGPH + c8 * 8) * 2,
              &xgh[((size_t)(m0 + row) * Tt + 0) * Gg + (size_t)gate * Hh + hc0 + colpart]);
    }
    CP_COMMIT();

    for (int t = 0; t < Tt; ++t) {
        const __half* hin = g_hbuf + (size_t)(t & 1) * Bb * Hh;
        __half* hout = g_hbuf + (size_t)((t + 1) & 1) * Bb * Hh;

        // ---- stage this half's 64x256 h region in TWO commit groups ----
#pragma unroll
        for (int it = 0; it < 8; ++it) {
            int seg = st + it * 128;
            int row = seg >> 4, c16 = seg & 15;
            cpa16(sH_u + row * (RHPH * 2) + hcolb + c16 * 16,
                  hin + (size_t)(m0 + row) * Hh + hcolh + c16 * 8);
        }
        CP_COMMIT();
#pragma unroll
        for (int it = 0; it < 8; ++it) {
            int seg = st + it * 128;
            int row = seg >> 4, c16 = (seg & 15) + 16;
            cpa16(sH_u + row * (RHPH * 2) + hcolb + c16 * 16,
                  hin + (size_t)(m0 + row) * Hh + hcolh + c16 * 8);
        }
        CP_COMMIT();

        float acc[2][4][4];
#pragma unroll
        for (int mt = 0; mt < 2; ++mt)
#pragma unroll
            for (int nt = 0; nt < 4; ++nt)
#pragma unroll
                for (int k = 0; k < 4; ++k) acc[mt][nt][k] = 0.f;

        const int kq0 = wK * 256;

        CP_WAIT1();
        asm volatile("bar.sync %0, 128;" :: "r"(barid) : "memory");
#pragma unroll
        for (int kk = 0; kk < 8; ++kk) {
            const int k0 = kq0 + kk * 16;
            uint32_t a[2][4];
#pragma unroll
            for (int mt = 0; mt < 2; ++mt) {
                const __half* ap = sHh + (wM * 32 + mt * 16 + gid) * RHPH + k0 + 2 * tq;
                a[mt][0] = ldu32(ap);
                a[mt][1] = ldu32(ap + 8 * RHPH);
                a[mt][2] = ldu32(ap + 8);
                a[mt][3] = ldu32(ap + 8 * RHPH + 8);
            }
#pragma unroll
            for (int nt = 0; nt < 4; ++nt) {
                const __half* bp = sWh + (wN * 32 + nt * 8 + gid) * RWPH + k0 + 2 * tq;
                uint32_t bfr[2];
                bfr[0] = ldu32(bp);
                bfr[1] = ldu32(bp + 8);
#pragma unroll
                for (int mt = 0; mt < 2; ++mt)
                    mma_f16(acc[mt][nt], a[mt], bfr);
            }
        }
        CP_WAIT0();
        asm volatile("bar.sync %0, 128;" :: "r"(barid) : "memory");
#pragma unroll
        for (int kk = 8; kk < 16; ++kk) {
            const int k0 = kq0 + kk * 16;
            uint32_t a[2][4];
#pragma unroll
            for (int mt = 0; mt < 2; ++mt) {
                const __half* ap = sHh + (wM * 32 + mt * 16 + gid) * RHPH + k0 + 2 * tq;
                a[mt][0] = ldu32(ap);
                a[mt][1] = ldu32(ap + 8 * RHPH);
                a[mt][2] = ldu32(ap + 8);
                a[mt][3] = ldu32(ap + 8 * RHPH + 8);
            }
#pragma unroll
            for (int nt = 0; nt < 4; ++nt) {
                const __half* bp = sWh + (wN * 32 + nt * 8 + gid) * RWPH + k0 + 2 * tq;
                uint32_t bfr[2];
                bfr[0] = ldu32(bp);
                bfr[1] = ldu32(bp + 8);
#pragma unroll
                for (int mt = 0; mt < 2; ++mt)
                    mma_f16(acc[mt][nt], a[mt], bfr);
            }
        }

        // ---- symmetric K-split exchange: write NON-owned mt to sRed ----
        {
            int mtx = wK ^ 1;              // the mt this half does NOT own
#pragma unroll
            for (int nt = 0; nt < 4; ++nt) {
                float4 v;
                v.x = acc[mtx][nt][0]; v.y = acc[mtx][nt][1];
                v.z = acc[mtx][nt][2]; v.w = acc[mtx][nt][3];
                *reinterpret_cast<float4*>(
                    &sRed[((wK * 4 + pair) * 4 + nt) * 128 + lane * 4]) = v;
            }
        }
        __syncthreads();                   // (2)

        // ---- finalize owned mt: add peer partials, activations, write tile
        {
            int mto = wK;                  // owned mt
            int src = wK ^ 1;              // peer half wrote into its region
            int rl = wM * 32 + mto * 16 + gid + p * 8;
#pragma unroll
            for (int nt = 0; nt < 4; ++nt) {
                float4 v = *reinterpret_cast<const float4*>(
                    &sRed[((src * 4 + pair) * 4 + nt) * 128 + lane * 4]);
                float q0 = acc[mto][nt][0] + v.x;
                float q1 = acc[mto][nt][1] + v.y;
                float q2 = acc[mto][nt][2] + v.z;
                float q3 = acc[mto][nt][3] + v.w;
                float s0 = p ? q0 : q2;
                float s1 = p ? q1 : q3;
                float r0 = __shfl_xor_sync(0xffffffffu, s0, 1);
                float r1 = __shfl_xor_sync(0xffffffffu, s1, 1);
                float gi = p ? r0 : q0;
                float gf = p ? r1 : q1;
                float gg = p ? q2 : r0;
                float go = p ? q3 : r1;
                int cl = wN * 8 + nt * 2 + (tq >> 1);
                const __half* xp = &sXG[rl * XGPH + cl];
                float iv = sigmoid_ap(gi + __half2float(xp[0]));
                float fv = sigmoid_ap(gf + __half2float(xp[16]));
                float gv = tanh_ap(gg + __half2float(xp[32]));
                float ov = sigmoid_ap(go + __half2float(xp[48]));
                cst[nt] = fv * cst[nt] + iv * gv;
                float hv = ov * tanh_ap(cst[nt]);
                sTrH[rl * 16 + cl] = __float2half_rn(hv);
            }
        }
        __syncthreads();                   // (2b)

        // ---- coalesced copy-out: hout + hseq (both fp16, 8B/thread) ----
        {
            int row = tid >> 2, part = tid & 3;
            uint2 v = *reinterpret_cast<const uint2*>(&sTrH[row * 16 + part * 4]);
            *reinterpret_cast<uint2*>(&hout[(size_t)(m0 + row) * Hh + hc0 + part * 4]) = v;
            if (hseq) {
                *reinterpret_cast<uint2*>(
                    &hseq[((size_t)(m0 + row) * Tt + t) * Hh + hc0 + part * 4]) = v;
            }
        }

        // ---- xg(t+1) cp.async ----
        if (t + 1 < Tt) {
#pragma unroll
            for (int it = 0; it < 2; ++it) {
                int seg = tid + it * 256;
                int row = seg >> 3, c8 = seg & 7;
                int gate = c8 >> 1, colpart = (c8 & 1) * 8;
                cpa16(sXG_u + (row * XGPH + c8 * 8) * 2,
                      &xgh[((size_t)(m0 + row) * Tt + (t + 1)) * Gg
                           + (size_t)gate * Hh + hc0 + colpart]);
            }
            CP_COMMIT();
        }

        // ---- grid barrier: release arrive + acquire spin ----
        phase += NCTA_R;
        if (tid == 0) {
            asm volatile("red.release.gpu.add.u32 [%0], %1;"
                         :: "l"(&g_bar_count), "r"(1u) : "memory");
            unsigned v;
            while (true) {
                asm volatile("ld.acquire.gpu.u32 %0, [%1];"
                             : "=r"(v) : "l"(&g_bar_count) : "memory");
                if (v >= phase) break;
                __nanosleep(32);
            }
        }
        __syncthreads();                   // (4)
    }
}

// ---------------- final FC (h is fp16) --------------------------------------
__global__ void fc_kernel(const __half* __restrict__ h, const float* __restrict__ Wfc,
                          const float* __restrict__ bfc, float* __restrict__ out)
{
    int b = blockIdx.x;
    int tid = threadIdx.x;
    float s = 0.f;
    for (int k = tid; k < Hh; k += 128)
        s += __half2float(h[(size_t)b * Hh + k]) * Wfc[k];
#pragma unroll
    for (int o = 16; o > 0; o >>= 1) s += __shfl_xor_sync(0xffffffffu, s, o);
    __shared__ float ws[4];
    if ((tid & 31) == 0) ws[tid >> 5] = s;
    __syncthreads();
    if (tid == 0) out[b] = ws[0] + ws[1] + ws[2] + ws[3] + bfc[0];
}

// ---------------- launch ----------------------------------------------------
extern "C" void kernel_launch(void* const* d_in, const int* in_sizes, int n_in,
                              void* d_out, int out_size)
{
    (void)in_sizes; (void)n_in; (void)out_size;
    const float* x     = (const float*)d_in[0];
    const float* W_ih0 = (const float*)d_in[1];
    const float* W_hh0 = (const float*)d_in[2];
    const float* b_ih0 = (const float*)d_in[3];
    const float* b_hh0 = (const float*)d_in[4];
    const float* W_ih1 = (const float*)d_in[5];
    const float* W_hh1 = (const float*)d_in[6];
    const float* b_ih1 = (const float*)d_in[7];
    const float* b_hh1 = (const float*)d_in[8];
    const float* W_fc  = (const float*)d_in[9];
    const float* b_fc  = (const float*)d_in[10];
    float* out = (float*)d_out;

    void *p_xg = nullptr, *p_hseq = nullptr, *p_hbuf = nullptr;
    cudaGetSymbolAddress(&p_xg, g_xg);
    cudaGetSymbolAddress(&p_hseq, g_hseq);
    cudaGetSymbolAddress(&p_hbuf, g_hbuf);

    cudaFuncSetAttribute(mma_gemm, cudaFuncAttributeMaxDynamicSharedMemorySize,
                         GEMM_SMEM_BYTES);
    cudaFuncSetAttribute(mma_gemm_h, cudaFuncAttributeMaxDynamicSharedMemorySize,
                         GEMM_SMEM_BYTES);
    cudaFuncSetAttribute(lstm_rec, cudaFuncAttributeMaxDynamicSharedMemorySize,
                         REC_SMEM_BYTES);

    dim3 ggrid(Gg / 128, (Bb * Tt) / 128);   // (16, 1024)

    // Layer 0
    mma_gemm<<<ggrid, 256, GEMM_SMEM_BYTES>>>(x, W_ih0, b_ih0, b_hh0,
                                              (__half*)p_xg, Ii);
    init_kernel<<<1024, 256>>>();
    lstm_rec<<<NCTA_R, 256, REC_SMEM_BYTES>>>(W_hh0, (const __half*)p_xg,
                                              (__half*)p_hseq);

    // Layer 1 (A = fp16 hseq)
    mma_gemm_h<<<ggrid, 256, GEMM_SMEM_BYTES>>>((const __half*)p_hseq, W_ih1,
                                                b_ih1, b_hh1, (__half*)p_xg, Hh);
    init_kernel<<<1024, 256>>>();
    lstm_rec<<<NCTA_R, 256, REC_SMEM_BYTES>>>(W_hh1, (const __half*)p_xg, nullptr);

    // Final FC (h_last ends in buffer 0 since T=512 is even; fp16 layout)
    fc_kernel<<<Bb, 128>>>((const __half*)p_hbuf, W_fc, b_fc, out);
}

// round 14
// speedup vs baseline: 2.6787x; 1.0365x over previous
#include <cuda_runtime.h>
#include <cuda_fp16.h>
#include <cstdint>
#include <cstddef>

#define Bb 256
#define Tt 512
#define Ii 64
#define Hh 512
#define Gg 2048   // 4*H

// ---------------- mma.sync helpers (baseline PTX, sm_80+) ------------------
__device__ __forceinline__ void mma_f16(float* d, const uint32_t* a, const uint32_t* b) {
    asm volatile(
        "mma.sync.aligned.m16n8k16.row.col.f32.f16.f16.f32 "
        "{%0,%1,%2,%3}, {%4,%5,%6,%7}, {%8,%9}, {%0,%1,%2,%3};"
        : "+f"(d[0]), "+f"(d[1]), "+f"(d[2]), "+f"(d[3])
        : "r"(a[0]), "r"(a[1]), "r"(a[2]), "r"(a[3]), "r"(b[0]), "r"(b[1]));
}
__device__ __forceinline__ uint32_t ldu32(const __half* p) {
    return *reinterpret_cast<const uint32_t*>(p);
}
__device__ __forceinline__ uint32_t h2u(__half2 v) {
    return *reinterpret_cast<uint32_t*>(&v);
}
__device__ __forceinline__ uint32_t smem_u32_of(const void* p) {
    uint32_t a;
    asm("{ .reg .u64 t; cvta.to.shared.u64 t, %1; cvt.u32.u64 %0, t; }" : "=r"(a) : "l"(p));
    return a;
}
__device__ __forceinline__ void cpa16(uint32_t dst, const void* src) {
    asm volatile("cp.async.cg.shared.global [%0], [%1], 16;"
                 :: "r"(dst), "l"(src) : "memory");
}
#define CP_COMMIT() asm volatile("cp.async.commit_group;" ::: "memory")
#define CP_WAIT0()  asm volatile("cp.async.wait_group 0;" ::: "memory")
#define CP_WAIT1()  asm volatile("cp.async.wait_group 1;" ::: "memory")

// MUFU activations (tanh.approx, sm_75+ baseline PTX)
__device__ __forceinline__ float tanh_ap(float x) {
    float y; asm("tanh.approx.f32 %0, %1;" : "=f"(y) : "f"(x)); return y;
}
__device__ __forceinline__ float sigmoid_ap(float x) {
    return fmaf(tanh_ap(0.5f * x), 0.5f, 0.5f);
}

// ---------------- static device scratch ------------------------------------
__device__ float  g_xg[(size_t)Bb * Tt * Gg / 2]; // 512 MiB gate pre-acts (fp16)
__device__ __half g_hseq[(size_t)Bb * Tt * Hh];   // 128 MiB layer-0 hidden (fp16)
__device__ __half g_hbuf[2 * (size_t)Bb * Hh];    // double-buffered h (fp16)
__device__ unsigned int g_bar[4];                 // per-M-group barrier counters

__global__ void init_kernel() {
    unsigned idx = blockIdx.x * blockDim.x + threadIdx.x;
    reinterpret_cast<unsigned int*>(g_hbuf)[idx] = 0u;
    if (idx < 4) g_bar[idx] = 0u;
}

// ================= fp16 mma GEMM (f32 inputs; validated) ====================
#define GPH 40
#define SABUF_H (128 * GPH)
#define GEMM_SMEM_BYTES (4 * SABUF_H * 2)

__global__ void __launch_bounds__(256)
mma_gemm(const float* __restrict__ A, const float* __restrict__ W,
         const float* __restrict__ b1, const float* __restrict__ b2,
         __half* __restrict__ C, int K)
{
    extern __shared__ __half smh[];
    __half* sA = smh;
    __half* sB = smh + 2 * SABUF_H;

    const int tid = threadIdx.x;
    const int lane = tid & 31;
    const int wid = tid >> 5;
    const int gid = lane >> 2;
    const int tq = lane & 3;
    const int warpM = wid >> 2;
    const int warpN = wid & 3;
    const size_t n0 = (size_t)blockIdx.x * 128;
    const size_t m0 = (size_t)blockIdx.y * 128;
    const int NC = K >> 5;

    const int lrow = tid >> 3;
    const int lq = tid & 7;

    float acc[4][4][4];
#pragma unroll
    for (int mt = 0; mt < 4; ++mt)
#pragma unroll
        for (int nt = 0; nt < 4; ++nt)
#pragma unroll
            for (int k = 0; k < 4; ++k) acc[mt][nt][k] = 0.f;

    float4 pa[4], pb[4];
#pragma unroll
    for (int i = 0; i < 4; ++i) {
        int row = lrow + i * 32;
        pa[i] = *reinterpret_cast<const float4*>(&A[(m0 + row) * (size_t)K + lq * 4]);
        pb[i] = *reinterpret_cast<const float4*>(&W[(n0 + row) * (size_t)K + lq * 4]);
    }
#pragma unroll
    for (int i = 0; i < 4; ++i) {
        int row = lrow + i * 32;
        uint2 ua, ub;
        ua.x = h2u(__floats2half2_rn(pa[i].x, pa[i].y));
        ua.y = h2u(__floats2half2_rn(pa[i].z, pa[i].w));
        ub.x = h2u(__floats2half2_rn(pb[i].x, pb[i].y));
        ub.y = h2u(__floats2half2_rn(pb[i].z, pb[i].w));
        *reinterpret_cast<uint2*>(&sA[row * GPH + lq * 4]) = ua;
        *reinterpret_cast<uint2*>(&sB[row * GPH + lq * 4]) = ub;
    }
    __syncthreads();

#pragma unroll 1
    for (int c = 0; c < NC; ++c) {
        const int buf = c & 1;
        if (c + 1 < NC) {
            int k0 = (c + 1) * 32;
#pragma unroll
            for (int i = 0; i < 4; ++i) {
                int row = lrow + i * 32;
                pa[i] = *reinterpret_cast<const float4*>(&A[(m0 + row) * (size_t)K + k0 + lq * 4]);
                pb[i] = *reinterpret_cast<const float4*>(&W[(n0 + row) * (size_t)K + k0 + lq * 4]);
            }
        }
        const __half* sAb = sA + buf * SABUF_H;
        const __half* sBb = sB + buf * SABUF_H;
#pragma unroll
        for (int kk = 0; kk < 2; ++kk) {
            const int k0 = kk * 16;
            uint32_t a[4][4];
#pragma unroll
            for (int mt = 0; mt < 4; ++mt) {
                const __half* ap = sAb + (warpM * 64 + mt * 16 + gid) * GPH + k0 + 2 * tq;
                a[mt][0] = ldu32(ap);
                a[mt][1] = ldu32(ap + 8 * GPH);
                a[mt][2] = ldu32(ap + 8);
                a[mt][3] = ldu32(ap + 8 * GPH + 8);
            }
            uint32_t bf[4][2];
#pragma unroll
            for (int nt = 0; nt < 4; ++nt) {
                const __half* bp = sBb + (warpN * 32 + nt * 8 + gid) * GPH + k0 + 2 * tq;
                bf[nt][0] = ldu32(bp);
                bf[nt][1] = ldu32(bp + 8);
            }
#pragma unroll
            for (int mt = 0; mt < 4; ++mt)
#pragma unroll
                for (int nt = 0; nt < 4; ++nt)
                    mma_f16(acc[mt][nt], a[mt], bf[nt]);
        }
        __syncthreads();
        if (c + 1 < NC) {
            __half* dA = sA + (buf ^ 1) * SABUF_H;
            __half* dB = sB + (buf ^ 1) * SABUF_H;
#pragma unroll
            for (int i = 0; i < 4; ++i) {
                int row = lrow + i * 32;
                uint2 ua, ub;
                ua.x = h2u(__floats2half2_rn(pa[i].x, pa[i].y));
                ua.y = h2u(__floats2half2_rn(pa[i].z, pa[i].w));
                ub.x = h2u(__floats2half2_rn(pb[i].x, pb[i].y));
                ub.y = h2u(__floats2half2_rn(pb[i].z, pb[i].w));
                *reinterpret_cast<uint2*>(&dA[row * GPH + lq * 4]) = ua;
                *reinterpret_cast<uint2*>(&dB[row * GPH + lq * 4]) = ub;
            }
            __syncthreads();
        }
    }

    float bias[4][2];
#pragma unroll
    for (int nt = 0; nt < 4; ++nt) {
        size_t ncol = n0 + warpN * 32 + nt * 8 + tq * 2;
        bias[nt][0] = b1[ncol] + b2[ncol];
        bias[nt][1] = b1[ncol + 1] + b2[ncol + 1];
    }
#pragma unroll
    for (int mt = 0; mt < 4; ++mt) {
        size_t r0 = m0 + warpM * 64 + mt * 16 + gid;
#pragma unroll
        for (int nt = 0; nt < 4; ++nt) {
            size_t ncol = n0 + warpN * 32 + nt * 8 + tq * 2;
            uint32_t u0 = h2u(__floats2half2_rn(acc[mt][nt][0] + bias[nt][0],
                                                acc[mt][nt][1] + bias[nt][1]));
            uint32_t u1 = h2u(__floats2half2_rn(acc[mt][nt][2] + bias[nt][0],
                                                acc[mt][nt][3] + bias[nt][1]));
            *reinterpret_cast<uint32_t*>(&C[r0 * Gg + ncol]) = u0;
            *reinterpret_cast<uint32_t*>(&C[(r0 + 8) * Gg + ncol]) = u1;
        }
    }
}

// ================= fp16 mma GEMM, A already fp16 (layer 1) ==================
__global__ void __launch_bounds__(256)
mma_gemm_h(const __half* __restrict__ A, const float* __restrict__ W,
           const float* __restrict__ b1, const float* __restrict__ b2,
           __half* __restrict__ C, int K)
{
    extern __shared__ __half smh[];
    __half* sA = smh;
    __half* sB = smh + 2 * SABUF_H;

    const int tid = threadIdx.x;
    const int lane = tid & 31;
    const int wid = tid >> 5;
    const int gid = lane >> 2;
    const int tq = lane & 3;
    const int warpM = wid >> 2;
    const int warpN = wid & 3;
    const size_t n0 = (size_t)blockIdx.x * 128;
    const size_t m0 = (size_t)blockIdx.y * 128;
    const int NC = K >> 5;

    const int lrow = tid >> 3;
    const int lq = tid & 7;

    float acc[4][4][4];
#pragma unroll
    for (int mt = 0; mt < 4; ++mt)
#pragma unroll
        for (int nt = 0; nt < 4; ++nt)
#pragma unroll
            for (int k = 0; k < 4; ++k) acc[mt][nt][k] = 0.f;

    uint2 pa[4];
    float4 pb[4];
#pragma unroll
    for (int i = 0; i < 4; ++i) {
        int row = lrow + i * 32;
        pa[i] = *reinterpret_cast<const uint2*>(&A[(m0 + row) * (size_t)K + lq * 4]);
        pb[i] = *reinterpret_cast<const float4*>(&W[(n0 + row) * (size_t)K + lq * 4]);
    }
#pragma unroll
    for (int i = 0; i < 4; ++i) {
        int row = lrow + i * 32;
        uint2 ub;
        ub.x = h2u(__floats2half2_rn(pb[i].x, pb[i].y));
        ub.y = h2u(__floats2half2_rn(pb[i].z, pb[i].w));
        *reinterpret_cast<uint2*>(&sA[row * GPH + lq * 4]) = pa[i];
        *reinterpret_cast<uint2*>(&sB[row * GPH + lq * 4]) = ub;
    }
    __syncthreads();

#pragma unroll 1
    for (int c = 0; c < NC; ++c) {
        const int buf = c & 1;
        if (c + 1 < NC) {
            int k0 = (c + 1) * 32;
#pragma unroll
            for (int i = 0; i < 4; ++i) {
                int row = lrow + i * 32;
                pa[i] = *reinterpret_cast<const uint2*>(&A[(m0 + row) * (size_t)K + k0 + lq * 4]);
                pb[i] = *reinterpret_cast<const float4*>(&W[(n0 + row) * (size_t)K + k0 + lq * 4]);
            }
        }
        const __half* sAb = sA + buf * SABUF_H;
        const __half* sBb = sB + buf * SABUF_H;
#pragma unroll
        for (int kk = 0; kk < 2; ++kk) {
            const int k0 = kk * 16;
            uint32_t a[4][4];
#pragma unroll
            for (int mt = 0; mt < 4; ++mt) {
                const __half* ap = sAb + (warpM * 64 + mt * 16 + gid) * GPH + k0 + 2 * tq;
                a[mt][0] = ldu32(ap);
                a[mt][1] = ldu32(ap + 8 * GPH);
                a[mt][2] = ldu32(ap + 8);
                a[mt][3] = ldu32(ap + 8 * GPH + 8);
            }
            uint32_t bf[4][2];
#pragma unroll
            for (int nt = 0; nt < 4; ++nt) {
                const __half* bp = sBb + (warpN * 32 + nt * 8 + gid) * GPH + k0 + 2 * tq;
                bf[nt][0] = ldu32(bp);
                bf[nt][1] = ldu32(bp + 8);
            }
#pragma unroll
            for (int mt = 0; mt < 4; ++mt)
#pragma unroll
                for (int nt = 0; nt < 4; ++nt)
                    mma_f16(acc[mt][nt], a[mt], bf[nt]);
        }
        __syncthreads();
        if (c + 1 < NC) {
            __half* dA = sA + (buf ^ 1) * SABUF_H;
            __half* dB = sB + (buf ^ 1) * SABUF_H;
#pragma unroll
            for (int i = 0; i < 4; ++i) {
                int row = lrow + i * 32;
                uint2 ub;
                ub.x = h2u(__floats2half2_rn(pb[i].x, pb[i].y));
                ub.y = h2u(__floats2half2_rn(pb[i].z, pb[i].w));
                *reinterpret_cast<uint2*>(&dA[row * GPH + lq * 4]) = pa[i];
                *reinterpret_cast<uint2*>(&dB[row * GPH + lq * 4]) = ub;
            }
            __syncthreads();
        }
    }

    float bias[4][2];
#pragma unroll
    for (int nt = 0; nt < 4; ++nt) {
        size_t ncol = n0 + warpN * 32 + nt * 8 + tq * 2;
        bias[nt][0] = b1[ncol] + b2[ncol];
        bias[nt][1] = b1[ncol + 1] + b2[ncol + 1];
    }
#pragma unroll
    for (int mt = 0; mt < 4; ++mt) {
        size_t r0 = m0 + warpM * 64 + mt * 16 + gid;
#pragma unroll
        for (int nt = 0; nt < 4; ++nt) {
            size_t ncol = n0 + warpN * 32 + nt * 8 + tq * 2;
            uint32_t u0 = h2u(__floats2half2_rn(acc[mt][nt][0] + bias[nt][0],
                                                acc[mt][nt][1] + bias[nt][1]));
            uint32_t u1 = h2u(__floats2half2_rn(acc[mt][nt][2] + bias[nt][0],
                                                acc[mt][nt][3] + bias[nt][1]));
            *reinterpret_cast<uint32_t*>(&C[r0 * Gg + ncol]) = u0;
            *reinterpret_cast<uint32_t*>(&C[(r0 + 8) * Gg + ncol]) = u1;
        }
    }
}

// ================= persistent LSTM recurrence ================================
// fp16 mma; split-half pipelined staging; symmetric K-split epilogue;
// MUFU activations; fp16 hseq; per-M-group (32-CTA) barrier with race-fixed
// ordering: hout -> sync -> arrive -> (hseq + xg prefetch in barrier shadow).
#define NCTA_R 128
#define GRP_CTAS 32
#define RWPH 520
#define RHPH 520
#define XGPH 72
#define SM_W_BYTES   (64 * RWPH * 2)     // 66560
#define SM_H_BYTES   (64 * RHPH * 2)     // 66560
#define SM_XG_BYTES  (64 * XGPH * 2)     // 9216
#define SM_RED_BYTES (4096 * 4)          // 16384
#define SM_TRH_BYTES (64 * 16 * 2)       // 2048
#define REC_SMEM_BYTES (SM_W_BYTES + SM_H_BYTES + SM_XG_BYTES + SM_RED_BYTES + \
                        SM_TRH_BYTES)    // 160768

__global__ void __launch_bounds__(256, 1)
lstm_rec(const float* __restrict__ W_hh, const __half* __restrict__ xgh,
         __half* __restrict__ hseq)
{
    extern __shared__ char smc[];
    __half* sWh  = reinterpret_cast<__half*>(smc);
    __half* sHh  = reinterpret_cast<__half*>(smc + SM_W_BYTES);
    __half* sXG  = reinterpret_cast<__half*>(smc + SM_W_BYTES + SM_H_BYTES);
    float*  sRed = reinterpret_cast<float*>(smc + SM_W_BYTES + SM_H_BYTES + SM_XG_BYTES);
    __half* sTrH = reinterpret_cast<__half*>(smc + SM_W_BYTES + SM_H_BYTES + SM_XG_BYTES + SM_RED_BYTES);

    const uint32_t sH_u  = smem_u32_of(sHh);
    const uint32_t sXG_u = smem_u32_of(sXG);

    const int tid = threadIdx.x;
    const int lane = tid & 31;
    const int wid = tid >> 5;
    const int wK = wid >> 2;              // == half; owns mt=wK
    const int wM = (wid >> 1) & 1;
    const int wN = wid & 1;
    const int gid = lane >> 2;
    const int tq = lane & 3;
    const int p = lane & 1;

    const int ctaM = blockIdx.x & 3;
    const int ctaC = blockIdx.x >> 2;
    const int m0 = ctaM * 64;
    const int hc0 = ctaC * 16;

    const int half = tid >> 7;
    const int st = tid & 127;
    const int hcolh = half * 256;
    const int hcolb = half * 512;
    const int barid = 1 + half;

    // W_hh slice -> smem (fp16 rne), row j = cl*4 + g
    for (int idx = tid; idx < 64 * 512; idx += 256) {
        int j = idx >> 9, k = idx & 511;
        sWh[j * RWPH + k] =
            __float2half_rn(W_hh[((size_t)(j & 3) * Hh + hc0 + (j >> 2)) * Hh + k]);
    }
    __syncthreads();

    float cst[4];
#pragma unroll
    for (int s = 0; s < 4; ++s) cst[s] = 0.f;
    unsigned phase = 0;
    const int pair = wM * 2 + wN;

    // ---- xg(0) cp.async ----
#pragma unroll
    for (int it = 0; it < 2; ++it) {
        int seg = tid + it * 256;
        int row = seg >> 3, c8 = seg & 7;
        int gate = c8 >> 1, colpart = (c8 & 1) * 8;
        cpa16(sXG_u + (row * XGPH + c8 * 8) * 2,
              &xgh[((size_t)(m0 + row) * Tt + 0) * Gg + (size_t)gate * Hh + hc0 + colpart]);
    }
    CP_COMMIT();

    for (int t = 0; t < Tt; ++t) {
        const __half* hin = g_hbuf + (size_t)(t & 1) * Bb * Hh;
        __half* hout = g_hbuf + (size_t)((t + 1) & 1) * Bb * Hh;

        // ---- stage this half's 64x256 h region in TWO commit groups ----
#pragma unroll
        for (int it = 0; it < 8; ++it) {
            int seg = st + it * 128;
            int row = seg >> 4, c16 = seg & 15;
            cpa16(sH_u + row * (RHPH * 2) + hcolb + c16 * 16,
                  hin + (size_t)(m0 + row) * Hh + hcolh + c16 * 8);
        }
        CP_COMMIT();
#pragma unroll
        for (int it = 0; it < 8; ++it) {
            int seg = st + it * 128;
            int row = seg >> 4, c16 = (seg & 15) + 16;
            cpa16(sH_u + row * (RHPH * 2) + hcolb + c16 * 16,
                  hin + (size_t)(m0 + row) * Hh + hcolh + c16 * 8);
        }
        CP_COMMIT();

        float acc[2][4][4];
#pragma unroll
        for (int mt = 0; mt < 2; ++mt)
#pragma unroll
            for (int nt = 0; nt < 4; ++nt)
#pragma unroll
                for (int k = 0; k < 4; ++k) acc[mt][nt][k] = 0.f;

        const int kq0 = wK * 256;

        CP_WAIT1();
        asm volatile("bar.sync %0, 128;" :: "r"(barid) : "memory");
#pragma unroll
        for (int kk = 0; kk < 8; ++kk) {
            const int k0 = kq0 + kk * 16;
            uint32_t a[2][4];
#pragma unroll
            for (int mt = 0; mt < 2; ++mt) {
                const __half* ap = sHh + (wM * 32 + mt * 16 + gid) * RHPH + k0 + 2 * tq;
                a[mt][0] = ldu32(ap);
                a[mt][1] = ldu32(ap + 8 * RHPH);
                a[mt][2] = ldu32(ap + 8);
                a[mt][3] = ldu32(ap + 8 * RHPH + 8);
            }
#pragma unroll
            for (int nt = 0; nt < 4; ++nt) {
                const __half* bp = sWh + (wN * 32 + nt * 8 + gid) * RWPH + k0 + 2 * tq;
                uint32_t bfr[2];
                bfr[0] = ldu32(bp);
                bfr[1] = ldu32(bp + 8);
#pragma unroll
                for (int mt = 0; mt < 2; ++mt)
                    mma_f16(acc[mt][nt], a[mt], bfr);
            }
        }
        CP_WAIT0();
        asm volatile("bar.sync %0, 128;" :: "r"(barid) : "memory");
#pragma unroll
        for (int kk = 8; kk < 16; ++kk) {
            const int k0 = kq0 + kk * 16;
            uint32_t a[2][4];
#pragma unroll
            for (int mt = 0; mt < 2; ++mt) {
                const __half* ap = sHh + (wM * 32 + mt * 16 + gid) * RHPH + k0 + 2 * tq;
                a[mt][0] = ldu32(ap);
                a[mt][1] = ldu32(ap + 8 * RHPH);
                a[mt][2] = ldu32(ap + 8);
                a[mt][3] = ldu32(ap + 8 * RHPH + 8);
            }
#pragma unroll
            for (int nt = 0; nt < 4; ++nt) {
                const __half* bp = sWh + (wN * 32 + nt * 8 + gid) * RWPH + k0 + 2 * tq;
                uint32_t bfr[2];
                bfr[0] = ldu32(bp);
                bfr[1] = ldu32(bp + 8);
#pragma unroll
                for (int mt = 0; mt < 2; ++mt)
                    mma_f16(acc[mt][nt], a[mt], bfr);
            }
        }

        // ---- symmetric K-split exchange: write NON-owned mt to sRed ----
        {
            int mtx = wK ^ 1;
#pragma unroll
            for (int nt = 0; nt < 4; ++nt) {
                float4 v;
                v.x = acc[mtx][nt][0]; v.y = acc[mtx][nt][1];
                v.z = acc[mtx][nt][2]; v.w = acc[mtx][nt][3];
                *reinterpret_cast<float4*>(
                    &sRed[((wK * 4 + pair) * 4 + nt) * 128 + lane * 4]) = v;
            }
        }
        __syncthreads();                   // (2)

        // ---- finalize owned mt: add peer partials, activations, write tile
        {
            int mto = wK;
            int src = wK ^ 1;
            int rl = wM * 32 + mto * 16 + gid + p * 8;
#pragma unroll
            for (int nt = 0; nt < 4; ++nt) {
                float4 v = *reinterpret_cast<const float4*>(
                    &sRed[((src * 4 + pair) * 4 + nt) * 128 + lane * 4]);
                float q0 = acc[mto][nt][0] + v.x;
                float q1 = acc[mto][nt][1] + v.y;
                float q2 = acc[mto][nt][2] + v.z;
                float q3 = acc[mto][nt][3] + v.w;
                float s0 = p ? q0 : q2;
                float s1 = p ? q1 : q3;
                float r0 = __shfl_xor_sync(0xffffffffu, s0, 1);
                float r1 = __shfl_xor_sync(0xffffffffu, s1, 1);
                float gi = p ? r0 : q0;
                float gf = p ? r1 : q1;
                float gg = p ? q2 : r0;
                float go = p ? q3 : r1;
                int cl = wN * 8 + nt * 2 + (tq >> 1);
                const __half* xp = &sXG[rl * XGPH + cl];
                float iv = sigmoid_ap(gi + __half2float(xp[0]));
                float fv = sigmoid_ap(gf + __half2float(xp[16]));
                float gv = tanh_ap(gg + __half2float(xp[32]));
                float ov = sigmoid_ap(go + __half2float(xp[48]));
                cst[nt] = fv * cst[nt] + iv * gv;
                float hv = ov * tanh_ap(cst[nt]);
                sTrH[rl * 16 + cl] = __float2half_rn(hv);
            }
        }
        __syncthreads();                   // (2b)

        // ---- coalesced hout write (inter-CTA critical data FIRST) ----
        {
            int row = tid >> 2, part = tid & 3;
            uint2 v = *reinterpret_cast<const uint2*>(&sTrH[row * 16 + part * 4]);
            *reinterpret_cast<uint2*>(&hout[(size_t)(m0 + row) * Hh + hc0 + part * 4]) = v;
        }
        __syncthreads();                   // (3) all hout stores issued

        // ---- arrive on the M-group barrier (release covers hout) ----
        phase += GRP_CTAS;
        if (tid == 0) {
            asm volatile("red.release.gpu.add.u32 [%0], %1;"
                         :: "l"(&g_bar[ctaM]), "r"(1u) : "memory");
        }

        // ---- non-critical work in barrier shadow: hseq + xg(t+1) ----
        if (hseq) {
            int row = tid >> 2, part = tid & 3;
            uint2 v = *reinterpret_cast<const uint2*>(&sTrH[row * 16 + part * 4]);
            *reinterpret_cast<uint2*>(
                &hseq[((size_t)(m0 + row) * Tt + t) * Hh + hc0 + part * 4]) = v;
        }
        if (t + 1 < Tt) {
#pragma unroll
            for (int it = 0; it < 2; ++it) {
                int seg = tid + it * 256;
                int row = seg >> 3, c8 = seg & 7;
                int gate = c8 >> 1, colpart = (c8 & 1) * 8;
                cpa16(sXG_u + (row * XGPH + c8 * 8) * 2,
                      &xgh[((size_t)(m0 + row) * Tt + (t + 1)) * Gg
                           + (size_t)gate * Hh + hc0 + colpart]);
            }
            CP_COMMIT();
        }

        // ---- spin for M-group arrival ----
        if (tid == 0) {
            unsigned v;
            while (true) {
                asm volatile("ld.acquire.gpu.u32 %0, [%1];"
                             : "=r"(v) : "l"(&g_bar[ctaM]) : "memory");
                if (v >= phase) break;
                __nanosleep(32);
            }
        }
        __syncthreads();                   // (4)
    }
}

// ---------------- final FC (h is fp16) --------------------------------------
__global__ void fc_kernel(const __half* __restrict__ h, const float* __restrict__ Wfc,
                          const float* __restrict__ bfc, float* __restrict__ out)
{
    int b = blockIdx.x;
    int tid = threadIdx.x;
    float s = 0.f;
    for (int k = tid; k < Hh; k += 128)
        s += __half2float(h[(size_t)b * Hh + k]) * Wfc[k];
#pragma unroll
    for (int o = 16; o > 0; o >>= 1) s += __shfl_xor_sync(0xffffffffu, s, o);
    __shared__ float ws[4];
    if ((tid & 31) == 0) ws[tid >> 5] = s;
    __syncthreads();
    if (tid == 0) out[b] = ws[0] + ws[1] + ws[2] + ws[3] + bfc[0];
}

// ---------------- launch ----------------------------------------------------
extern "C" void kernel_launch(void* const* d_in, const int* in_sizes, int n_in,
                              void* d_out, int out_size)
{
    (void)in_sizes; (void)n_in; (void)out_size;
    const float* x     = (const float*)d_in[0];
    const float* W_ih0 = (const float*)d_in[1];
    const float* W_hh0 = (const float*)d_in[2];
    const float* b_ih0 = (const float*)d_in[3];
    const float* b_hh0 = (const float*)d_in[4];
    const float* W_ih1 = (const float*)d_in[5];
    const float* W_hh1 = (const float*)d_in[6];
    const float* b_ih1 = (const float*)d_in[7];
    const float* b_hh1 = (const float*)d_in[8];
    const float* W_fc  = (const float*)d_in[9];
    const float* b_fc  = (const float*)d_in[10];
    float* out = (float*)d_out;

    void *p_xg = nullptr, *p_hseq = nullptr, *p_hbuf = nullptr;
    cudaGetSymbolAddress(&p_xg, g_xg);
    cudaGetSymbolAddress(&p_hseq, g_hseq);
    cudaGetSymbolAddress(&p_hbuf, g_hbuf);

    cudaFuncSetAttribute(mma_gemm, cudaFuncAttributeMaxDynamicSharedMemorySize,
                         GEMM_SMEM_BYTES);
    cudaFuncSetAttribute(mma_gemm_h, cudaFuncAttributeMaxDynamicSharedMemorySize,
                         GEMM_SMEM_BYTES);
    cudaFuncSetAttribute(lstm_rec, cudaFuncAttributeMaxDynamicSharedMemorySize,
                         REC_SMEM_BYTES);

    dim3 ggrid(Gg / 128, (Bb * Tt) / 128);   // (16, 1024)

    // Layer 0
    mma_gemm<<<ggrid, 256, GEMM_SMEM_BYTES>>>(x, W_ih0, b_ih0, b_hh0,
                                              (__half*)p_xg, Ii);
    init_kernel<<<1024, 256>>>();
    lstm_rec<<<NCTA_R, 256, REC_SMEM_BYTES>>>(W_hh0, (const __half*)p_xg,
                                              (__half*)p_hseq);

    // Layer 1 (A = fp16 hseq)
    mma_gemm_h<<<ggrid, 256, GEMM_SMEM_BYTES>>>((const __half*)p_hseq, W_ih1,
                                                b_ih1, b_hh1, (__half*)p_xg, Hh);
    init_kernel<<<1024, 256>>>();
    lstm_rec<<<NCTA_R, 256, REC_SMEM_BYTES>>>(W_hh1, (const __half*)p_xg, nullptr);

    // Final FC (h_last ends in buffer 0 since T=512 is even; fp16 layout)
    fc_kernel<<<Bb, 128>>>((const __half*)p_hbuf, W_fc, b_fc, out);
}

// round 15
// speedup vs baseline: 2.7516x; 1.0272x over previous
#include <cuda_runtime.h>
#include <cuda_fp16.h>
#include <cstdint>
#include <cstddef>

#define Bb 256
#define Tt 512
#define Ii 64
#define Hh 512
#define Gg 2048   // 4*H

// ---------------- mma.sync helpers (baseline PTX, sm_80+) ------------------
__device__ __forceinline__ void mma_f16(float* d, const uint32_t* a, const uint32_t* b) {
    asm volatile(
        "mma.sync.aligned.m16n8k16.row.col.f32.f16.f16.f32 "
        "{%0,%1,%2,%3}, {%4,%5,%6,%7}, {%8,%9}, {%0,%1,%2,%3};"
        : "+f"(d[0]), "+f"(d[1]), "+f"(d[2]), "+f"(d[3])
        : "r"(a[0]), "r"(a[1]), "r"(a[2]), "r"(a[3]), "r"(b[0]), "r"(b[1]));
}
__device__ __forceinline__ uint32_t ldu32(const __half* p) {
    return *reinterpret_cast<const uint32_t*>(p);
}
__device__ __forceinline__ uint32_t h2u(__half2 v) {
    return *reinterpret_cast<uint32_t*>(&v);
}
__device__ __forceinline__ uint32_t smem_u32_of(const void* p) {
    uint32_t a;
    asm("{ .reg .u64 t; cvta.to.shared.u64 t, %1; cvt.u32.u64 %0, t; }" : "=r"(a) : "l"(p));
    return a;
}
__device__ __forceinline__ void cpa16(uint32_t dst, const void* src) {
    asm volatile("cp.async.cg.shared.global [%0], [%1], 16;"
                 :: "r"(dst), "l"(src) : "memory");
}
#define CP_COMMIT() asm volatile("cp.async.commit_group;" ::: "memory")
#define CP_WAIT0()  asm volatile("cp.async.wait_group 0;" ::: "memory")
#define CP_WAIT1()  asm volatile("cp.async.wait_group 1;" ::: "memory")

// MUFU activations (tanh.approx, sm_75+ baseline PTX)
__device__ __forceinline__ float tanh_ap(float x) {
    float y; asm("tanh.approx.f32 %0, %1;" : "=f"(y) : "f"(x)); return y;
}
__device__ __forceinline__ float sigmoid_ap(float x) {
    return fmaf(tanh_ap(0.5f * x), 0.5f, 0.5f);
}

// ---------------- static device scratch ------------------------------------
__device__ float  g_xg[(size_t)Bb * Tt * Gg / 2]; // 512 MiB gate pre-acts (fp16)
__device__ __half g_hseq[(size_t)Bb * Tt * Hh];   // 128 MiB layer-0 hidden (fp16)
__device__ __half g_hbuf[2 * (size_t)Bb * Hh];    // double-buffered h (fp16)
__device__ unsigned int g_bar[4];                 // per-M-group barrier counters

__global__ void init_kernel() {
    unsigned idx = blockIdx.x * blockDim.x + threadIdx.x;
    reinterpret_cast<unsigned int*>(g_hbuf)[idx] = 0u;
    if (idx < 4) g_bar[idx] = 0u;
}

// ================= fp16 mma GEMM (f32 inputs; validated) ====================
#define GPH 40
#define SABUF_H (128 * GPH)
#define GEMM_SMEM_BYTES (4 * SABUF_H * 2)

__global__ void __launch_bounds__(256, 2)
mma_gemm(const float* __restrict__ A, const float* __restrict__ W,
         const float* __restrict__ b1, const float* __restrict__ b2,
         __half* __restrict__ C, int K)
{
    extern __shared__ __half smh[];
    __half* sA = smh;
    __half* sB = smh + 2 * SABUF_H;

    const int tid = threadIdx.x;
    const int lane = tid & 31;
    const int wid = tid >> 5;
    const int gid = lane >> 2;
    const int tq = lane & 3;
    const int warpM = wid >> 2;
    const int warpN = wid & 3;
    const size_t n0 = (size_t)blockIdx.x * 128;
    const size_t m0 = (size_t)blockIdx.y * 128;
    const int NC = K >> 5;

    const int lrow = tid >> 3;
    const int lq = tid & 7;

    float acc[4][4][4];
#pragma unroll
    for (int mt = 0; mt < 4; ++mt)
#pragma unroll
        for (int nt = 0; nt < 4; ++nt)
#pragma unroll
            for (int k = 0; k < 4; ++k) acc[mt][nt][k] = 0.f;

    float4 pa[4], pb[4];
#pragma unroll
    for (int i = 0; i < 4; ++i) {
        int row = lrow + i * 32;
        pa[i] = *reinterpret_cast<const float4*>(&A[(m0 + row) * (size_t)K + lq * 4]);
        pb[i] = *reinterpret_cast<const float4*>(&W[(n0 + row) * (size_t)K + lq * 4]);
    }
#pragma unroll
    for (int i = 0; i < 4; ++i) {
        int row = lrow + i * 32;
        uint2 ua, ub;
        ua.x = h2u(__floats2half2_rn(pa[i].x, pa[i].y));
        ua.y = h2u(__floats2half2_rn(pa[i].z, pa[i].w));
        ub.x = h2u(__floats2half2_rn(pb[i].x, pb[i].y));
        ub.y = h2u(__floats2half2_rn(pb[i].z, pb[i].w));
        *reinterpret_cast<uint2*>(&sA[row * GPH + lq * 4]) = ua;
        *reinterpret_cast<uint2*>(&sB[row * GPH + lq * 4]) = ub;
    }
    __syncthreads();

#pragma unroll 1
    for (int c = 0; c < NC; ++c) {
        const int buf = c & 1;
        if (c + 1 < NC) {
            int k0 = (c + 1) * 32;
#pragma unroll
            for (int i = 0; i < 4; ++i) {
                int row = lrow + i * 32;
                pa[i] = *reinterpret_cast<const float4*>(&A[(m0 + row) * (size_t)K + k0 + lq * 4]);
                pb[i] = *reinterpret_cast<const float4*>(&W[(n0 + row) * (size_t)K + k0 + lq * 4]);
            }
        }
        const __half* sAb = sA + buf * SABUF_H;
        const __half* sBb = sB + buf * SABUF_H;
#pragma unroll
        for (int kk = 0; kk < 2; ++kk) {
            const int k0 = kk * 16;
            uint32_t a[4][4];
#pragma unroll
            for (int mt = 0; mt < 4; ++mt) {
                const __half* ap = sAb + (warpM * 64 + mt * 16 + gid) * GPH + k0 + 2 * tq;
                a[mt][0] = ldu32(ap);
                a[mt][1] = ldu32(ap + 8 * GPH);
                a[mt][2] = ldu32(ap + 8);
                a[mt][3] = ldu32(ap + 8 * GPH + 8);
            }
            uint32_t bf[4][2];
#pragma unroll
            for (int nt = 0; nt < 4; ++nt) {
                const __half* bp = sBb + (warpN * 32 + nt * 8 + gid) * GPH + k0 + 2 * tq;
                bf[nt][0] = ldu32(bp);
                bf[nt][1] = ldu32(bp + 8);
            }
#pragma unroll
            for (int mt = 0; mt < 4; ++mt)
#pragma unroll
                for (int nt = 0; nt < 4; ++nt)
                    mma_f16(acc[mt][nt], a[mt], bf[nt]);
        }
        __syncthreads();
        if (c + 1 < NC) {
            __half* dA = sA + (buf ^ 1) * SABUF_H;
            __half* dB = sB + (buf ^ 1) * SABUF_H;
#pragma unroll
            for (int i = 0; i < 4; ++i) {
                int row = lrow + i * 32;
                uint2 ua, ub;
                ua.x = h2u(__floats2half2_rn(pa[i].x, pa[i].y));
                ua.y = h2u(__floats2half2_rn(pa[i].z, pa[i].w));
                ub.x = h2u(__floats2half2_rn(pb[i].x, pb[i].y));
                ub.y = h2u(__floats2half2_rn(pb[i].z, pb[i].w));
                *reinterpret_cast<uint2*>(&dA[row * GPH + lq * 4]) = ua;
                *reinterpret_cast<uint2*>(&dB[row * GPH + lq * 4]) = ub;
            }
            __syncthreads();
        }
    }

    float bias[4][2];
#pragma unroll
    for (int nt = 0; nt < 4; ++nt) {
        size_t ncol = n0 + warpN * 32 + nt * 8 + tq * 2;
        bias[nt][0] = b1[ncol] + b2[ncol];
        bias[nt][1] = b1[ncol + 1] + b2[ncol + 1];
    }
#pragma unroll
    for (int mt = 0; mt < 4; ++mt) {
        size_t r0 = m0 + warpM * 64 + mt * 16 + gid;
#pragma unroll
        for (int nt = 0; nt < 4; ++nt) {
            size_t ncol = n0 + warpN * 32 + nt * 8 + tq * 2;
            uint32_t u0 = h2u(__floats2half2_rn(acc[mt][nt][0] + bias[nt][0],
                                                acc[mt][nt][1] + bias[nt][1]));
            uint32_t u1 = h2u(__floats2half2_rn(acc[mt][nt][2] + bias[nt][0],
                                                acc[mt][nt][3] + bias[nt][1]));
            *reinterpret_cast<uint32_t*>(&C[r0 * Gg + ncol]) = u0;
            *reinterpret_cast<uint32_t*>(&C[(r0 + 8) * Gg + ncol]) = u1;
        }
    }
}

// ================= fp16 mma GEMM, A already fp16 (layer 1) ==================
__global__ void __launch_bounds__(256, 2)
mma_gemm_h(const __half* __restrict__ A, const float* __restrict__ W,
           const float* __restrict__ b1, const float* __restrict__ b2,
           __half* __restrict__ C, int K)
{
    extern __shared__ __half smh[];
    __half* sA = smh;
    __half* sB = smh + 2 * SABUF_H;

    const int tid = threadIdx.x;
    const int lane = tid & 31;
    const int wid = tid >> 5;
    const int gid = lane >> 2;
    const int tq = lane & 3;
    const int warpM = wid >> 2;
    const int warpN = wid & 3;
    const size_t n0 = (size_t)blockIdx.x * 128;
    const size_t m0 = (size_t)blockIdx.y * 128;
    const int NC = K >> 5;

    const int lrow = tid >> 3;
    const int lq = tid & 7;

    float acc[4][4][4];
#pragma unroll
    for (int mt = 0; mt < 4; ++mt)
#pragma unroll
        for (int nt = 0; nt < 4; ++nt)
#pragma unroll
            for (int k = 0; k < 4; ++k) acc[mt][nt][k] = 0.f;

    uint2 pa[4];
    float4 pb[4];
#pragma unroll
    for (int i = 0; i < 4; ++i) {
        int row = lrow + i * 32;
        pa[i] = *reinterpret_cast<const uint2*>(&A[(m0 + row) * (size_t)K + lq * 4]);
        pb[i] = *reinterpret_cast<const float4*>(&W[(n0 + row) * (size_t)K + lq * 4]);
    }
#pragma unroll
    for (int i = 0; i < 4; ++i) {
        int row = lrow + i * 32;
        uint2 ub;
        ub.x = h2u(__floats2half2_rn(pb[i].x, pb[i].y));
        ub.y = h2u(__floats2half2_rn(pb[i].z, pb[i].w));
        *reinterpret_cast<uint2*>(&sA[row * GPH + lq * 4]) = pa[i];
        *reinterpret_cast<uint2*>(&sB[row * GPH + lq * 4]) = ub;
    }
    __syncthreads();

#pragma unroll 1
    for (int c = 0; c < NC; ++c) {
        const int buf = c & 1;
        if (c + 1 < NC) {
            int k0 = (c + 1) * 32;
#pragma unroll
            for (int i = 0; i < 4; ++i) {
                int row = lrow + i * 32;
                pa[i] = *reinterpret_cast<const uint2*>(&A[(m0 + row) * (size_t)K + k0 + lq * 4]);
                pb[i] = *reinterpret_cast<const float4*>(&W[(n0 + row) * (size_t)K + k0 + lq * 4]);
            }
        }
        const __half* sAb = sA + buf * SABUF_H;
        const __half* sBb = sB + buf * SABUF_H;
#pragma unroll
        for (int kk = 0; kk < 2; ++kk) {
            const int k0 = kk * 16;
            uint32_t a[4][4];
#pragma unroll
            for (int mt = 0; mt < 4; ++mt) {
                const __half* ap = sAb + (warpM * 64 + mt * 16 + gid) * GPH + k0 + 2 * tq;
                a[mt][0] = ldu32(ap);
                a[mt][1] = ldu32(ap + 8 * GPH);
                a[mt][2] = ldu32(ap + 8);
                a[mt][3] = ldu32(ap + 8 * GPH + 8);
            }
            uint32_t bf[4][2];
#pragma unroll
            for (int nt = 0; nt < 4; ++nt) {
                const __half* bp = sBb + (warpN * 32 + nt * 8 + gid) * GPH + k0 + 2 * tq;
                bf[nt][0] = ldu32(bp);
                bf[nt][1] = ldu32(bp + 8);
            }
#pragma unroll
            for (int mt = 0; mt < 4; ++mt)
#pragma unroll
                for (int nt = 0; nt < 4; ++nt)
                    mma_f16(acc[mt][nt], a[mt], bf[nt]);
        }
        __syncthreads();
        if (c + 1 < NC) {
            __half* dA = sA + (buf ^ 1) * SABUF_H;
            __half* dB = sB + (buf ^ 1) * SABUF_H;
#pragma unroll
            for (int i = 0; i < 4; ++i) {
                int row = lrow + i * 32;
                uint2 ub;
                ub.x = h2u(__floats2half2_rn(pb[i].x, pb[i].y));
                ub.y = h2u(__floats2half2_rn(pb[i].z, pb[i].w));
                *reinterpret_cast<uint2*>(&dA[row * GPH + lq * 4]) = pa[i];
                *reinterpret_cast<uint2*>(&dB[row * GPH + lq * 4]) = ub;
            }
            __syncthreads();
        }
    }

    float bias[4][2];
#pragma unroll
    for (int nt = 0; nt < 4; ++nt) {
        size_t ncol = n0 + warpN * 32 + nt * 8 + tq * 2;
        bias[nt][0] = b1[ncol] + b2[ncol];
        bias[nt][1] = b1[ncol + 1] + b2[ncol + 1];
    }
#pragma unroll
    for (int mt = 0; mt < 4; ++mt) {
        size_t r0 = m0 + warpM * 64 + mt * 16 + gid;
#pragma unroll
        for (int nt = 0; nt < 4; ++nt) {
            size_t ncol = n0 + warpN * 32 + nt * 8 + tq * 2;
            uint32_t u0 = h2u(__floats2half2_rn(acc[mt][nt][0] + bias[nt][0],
                                                acc[mt][nt][1] + bias[nt][1]));
            uint32_t u1 = h2u(__floats2half2_rn(acc[mt][nt][2] + bias[nt][0],
                                                acc[mt][nt][3] + bias[nt][1]));
            *reinterpret_cast<uint32_t*>(&C[r0 * Gg + ncol]) = u0;
            *reinterpret_cast<uint32_t*>(&C[(r0 + 8) * Gg + ncol]) = u1;
        }
    }
}

// ================= persistent LSTM recurrence ================================
// fp16 mma; split-half pipelined staging; symmetric K-split epilogue;
// MUFU activations; fp16 hseq; WARP-GRANULAR per-M-group barrier:
// 256 arrivals (32 CTAs x 8 warps), per-warp release-arrive after its own
// hout stores, per-warp acquire-poll -> fast warps start next step early.
#define NCTA_R 128
#define GRP_ARR 256                      // 32 CTAs x 8 warps
#define RWPH 520
#define RHPH 520
#define XGPH 72
#define SM_W_BYTES   (64 * RWPH * 2)     // 66560
#define SM_H_BYTES   (64 * RHPH * 2)     // 66560
#define SM_XG_BYTES  (64 * XGPH * 2)     // 9216
#define SM_RED_BYTES (4096 * 4)          // 16384
#define SM_TRH_BYTES (64 * 16 * 2)       // 2048
#define REC_SMEM_BYTES (SM_W_BYTES + SM_H_BYTES + SM_XG_BYTES + SM_RED_BYTES + \
                        SM_TRH_BYTES)    // 160768

__global__ void __launch_bounds__(256, 1)
lstm_rec(const float* __restrict__ W_hh, const __half* __restrict__ xgh,
         __half* __restrict__ hseq)
{
    extern __shared__ char smc[];
    __half* sWh  = reinterpret_cast<__half*>(smc);
    __half* sHh  = reinterpret_cast<__half*>(smc + SM_W_BYTES);
    __half* sXG  = reinterpret_cast<__half*>(smc + SM_W_BYTES + SM_H_BYTES);
    float*  sRed = reinterpret_cast<float*>(smc + SM_W_BYTES + SM_H_BYTES + SM_XG_BYTES);
    __half* sTrH = reinterpret_cast<__half*>(smc + SM_W_BYTES + SM_H_BYTES + SM_XG_BYTES + SM_RED_BYTES);

    const uint32_t sH_u  = smem_u32_of(sHh);
    const uint32_t sXG_u = smem_u32_of(sXG);

    const int tid = threadIdx.x;
    const int lane = tid & 31;
    const int wid = tid >> 5;
    const int wK = wid >> 2;              // == half; owns mt=wK
    const int wM = (wid >> 1) & 1;
    const int wN = wid & 1;
    const int gid = lane >> 2;
    const int tq = lane & 3;
    const int p = lane & 1;

    const int ctaM = blockIdx.x & 3;
    const int ctaC = blockIdx.x >> 2;
    const int m0 = ctaM * 64;
    const int hc0 = ctaC * 16;

    const int half = tid >> 7;
    const int st = tid & 127;
    const int hcolh = half * 256;
    const int hcolb = half * 512;
    const int barid = 1 + half;

    // W_hh slice -> smem (fp16 rne), row j = cl*4 + g
    for (int idx = tid; idx < 64 * 512; idx += 256) {
        int j = idx >> 9, k = idx & 511;
        sWh[j * RWPH + k] =
            __float2half_rn(W_hh[((size_t)(j & 3) * Hh + hc0 + (j >> 2)) * Hh + k]);
    }
    __syncthreads();

    float cst[4];
#pragma unroll
    for (int s = 0; s < 4; ++s) cst[s] = 0.f;
    unsigned phase = 0;
    const int pair = wM * 2 + wN;

    // ---- xg(0) cp.async ----
#pragma unroll
    for (int it = 0; it < 2; ++it) {
        int seg = tid + it * 256;
        int row = seg >> 3, c8 = seg & 7;
        int gate = c8 >> 1, colpart = (c8 & 1) * 8;
        cpa16(sXG_u + (row * XGPH + c8 * 8) * 2,
              &xgh[((size_t)(m0 + row) * Tt + 0) * Gg + (size_t)gate * Hh + hc0 + colpart]);
    }
    CP_COMMIT();

    for (int t = 0; t < Tt; ++t) {
        const __half* hin = g_hbuf + (size_t)(t & 1) * Bb * Hh;
        __half* hout = g_hbuf + (size_t)((t + 1) & 1) * Bb * Hh;

        // ---- stage this half's 64x256 h region in TWO commit groups ----
#pragma unroll
        for (int it = 0; it < 8; ++it) {
            int seg = st + it * 128;
            int row = seg >> 4, c16 = seg & 15;
            cpa16(sH_u + row * (RHPH * 2) + hcolb + c16 * 16,
                  hin + (size_t)(m0 + row) * Hh + hcolh + c16 * 8);
        }
        CP_COMMIT();
#pragma unroll
        for (int it = 0; it < 8; ++it) {
            int seg = st + it * 128;
            int row = seg >> 4, c16 = (seg & 15) + 16;
            cpa16(sH_u + row * (RHPH * 2) + hcolb + c16 * 16,
                  hin + (size_t)(m0 + row) * Hh + hcolh + c16 * 8);
        }
        CP_COMMIT();

        float acc[2][4][4];
#pragma unroll
        for (int mt = 0; mt < 2; ++mt)
#pragma unroll
            for (int nt = 0; nt < 4; ++nt)
#pragma unroll
                for (int k = 0; k < 4; ++k) acc[mt][nt][k] = 0.f;

        const int kq0 = wK * 256;

        CP_WAIT1();
        asm volatile("bar.sync %0, 128;" :: "r"(barid) : "memory");
#pragma unroll
        for (int kk = 0; kk < 8; ++kk) {
            const int k0 = kq0 + kk * 16;
            uint32_t a[2][4];
#pragma unroll
            for (int mt = 0; mt < 2; ++mt) {
                const __half* ap = sHh + (wM * 32 + mt * 16 + gid) * RHPH + k0 + 2 * tq;
                a[mt][0] = ldu32(ap);
                a[mt][1] = ldu32(ap + 8 * RHPH);
                a[mt][2] = ldu32(ap + 8);
                a[mt][3] = ldu32(ap + 8 * RHPH + 8);
            }
#pragma unroll
            for (int nt = 0; nt < 4; ++nt) {
                const __half* bp = sWh + (wN * 32 + nt * 8 + gid) * RWPH + k0 + 2 * tq;
                uint32_t bfr[2];
                bfr[0] = ldu32(bp);
                bfr[1] = ldu32(bp + 8);
#pragma unroll
                for (int mt = 0; mt < 2; ++mt)
                    mma_f16(acc[mt][nt], a[mt], bfr);
            }
        }
        CP_WAIT0();
        asm volatile("bar.sync %0, 128;" :: "r"(barid) : "memory");
#pragma unroll
        for (int kk = 8; kk < 16; ++kk) {
            const int k0 = kq0 + kk * 16;
            uint32_t a[2][4];
#pragma unroll
            for (int mt = 0; mt < 2; ++mt) {
                const __half* ap = sHh + (wM * 32 + mt * 16 + gid) * RHPH + k0 + 2 * tq;
                a[mt][0] = ldu32(ap);
                a[mt][1] = ldu32(ap + 8 * RHPH);
                a[mt][2] = ldu32(ap + 8);
                a[mt][3] = ldu32(ap + 8 * RHPH + 8);
            }
#pragma unroll
            for (int nt = 0; nt < 4; ++nt) {
                const __half* bp = sWh + (wN * 32 + nt * 8 + gid) * RWPH + k0 + 2 * tq;
                uint32_t bfr[2];
                bfr[0] = ldu32(bp);
                bfr[1] = ldu32(bp + 8);
#pragma unroll
                for (int mt = 0; mt < 2; ++mt)
                    mma_f16(acc[mt][nt], a[mt], bfr);
            }
        }

        // ---- symmetric K-split exchange: write NON-owned mt to sRed ----
        {
            int mtx = wK ^ 1;
#pragma unroll
            for (int nt = 0; nt < 4; ++nt) {
                float4 v;
                v.x = acc[mtx][nt][0]; v.y = acc[mtx][nt][1];
                v.z = acc[mtx][nt][2]; v.w = acc[mtx][nt][3];
                *reinterpret_cast<float4*>(
                    &sRed[((wK * 4 + pair) * 4 + nt) * 128 + lane * 4]) = v;
            }
        }
        __syncthreads();                   // (2)

        // ---- finalize owned mt: add peer partials, activations, write tile
        {
            int mto = wK;
            int src = wK ^ 1;
            int rl = wM * 32 + mto * 16 + gid + p * 8;
#pragma unroll
            for (int nt = 0; nt < 4; ++nt) {
                float4 v = *reinterpret_cast<const float4*>(
                    &sRed[((src * 4 + pair) * 4 + nt) * 128 + lane * 4]);
                float q0 = acc[mto][nt][0] + v.x;
                float q1 = acc[mto][nt][1] + v.y;
                float q2 = acc[mto][nt][2] + v.z;
                float q3 = acc[mto][nt][3] + v.w;
                float s0 = p ? q0 : q2;
                float s1 = p ? q1 : q3;
                float r0 = __shfl_xor_sync(0xffffffffu, s0, 1);
                float r1 = __shfl_xor_sync(0xffffffffu, s1, 1);
                float gi = p ? r0 : q0;
                float gf = p ? r1 : q1;
                float gg = p ? q2 : r0;
                float go = p ? q3 : r1;
                int cl = wN * 8 + nt * 2 + (tq >> 1);
                const __half* xp = &sXG[rl * XGPH + cl];
                float iv = sigmoid_ap(gi + __half2float(xp[0]));
                float fv = sigmoid_ap(gf + __half2float(xp[16]));
                float gv = tanh_ap(gg + __half2float(xp[32]));
                float ov = sigmoid_ap(go + __half2float(xp[48]));
                cst[nt] = fv * cst[nt] + iv * gv;
                float hv = ov * tanh_ap(cst[nt]);
                sTrH[rl * 16 + cl] = __float2half_rn(hv);
            }
        }
        __syncthreads();                   // (2b) sTrH complete; sXG consumed

        // ---- coalesced hout write (each warp its own 8 rows) ----
        {
            int row = tid >> 2, part = tid & 3;
            uint2 v = *reinterpret_cast<const uint2*>(&sTrH[row * 16 + part * 4]);
            *reinterpret_cast<uint2*>(&hout[(size_t)(m0 + row) * Hh + hc0 + part * 4]) = v;
        }

        // ---- warp-granular arrive (release covers this warp's hout) ----
        phase += GRP_ARR;
        __syncwarp();
        if (lane == 0) {
            asm volatile("red.release.gpu.add.u32 [%0], %1;"
                         :: "l"(&g_bar[ctaM]), "r"(1u) : "memory");
        }

        // ---- non-critical work in barrier shadow: hseq + xg(t+1) ----
        if (hseq) {
            int row = tid >> 2, part = tid & 3;
            uint2 v = *reinterpret_cast<const uint2*>(&sTrH[row * 16 + part * 4]);
            *reinterpret_cast<uint2*>(
                &hseq[((size_t)(m0 + row) * Tt + t) * Hh + hc0 + part * 4]) = v;
        }
        if (t + 1 < Tt) {
#pragma unroll
            for (int it = 0; it < 2; ++it) {
                int seg = tid + it * 256;
                int row = seg >> 3, c8 = seg & 7;
                int gate = c8 >> 1, colpart = (c8 & 1) * 8;
                cpa16(sXG_u + (row * XGPH + c8 * 8) * 2,
                      &xgh[((size_t)(m0 + row) * Tt + (t + 1)) * Gg
                           + (size_t)gate * Hh + hc0 + colpart]);
            }
            CP_COMMIT();
        }

        // ---- per-warp acquire-poll (no CTA-wide sync; no sleep) ----
        if (lane == 0) {
            unsigned v;
            do {
                asm volatile("ld.acquire.gpu.u32 %0, [%1];"
                             : "=r"(v) : "l"(&g_bar[ctaM]) : "memory");
            } while (v < phase);
        }
        __syncwarp();
    }
}

// ---------------- final FC (h is fp16) --------------------------------------
__global__ void fc_kernel(const __half* __restrict__ h, const float* __restrict__ Wfc,
                          const float* __restrict__ bfc, float* __restrict__ out)
{
    int b = blockIdx.x;
    int tid = threadIdx.x;
    float s = 0.f;
    for (int k = tid; k < Hh; k += 128)
        s += __half2float(h[(size_t)b * Hh + k]) * Wfc[k];
#pragma unroll
    for (int o = 16; o > 0; o >>= 1) s += __shfl_xor_sync(0xffffffffu, s, o);
    __shared__ float ws[4];
    if ((tid & 31) == 0) ws[tid >> 5] = s;
    __syncthreads();
    if (tid == 0) out[b] = ws[0] + ws[1] + ws[2] + ws[3] + bfc[0];
}

// ---------------- launch ----------------------------------------------------
extern "C" void kernel_launch(void* const* d_in, const int* in_sizes, int n_in,
                              void* d_out, int out_size)
{
    (void)in_sizes; (void)n_in; (void)out_size;
    const float* x     = (const float*)d_in[0];
    const float* W_ih0 = (const float*)d_in[1];
    const float* W_hh0 = (const float*)d_in[2];
    const float* b_ih0 = (const float*)d_in[3];
    const float* b_hh0 = (const float*)d_in[4];
    const float* W_ih1 = (const float*)d_in[5];
    const float* W_hh1 = (const float*)d_in[6];
    const float* b_ih1 = (const float*)d_in[7];
    const float* b_hh1 = (const float*)d_in[8];
    const float* W_fc  = (const float*)d_in[9];
    const float* b_fc  = (const float*)d_in[10];
    float* out = (float*)d_out;

    void *p_xg = nullptr, *p_hseq = nullptr, *p_hbuf = nullptr;
    cudaGetSymbolAddress(&p_xg, g_xg);
    cudaGetSymbolAddress(&p_hseq, g_hseq);
    cudaGetSymbolAddress(&p_hbuf, g_hbuf);

    cudaFuncSetAttribute(mma_gemm, cudaFuncAttributeMaxDynamicSharedMemorySize,
                         GEMM_SMEM_BYTES);
    cudaFuncSetAttribute(mma_gemm_h, cudaFuncAttributeMaxDynamicSharedMemorySize,
                         GEMM_SMEM_BYTES);
    cudaFuncSetAttribute(lstm_rec, cudaFuncAttributeMaxDynamicSharedMemorySize,
                         REC_SMEM_BYTES);

    dim3 ggrid(Gg / 128, (Bb * Tt) / 128);   // (16, 1024)

    // Layer 0
    mma_gemm<<<ggrid, 256, GEMM_SMEM_BYTES>>>(x, W_ih0, b_ih0, b_hh0,
                                              (__half*)p_xg, Ii);
    init_kernel<<<1024, 256>>>();
    lstm_rec<<<NCTA_R, 256, REC_SMEM_BYTES>>>(W_hh0, (const __half*)p_xg,
                                              (__half*)p_hseq);

    // Layer 1 (A = fp16 hseq)
    mma_gemm_h<<<ggrid, 256, GEMM_SMEM_BYTES>>>((const __half*)p_hseq, W_ih1,
                                                b_ih1, b_hh1, (__half*)p_xg, Hh);
    init_kernel<<<1024, 256>>>();
    lstm_rec<<<NCTA_R, 256, REC_SMEM_BYTES>>>(W_hh1, (const __half*)p_xg, nullptr);

    // Final FC (h_last ends in buffer 0 since T=512 is even; fp16 layout)
    fc_kernel<<<Bb, 128>>>((const __half*)p_hbuf, W_fc, b_fc, out);
}